// round 1
// baseline (speedup 1.0000x reference)
#include <cuda_runtime.h>
#include <math.h>
#include <stdint.h>

// Problem constants (shape-specialized; N/E derived from in_sizes at launch)
static constexpr int MAXN = 100000;
static constexpr int MAXE = 1600000;
static constexpr int F1   = 128;   // F_in and H*HID
static constexpr int F2   = 160;   // H*NCLS
static constexpr int NH   = 4;     // heads
static constexpr float NEG_SLOPE = 0.2f;

// ---------------- scratch (device globals; no allocation allowed) ----------
__device__ float g_h1  [(size_t)MAXN * F1];
__device__ float g_out1[(size_t)MAXN * F1];
__device__ float g_h2  [(size_t)MAXN * F2];
__device__ float g_out2[(size_t)MAXN * F2];
__device__ float g_als1[(size_t)MAXN * NH];
__device__ float g_ald1[(size_t)MAXN * NH];
__device__ float g_s1  [(size_t)MAXN * NH];
__device__ float g_als2[(size_t)MAXN * NH];
__device__ float g_ald2[(size_t)MAXN * NH];
__device__ float g_s2  [(size_t)MAXN * NH];

// ---------------- helpers ---------------------------------------------------
__device__ __forceinline__ void red_add_v4(float* addr, float4 v) {
#if __CUDA_ARCH__ >= 900
    asm volatile("red.global.add.v4.f32 [%0], {%1,%2,%3,%4};"
                 :: "l"(addr), "f"(v.x), "f"(v.y), "f"(v.z), "f"(v.w)
                 : "memory");
#else
    atomicAdd(addr + 0, v.x);
    atomicAdd(addr + 1, v.y);
    atomicAdd(addr + 2, v.z);
    atomicAdd(addr + 3, v.w);
#endif
}

__device__ __forceinline__ float lrelu(float v) {
    return v > 0.f ? v : NEG_SLOPE * v;
}

// ---------------- zero fill -------------------------------------------------
__global__ void zero4_kernel(float4* __restrict__ p, int n4) {
    int i = blockIdx.x * blockDim.x + threadIdx.x;
    if (i < n4) p[i] = make_float4(0.f, 0.f, 0.f, 0.f);
}

// ---------------- GEMM: out[N,NOUT] = act(A[N,128] (+bias)) @ W[128,NOUT] ---
// Whole W resident in SMEM; 64 rows of A per block; 256 threads.
// Warp w handles rows [w*8, w*8+8); lane handles cols lane + 32*q.
template<int NOUT, bool RELU_BIAS>
__global__ void gemm_k128(const float* __restrict__ A,
                          const float* __restrict__ W,
                          const float* __restrict__ bias,   // [128] when RELU_BIAS
                          float* __restrict__ out, int N)
{
    extern __shared__ float smem[];
    float* sW = smem;               // 128*NOUT
    float* sA = smem + 128 * NOUT;  // 64*128
    const int tid  = threadIdx.x;
    const int warp = tid >> 5;
    const int lane = tid & 31;
    const int row0 = blockIdx.x * 64;

    // load W (coalesced float4)
    for (int i = tid * 4; i < 128 * NOUT; i += 256 * 4) {
        *reinterpret_cast<float4*>(sW + i) =
            *reinterpret_cast<const float4*>(W + i);
    }
    // load A tile (64 rows x 128 cols)
    for (int i = tid; i < 64 * 128 / 4; i += 256) {
        int idx = i * 4;
        int r   = idx >> 7;
        int k   = idx & 127;
        int gr  = row0 + r;
        float4 v = make_float4(0.f, 0.f, 0.f, 0.f);
        if (gr < N) {
            v = *reinterpret_cast<const float4*>(A + (size_t)gr * 128 + k);
            if (RELU_BIAS) {
                v.x = fmaxf(v.x + bias[k + 0], 0.f);
                v.y = fmaxf(v.y + bias[k + 1], 0.f);
                v.z = fmaxf(v.z + bias[k + 2], 0.f);
                v.w = fmaxf(v.w + bias[k + 3], 0.f);
            }
        }
        *reinterpret_cast<float4*>(sA + idx) = v;
    }
    __syncthreads();

    constexpr int Q = NOUT / 32;
    float acc[8][Q];
#pragma unroll
    for (int i = 0; i < 8; ++i)
#pragma unroll
        for (int q = 0; q < Q; ++q) acc[i][q] = 0.f;

    const float* sArow = sA + (warp * 8) * 128;
#pragma unroll 8
    for (int k = 0; k < 128; ++k) {
        float wv[Q];
#pragma unroll
        for (int q = 0; q < Q; ++q) wv[q] = sW[k * NOUT + lane + 32 * q];
#pragma unroll
        for (int i = 0; i < 8; ++i) {
            float a = sArow[i * 128 + k];
#pragma unroll
            for (int q = 0; q < Q; ++q) acc[i][q] = fmaf(a, wv[q], acc[i][q]);
        }
    }

#pragma unroll
    for (int i = 0; i < 8; ++i) {
        int r = row0 + warp * 8 + i;
        if (r < N) {
#pragma unroll
            for (int q = 0; q < Q; ++q)
                out[(size_t)r * NOUT + lane + 32 * q] = acc[i][q];
        }
    }
}

// ---------------- attention coefficients: al[n,h] = sum_c h[n,h,c]*a[h,c] ---
// one warp per (node, head)
template<int C>
__global__ void attn_coef(const float* __restrict__ Hm,
                          const float* __restrict__ a_s,
                          const float* __restrict__ a_d,
                          float* __restrict__ als, float* __restrict__ ald, int N)
{
    int gw   = (int)((blockIdx.x * (size_t)blockDim.x + threadIdx.x) >> 5);
    int lane = threadIdx.x & 31;
    int n = gw >> 2;
    int h = gw & 3;
    if (n >= N) return;
    const float* base = Hm + (size_t)n * (NH * C) + h * C;
    float vs = 0.f, vd = 0.f;
    for (int c = lane; c < C; c += 32) {
        float hv = base[c];
        vs = fmaf(hv, a_s[h * C + c], vs);
        vd = fmaf(hv, a_d[h * C + c], vd);
    }
#pragma unroll
    for (int o = 16; o; o >>= 1) {
        vs += __shfl_xor_sync(0xffffffffu, vs, o);
        vd += __shfl_xor_sync(0xffffffffu, vd, o);
    }
    if (lane == 0) {
        als[n * NH + h] = vs;
        ald[n * NH + h] = vd;
    }
}

// ---------------- softmax denominator: s[d,h] += exp(lrelu(als[s]+ald[d])) --
// one thread per edge; no max-shift needed (logits are O(1))
__global__ void edge_softmax_denom(const int* __restrict__ src,
                                   const int* __restrict__ dst,
                                   const float* __restrict__ als,
                                   const float* __restrict__ ald,
                                   float* __restrict__ sbuf, int E)
{
    int e = blockIdx.x * blockDim.x + threadIdx.x;
    if (e >= E) return;
    int s = src[e], d = dst[e];
    float4 a = __ldg(reinterpret_cast<const float4*>(als + (size_t)s * 4));
    float4 b = __ldg(reinterpret_cast<const float4*>(ald + (size_t)d * 4));
    float4 ex;
    ex.x = __expf(lrelu(a.x + b.x));
    ex.y = __expf(lrelu(a.y + b.y));
    ex.z = __expf(lrelu(a.z + b.z));
    ex.w = __expf(lrelu(a.w + b.w));
    red_add_v4(sbuf + (size_t)d * 4, ex);
}

// ---------------- edge aggregation: out[d] += h[s] * alpha -------------------
// one warp per edge; lane j handles float4 chunk j of the feature row
template<int NOUT, int C>
__global__ void edge_aggregate(const int* __restrict__ src,
                               const int* __restrict__ dst,
                               const float* __restrict__ als,
                               const float* __restrict__ ald,
                               const float* __restrict__ sbuf,
                               const float* __restrict__ Hm,
                               float* __restrict__ outm, int E)
{
    int gw   = (int)((blockIdx.x * (size_t)blockDim.x + threadIdx.x) >> 5);
    int lane = threadIdx.x & 31;
    if (gw >= E) return;
    int s = src[gw], d = dst[gw];
    float4 a  = __ldg(reinterpret_cast<const float4*>(als  + (size_t)s * 4));
    float4 b  = __ldg(reinterpret_cast<const float4*>(ald  + (size_t)d * 4));
    float4 sv = __ldg(reinterpret_cast<const float4*>(sbuf + (size_t)d * 4));
    float al0 = __expf(lrelu(a.x + b.x)) / (sv.x + 1e-16f);
    float al1 = __expf(lrelu(a.y + b.y)) / (sv.y + 1e-16f);
    float al2 = __expf(lrelu(a.z + b.z)) / (sv.z + 1e-16f);
    float al3 = __expf(lrelu(a.w + b.w)) / (sv.w + 1e-16f);

    const float4* hrow = reinterpret_cast<const float4*>(Hm + (size_t)s * NOUT);
    float* orow = outm + (size_t)d * NOUT;
#pragma unroll
    for (int j = lane; j < NOUT / 4; j += 32) {
        int head = (j * 4) / C;
        float al = (head == 0) ? al0 : (head == 1) ? al1 : (head == 2) ? al2 : al3;
        float4 hv = __ldg(hrow + j);
        red_add_v4(orow + j * 4,
                   make_float4(hv.x * al, hv.y * al, hv.z * al, hv.w * al));
    }
}

// ---------------- final: mean over heads + b2, log_softmax -------------------
// one warp per node, 40 classes (lane covers c=lane, c=lane+32 for lane<8)
__global__ void final_logsoftmax(const float* __restrict__ out2,
                                 const float* __restrict__ b2,
                                 float* __restrict__ y, int N)
{
    int gw   = (int)((blockIdx.x * (size_t)blockDim.x + threadIdx.x) >> 5);
    int lane = threadIdx.x & 31;
    if (gw >= N) return;
    const float* base = out2 + (size_t)gw * F2;
    int c0 = lane;          // always < 40
    int c1 = lane + 32;     // valid for lane < 8
    bool has1 = (c1 < 40);

    float v0 = 0.25f * (base[c0] + base[40 + c0] + base[80 + c0] + base[120 + c0]) + b2[c0];
    float v1 = -1e30f;
    if (has1)
        v1 = 0.25f * (base[c1] + base[40 + c1] + base[80 + c1] + base[120 + c1]) + b2[c1];

    float m = fmaxf(v0, v1);
#pragma unroll
    for (int o = 16; o; o >>= 1) m = fmaxf(m, __shfl_xor_sync(0xffffffffu, m, o));
    float se = __expf(v0 - m) + (has1 ? __expf(v1 - m) : 0.f);
#pragma unroll
    for (int o = 16; o; o >>= 1) se += __shfl_xor_sync(0xffffffffu, se, o);
    float lse = logf(se) + m;

    y[(size_t)gw * 40 + c0] = v0 - lse;
    if (has1) y[(size_t)gw * 40 + c1] = v1 - lse;
}

// ---------------- host side --------------------------------------------------
extern "C" void kernel_launch(void* const* d_in, const int* in_sizes, int n_in,
                              void* d_out, int out_size)
{
    const float* x   = (const float*)d_in[0];
    const int*   ei  = (const int*)  d_in[1];
    const float* W1  = (const float*)d_in[2];
    const float* as1 = (const float*)d_in[3];
    const float* ad1 = (const float*)d_in[4];
    const float* b1  = (const float*)d_in[5];
    const float* W2  = (const float*)d_in[6];
    const float* as2 = (const float*)d_in[7];
    const float* ad2 = (const float*)d_in[8];
    const float* b2  = (const float*)d_in[9];
    float* y = (float*)d_out;

    const int N = in_sizes[0] / F1;
    const int E = in_sizes[1] / 2;
    const int* src = ei;
    const int* dst = ei + E;

    void* p;
    cudaGetSymbolAddress(&p, g_h1);   float* h1   = (float*)p;
    cudaGetSymbolAddress(&p, g_out1); float* o1   = (float*)p;
    cudaGetSymbolAddress(&p, g_h2);   float* h2   = (float*)p;
    cudaGetSymbolAddress(&p, g_out2); float* o2   = (float*)p;
    cudaGetSymbolAddress(&p, g_als1); float* als1 = (float*)p;
    cudaGetSymbolAddress(&p, g_ald1); float* ald1 = (float*)p;
    cudaGetSymbolAddress(&p, g_s1);   float* s1   = (float*)p;
    cudaGetSymbolAddress(&p, g_als2); float* als2 = (float*)p;
    cudaGetSymbolAddress(&p, g_ald2); float* ald2 = (float*)p;
    cudaGetSymbolAddress(&p, g_s2);   float* s2   = (float*)p;

    const int smem1 = (128 * F1 + 64 * 128) * sizeof(float);   // 96 KB
    const int smem2 = (128 * F2 + 64 * 128) * sizeof(float);   // 112 KB
    cudaFuncSetAttribute(gemm_k128<F1, false>,
                         cudaFuncAttributeMaxDynamicSharedMemorySize, smem1);
    cudaFuncSetAttribute(gemm_k128<F2, true>,
                         cudaFuncAttributeMaxDynamicSharedMemorySize, smem2);

    const int TB = 256;
    // ---- zero accumulators ----
    {
        int n4 = N * F1 / 4;
        zero4_kernel<<<(n4 + TB - 1) / TB, TB>>>((float4*)o1, n4);
        n4 = N * F2 / 4;
        zero4_kernel<<<(n4 + TB - 1) / TB, TB>>>((float4*)o2, n4);
        n4 = N;  // N*4 floats
        zero4_kernel<<<(n4 + TB - 1) / TB, TB>>>((float4*)s1, n4);
        zero4_kernel<<<(n4 + TB - 1) / TB, TB>>>((float4*)s2, n4);
    }

    const int gemmBlocks = (N + 63) / 64;
    const int coefBlocks = (N * NH * 32 + TB - 1) / TB;
    const int edgeTBlocks = (E + TB - 1) / TB;            // thread-per-edge
    const int edgeWBlocks = (int)(((size_t)E * 32 + TB - 1) / TB);  // warp-per-edge
    const int nodeWBlocks = (int)(((size_t)N * 32 + TB - 1) / TB);  // warp-per-node

    // ---- layer 1 ----
    gemm_k128<F1, false><<<gemmBlocks, TB, smem1>>>(x, W1, nullptr, h1, N);
    attn_coef<32><<<coefBlocks, TB>>>(h1, as1, ad1, als1, ald1, N);
    edge_softmax_denom<<<edgeTBlocks, TB>>>(src, dst, als1, ald1, s1, E);
    edge_aggregate<F1, 32><<<edgeWBlocks, TB>>>(src, dst, als1, ald1, s1, h1, o1, E);

    // ---- layer 2 ----
    gemm_k128<F2, true><<<gemmBlocks, TB, smem2>>>(o1, W2, b1, h2, N);
    attn_coef<40><<<coefBlocks, TB>>>(h2, as2, ad2, als2, ald2, N);
    edge_softmax_denom<<<edgeTBlocks, TB>>>(src, dst, als2, ald2, s2, E);
    edge_aggregate<F2, 40><<<edgeWBlocks, TB>>>(src, dst, als2, ald2, s2, h2, o2, E);

    // ---- output ----
    final_logsoftmax<<<nodeWBlocks, TB>>>(o2, b2, y, N);
}

// round 2
// speedup vs baseline: 1.7578x; 1.7578x over previous
#include <cuda_runtime.h>
#include <math.h>
#include <stdint.h>

static constexpr int MAXN = 100000;
static constexpr int MAXE = 1600000;
static constexpr int F1   = 128;   // F_in and H*HID
static constexpr int F2   = 160;   // H*NCLS
static constexpr int NH   = 4;
static constexpr float NEG_SLOPE = 0.2f;
static constexpr int SCAN_CHUNK = 512;
static constexpr int MAXNB = (MAXN + SCAN_CHUNK - 1) / SCAN_CHUNK;  // 196

// ---------------- scratch ----------------------------------------------------
__device__ float g_h1  [(size_t)MAXN * F1];
__device__ float g_out1[(size_t)MAXN * F1];
__device__ float g_h2  [(size_t)MAXN * F2];
__device__ float g_out2[(size_t)MAXN * F2];
__device__ float g_als1[(size_t)MAXN * NH];
__device__ float g_ald1[(size_t)MAXN * NH];
__device__ float g_als2[(size_t)MAXN * NH];
__device__ float g_ald2[(size_t)MAXN * NH];
__device__ int   g_cnt [MAXN];
__device__ int   g_rowp[MAXN + 1];
__device__ int   g_excl[MAXN + SCAN_CHUNK];
__device__ int   g_bsum[256];
__device__ int   g_boff[256];
__device__ int   g_col [MAXE];

__device__ __forceinline__ float lrelu(float v) {
    return v > 0.f ? v : NEG_SLOPE * v;
}

// ---------------- CSR build --------------------------------------------------
__global__ void zero_int(int* __restrict__ p, int n) {
    int i = blockIdx.x * blockDim.x + threadIdx.x;
    if (i < n) p[i] = 0;
}

__global__ void count_deg(const int* __restrict__ dst, int* __restrict__ cnt, int E) {
    int e = blockIdx.x * blockDim.x + threadIdx.x;
    if (e < E) atomicAdd(&cnt[dst[e]], 1);
}

// per-chunk exclusive scan (chunk = 512)
__global__ void scan1(const int* __restrict__ cnt, int* __restrict__ excl,
                      int* __restrict__ bsum, int N) {
    __shared__ int sm[SCAN_CHUNK];
    int t = threadIdx.x;
    int i = blockIdx.x * SCAN_CHUNK + t;
    int v = (i < N) ? cnt[i] : 0;
    sm[t] = v;
    __syncthreads();
    for (int o = 1; o < SCAN_CHUNK; o <<= 1) {
        int add = (t >= o) ? sm[t - o] : 0;
        __syncthreads();
        sm[t] += add;
        __syncthreads();
    }
    excl[i] = sm[t] - v;
    if (t == SCAN_CHUNK - 1) bsum[blockIdx.x] = sm[t];
}

// scan of block sums (single block, NB <= 256)
__global__ void scan2(const int* __restrict__ bsum, int* __restrict__ boff, int NB) {
    __shared__ int sm[256];
    int t = threadIdx.x;
    int v = (t < NB) ? bsum[t] : 0;
    sm[t] = v;
    __syncthreads();
    for (int o = 1; o < 256; o <<= 1) {
        int add = (t >= o) ? sm[t - o] : 0;
        __syncthreads();
        sm[t] += add;
        __syncthreads();
    }
    boff[t] = sm[t] - v;
}

__global__ void scan3(const int* __restrict__ excl, const int* __restrict__ boff,
                      int* __restrict__ rowp, int N, int E) {
    int i = blockIdx.x * blockDim.x + threadIdx.x;
    if (i < N) rowp[i] = excl[i] + boff[i / SCAN_CHUNK];
    if (i == N) rowp[N] = E;
}

__global__ void fill_csr(const int* __restrict__ src, const int* __restrict__ dst,
                         const int* __restrict__ rowp, int* __restrict__ cnt,
                         int* __restrict__ col, int E) {
    int e = blockIdx.x * blockDim.x + threadIdx.x;
    if (e >= E) return;
    int d = dst[e];
    int k = atomicAdd(&cnt[d], 1);
    col[rowp[d] + k] = src[e];
}

// ---------------- GEMM: out[N,NOUT] = act(A[N,128] (+bias)) @ W[128,NOUT] ----
template<int NOUT, bool RELU_BIAS>
__global__ void gemm_k128(const float* __restrict__ A,
                          const float* __restrict__ W,
                          const float* __restrict__ bias,
                          float* __restrict__ out, int N)
{
    extern __shared__ float smem[];
    float* sW = smem;               // 128*NOUT
    float* sA = smem + 128 * NOUT;  // 64*128
    const int tid  = threadIdx.x;
    const int warp = tid >> 5;
    const int lane = tid & 31;
    const int row0 = blockIdx.x * 64;

    for (int i = tid * 4; i < 128 * NOUT; i += 256 * 4)
        *reinterpret_cast<float4*>(sW + i) = *reinterpret_cast<const float4*>(W + i);
    for (int i = tid; i < 64 * 128 / 4; i += 256) {
        int idx = i * 4;
        int r   = idx >> 7;
        int k   = idx & 127;
        int gr  = row0 + r;
        float4 v = make_float4(0.f, 0.f, 0.f, 0.f);
        if (gr < N) {
            v = *reinterpret_cast<const float4*>(A + (size_t)gr * 128 + k);
            if (RELU_BIAS) {
                v.x = fmaxf(v.x + bias[k + 0], 0.f);
                v.y = fmaxf(v.y + bias[k + 1], 0.f);
                v.z = fmaxf(v.z + bias[k + 2], 0.f);
                v.w = fmaxf(v.w + bias[k + 3], 0.f);
            }
        }
        *reinterpret_cast<float4*>(sA + idx) = v;
    }
    __syncthreads();

    constexpr int Q = NOUT / 32;
    float acc[8][Q];
#pragma unroll
    for (int i = 0; i < 8; ++i)
#pragma unroll
        for (int q = 0; q < Q; ++q) acc[i][q] = 0.f;

    const float* sArow = sA + (warp * 8) * 128;
#pragma unroll 8
    for (int k = 0; k < 128; ++k) {
        float wv[Q];
#pragma unroll
        for (int q = 0; q < Q; ++q) wv[q] = sW[k * NOUT + lane + 32 * q];
#pragma unroll
        for (int i = 0; i < 8; ++i) {
            float a = sArow[i * 128 + k];
#pragma unroll
            for (int q = 0; q < Q; ++q) acc[i][q] = fmaf(a, wv[q], acc[i][q]);
        }
    }

#pragma unroll
    for (int i = 0; i < 8; ++i) {
        int r = row0 + warp * 8 + i;
        if (r < N) {
#pragma unroll
            for (int q = 0; q < Q; ++q)
                out[(size_t)r * NOUT + lane + 32 * q] = acc[i][q];
        }
    }
}

// ---------------- attention coefficients ------------------------------------
template<int C>
__global__ void attn_coef(const float* __restrict__ Hm,
                          const float* __restrict__ a_s,
                          const float* __restrict__ a_d,
                          float* __restrict__ als, float* __restrict__ ald, int N)
{
    int gw   = (int)((blockIdx.x * (size_t)blockDim.x + threadIdx.x) >> 5);
    int lane = threadIdx.x & 31;
    int n = gw >> 2;
    int h = gw & 3;
    if (n >= N) return;
    const float* base = Hm + (size_t)n * (NH * C) + h * C;
    float vs = 0.f, vd = 0.f;
    for (int c = lane; c < C; c += 32) {
        float hv = base[c];
        vs = fmaf(hv, a_s[h * C + c], vs);
        vd = fmaf(hv, a_d[h * C + c], vd);
    }
#pragma unroll
    for (int o = 16; o; o >>= 1) {
        vs += __shfl_xor_sync(0xffffffffu, vs, o);
        vd += __shfl_xor_sync(0xffffffffu, vd, o);
    }
    if (lane == 0) {
        als[n * NH + h] = vs;
        ald[n * NH + h] = vd;
    }
}

// ---------------- fused CSR aggregation (warp per dst node) ------------------
// out[n] = (sum_e exp(e) * h[src_e]) / (sum_e exp(e))   — single pass, no atomics
__global__ void aggregate_csr_128(const int* __restrict__ rowp,
                                  const int* __restrict__ col,
                                  const float* __restrict__ als,
                                  const float* __restrict__ ald,
                                  const float* __restrict__ Hm,
                                  float* __restrict__ outm, int N)
{
    int n    = (int)((blockIdx.x * (size_t)blockDim.x + threadIdx.x) >> 5);
    int lane = threadIdx.x & 31;
    if (n >= N) return;
    int head = lane >> 3;                       // 32 float4 chunks, 8 per head
    float ald_h = ald[(size_t)n * 4 + head];
    int beg = rowp[n], end = rowp[n + 1];

    float4 acc = make_float4(0.f, 0.f, 0.f, 0.f);
    float den = 0.f;

    int i = beg;
    for (; i + 1 < end; i += 2) {
        int s0 = col[i], s1 = col[i + 1];
        float ex0 = __expf(lrelu(als[(size_t)s0 * 4 + head] + ald_h));
        float ex1 = __expf(lrelu(als[(size_t)s1 * 4 + head] + ald_h));
        float4 h0 = *reinterpret_cast<const float4*>(Hm + (size_t)s0 * 128 + lane * 4);
        float4 h1 = *reinterpret_cast<const float4*>(Hm + (size_t)s1 * 128 + lane * 4);
        acc.x = fmaf(ex0, h0.x, acc.x); acc.y = fmaf(ex0, h0.y, acc.y);
        acc.z = fmaf(ex0, h0.z, acc.z); acc.w = fmaf(ex0, h0.w, acc.w);
        acc.x = fmaf(ex1, h1.x, acc.x); acc.y = fmaf(ex1, h1.y, acc.y);
        acc.z = fmaf(ex1, h1.z, acc.z); acc.w = fmaf(ex1, h1.w, acc.w);
        den += ex0 + ex1;
    }
    if (i < end) {
        int s0 = col[i];
        float ex0 = __expf(lrelu(als[(size_t)s0 * 4 + head] + ald_h));
        float4 h0 = *reinterpret_cast<const float4*>(Hm + (size_t)s0 * 128 + lane * 4);
        acc.x = fmaf(ex0, h0.x, acc.x); acc.y = fmaf(ex0, h0.y, acc.y);
        acc.z = fmaf(ex0, h0.z, acc.z); acc.w = fmaf(ex0, h0.w, acc.w);
        den += ex0;
    }
    float inv = 1.f / (den + 1e-16f);
    float4 o = make_float4(acc.x * inv, acc.y * inv, acc.z * inv, acc.w * inv);
    *reinterpret_cast<float4*>(outm + (size_t)n * 128 + lane * 4) = o;
}

// layer 2: 160 features = 40 float4 chunks; lane owns chunk lane, and chunk
// lane+32 for lane<8 (those are always head 3).
__global__ void aggregate_csr_160(const int* __restrict__ rowp,
                                  const int* __restrict__ col,
                                  const float* __restrict__ als,
                                  const float* __restrict__ ald,
                                  const float* __restrict__ Hm,
                                  float* __restrict__ outm, int N)
{
    int n    = (int)((blockIdx.x * (size_t)blockDim.x + threadIdx.x) >> 5);
    int lane = threadIdx.x & 31;
    if (n >= N) return;
    int head = lane / 10;                       // chunk lane -> head (4*lane)/40
    bool two = (lane < 8);
    float ald_h = ald[(size_t)n * 4 + head];
    int beg = rowp[n], end = rowp[n + 1];

    float4 acc0 = make_float4(0.f, 0.f, 0.f, 0.f);
    float4 acc1 = make_float4(0.f, 0.f, 0.f, 0.f);
    float den = 0.f;

    for (int i = beg; i < end; ++i) {
        int s = col[i];
        float ex = __expf(lrelu(als[(size_t)s * 4 + head] + ald_h));
        float ex3 = __shfl_sync(0xffffffffu, ex, 31);   // head-3 weight
        const float* hrow = Hm + (size_t)s * 160;
        float4 h0 = *reinterpret_cast<const float4*>(hrow + lane * 4);
        acc0.x = fmaf(ex, h0.x, acc0.x); acc0.y = fmaf(ex, h0.y, acc0.y);
        acc0.z = fmaf(ex, h0.z, acc0.z); acc0.w = fmaf(ex, h0.w, acc0.w);
        if (two) {
            float4 h1 = *reinterpret_cast<const float4*>(hrow + 128 + lane * 4);
            acc1.x = fmaf(ex3, h1.x, acc1.x); acc1.y = fmaf(ex3, h1.y, acc1.y);
            acc1.z = fmaf(ex3, h1.z, acc1.z); acc1.w = fmaf(ex3, h1.w, acc1.w);
        }
        den += ex;
    }
    float den3 = __shfl_sync(0xffffffffu, den, 31);
    float inv  = 1.f / (den  + 1e-16f);
    float inv3 = 1.f / (den3 + 1e-16f);
    float* orow = outm + (size_t)n * 160;
    *reinterpret_cast<float4*>(orow + lane * 4) =
        make_float4(acc0.x * inv, acc0.y * inv, acc0.z * inv, acc0.w * inv);
    if (two)
        *reinterpret_cast<float4*>(orow + 128 + lane * 4) =
            make_float4(acc1.x * inv3, acc1.y * inv3, acc1.z * inv3, acc1.w * inv3);
}

// ---------------- final: mean over heads + b2, log_softmax -------------------
__global__ void final_logsoftmax(const float* __restrict__ out2,
                                 const float* __restrict__ b2,
                                 float* __restrict__ y, int N)
{
    int gw   = (int)((blockIdx.x * (size_t)blockDim.x + threadIdx.x) >> 5);
    int lane = threadIdx.x & 31;
    if (gw >= N) return;
    const float* base = out2 + (size_t)gw * F2;
    int c0 = lane;
    int c1 = lane + 32;
    bool has1 = (c1 < 40);

    float v0 = 0.25f * (base[c0] + base[40 + c0] + base[80 + c0] + base[120 + c0]) + b2[c0];
    float v1 = -1e30f;
    if (has1)
        v1 = 0.25f * (base[c1] + base[40 + c1] + base[80 + c1] + base[120 + c1]) + b2[c1];

    float m = fmaxf(v0, v1);
#pragma unroll
    for (int o = 16; o; o >>= 1) m = fmaxf(m, __shfl_xor_sync(0xffffffffu, m, o));
    float se = __expf(v0 - m) + (has1 ? __expf(v1 - m) : 0.f);
#pragma unroll
    for (int o = 16; o; o >>= 1) se += __shfl_xor_sync(0xffffffffu, se, o);
    float lse = logf(se) + m;

    y[(size_t)gw * 40 + c0] = v0 - lse;
    if (has1) y[(size_t)gw * 40 + c1] = v1 - lse;
}

// ---------------- host side --------------------------------------------------
extern "C" void kernel_launch(void* const* d_in, const int* in_sizes, int n_in,
                              void* d_out, int out_size)
{
    const float* x   = (const float*)d_in[0];
    const int*   ei  = (const int*)  d_in[1];
    const float* W1  = (const float*)d_in[2];
    const float* as1 = (const float*)d_in[3];
    const float* ad1 = (const float*)d_in[4];
    const float* b1  = (const float*)d_in[5];
    const float* W2  = (const float*)d_in[6];
    const float* as2 = (const float*)d_in[7];
    const float* ad2 = (const float*)d_in[8];
    const float* b2  = (const float*)d_in[9];
    float* y = (float*)d_out;

    const int N = in_sizes[0] / F1;
    const int E = in_sizes[1] / 2;
    const int* src = ei;
    const int* dst = ei + E;

    void* p;
    cudaGetSymbolAddress(&p, g_h1);   float* h1   = (float*)p;
    cudaGetSymbolAddress(&p, g_out1); float* o1   = (float*)p;
    cudaGetSymbolAddress(&p, g_h2);   float* h2   = (float*)p;
    cudaGetSymbolAddress(&p, g_out2); float* o2   = (float*)p;
    cudaGetSymbolAddress(&p, g_als1); float* als1 = (float*)p;
    cudaGetSymbolAddress(&p, g_ald1); float* ald1 = (float*)p;
    cudaGetSymbolAddress(&p, g_als2); float* als2 = (float*)p;
    cudaGetSymbolAddress(&p, g_ald2); float* ald2 = (float*)p;
    cudaGetSymbolAddress(&p, g_cnt);  int* cnt  = (int*)p;
    cudaGetSymbolAddress(&p, g_rowp); int* rowp = (int*)p;
    cudaGetSymbolAddress(&p, g_excl); int* excl = (int*)p;
    cudaGetSymbolAddress(&p, g_bsum); int* bsum = (int*)p;
    cudaGetSymbolAddress(&p, g_boff); int* boff = (int*)p;
    cudaGetSymbolAddress(&p, g_col);  int* col  = (int*)p;

    const int smem1 = (128 * F1 + 64 * 128) * sizeof(float);
    const int smem2 = (128 * F2 + 64 * 128) * sizeof(float);
    cudaFuncSetAttribute(gemm_k128<F1, false>,
                         cudaFuncAttributeMaxDynamicSharedMemorySize, smem1);
    cudaFuncSetAttribute(gemm_k128<F2, true>,
                         cudaFuncAttributeMaxDynamicSharedMemorySize, smem2);

    const int TB = 256;
    const int NB = (N + SCAN_CHUNK - 1) / SCAN_CHUNK;

    // ---- CSR build (dst-sorted) ----
    zero_int<<<(N + TB - 1) / TB, TB>>>(cnt, N);
    count_deg<<<(E + TB - 1) / TB, TB>>>(dst, cnt, E);
    scan1<<<NB, SCAN_CHUNK>>>(cnt, excl, bsum, N);
    scan2<<<1, 256>>>(bsum, boff, NB);
    scan3<<<(N + 1 + TB - 1) / TB, TB>>>(excl, boff, rowp, N, E);
    zero_int<<<(N + TB - 1) / TB, TB>>>(cnt, N);
    fill_csr<<<(E + TB - 1) / TB, TB>>>(src, dst, rowp, cnt, col, E);

    const int gemmBlocks  = (N + 63) / 64;
    const int coefBlocks  = (N * NH * 32 + TB - 1) / TB;
    const int nodeWBlocks = (int)(((size_t)N * 32 + TB - 1) / TB);

    // ---- layer 1 ----
    gemm_k128<F1, false><<<gemmBlocks, TB, smem1>>>(x, W1, nullptr, h1, N);
    attn_coef<32><<<coefBlocks, TB>>>(h1, as1, ad1, als1, ald1, N);
    aggregate_csr_128<<<nodeWBlocks, TB>>>(rowp, col, als1, ald1, h1, o1, N);

    // ---- layer 2 ----
    gemm_k128<F2, true><<<gemmBlocks, TB, smem2>>>(o1, W2, b1, h2, N);
    attn_coef<40><<<coefBlocks, TB>>>(h2, as2, ad2, als2, ald2, N);
    aggregate_csr_160<<<nodeWBlocks, TB>>>(rowp, col, als2, ald2, h2, o2, N);

    // ---- output ----
    final_logsoftmax<<<nodeWBlocks, TB>>>(o2, b2, y, N);
}

// round 3
// speedup vs baseline: 1.9539x; 1.1116x over previous
#include <cuda_runtime.h>
#include <math.h>
#include <stdint.h>

static constexpr int MAXN = 100000;
static constexpr int MAXE = 1600000;
static constexpr int F1   = 128;   // F_in and H*HID
static constexpr int F2   = 160;   // H*NCLS
static constexpr int NH   = 4;
static constexpr float NEG_SLOPE = 0.2f;
static constexpr int SCAN_CHUNK = 512;

// ---------------- scratch ----------------------------------------------------
__device__ float g_h1  [(size_t)MAXN * F1];
__device__ float g_out1[(size_t)MAXN * F1];
__device__ float g_h2  [(size_t)MAXN * F2];
__device__ float g_als1[(size_t)MAXN * NH];
__device__ float g_ald1[(size_t)MAXN * NH];
__device__ float g_als2[(size_t)MAXN * NH];
__device__ float g_ald2[(size_t)MAXN * NH];
__device__ int   g_cnt [2 * MAXN];           // [0,N): count pass, [N,2N): fill pass
__device__ int   g_rowp[MAXN + 1];
__device__ int   g_excl[MAXN + SCAN_CHUNK];
__device__ int   g_bsum[256];
__device__ int   g_boff[256];
__device__ int   g_col [MAXE];

__device__ __forceinline__ float lrelu(float v) {
    return v > 0.f ? v : NEG_SLOPE * v;
}

// ---------------- CSR build --------------------------------------------------
__global__ void zero_int(int* __restrict__ p, int n) {
    int i = blockIdx.x * blockDim.x + threadIdx.x;
    if (i < n) p[i] = 0;
}

__global__ void count_deg(const int* __restrict__ dst, int* __restrict__ cnt, int E) {
    int e = blockIdx.x * blockDim.x + threadIdx.x;
    if (e < E) atomicAdd(&cnt[dst[e]], 1);
}

__global__ void scan1(const int* __restrict__ cnt, int* __restrict__ excl,
                      int* __restrict__ bsum, int N) {
    __shared__ int sm[SCAN_CHUNK];
    int t = threadIdx.x;
    int i = blockIdx.x * SCAN_CHUNK + t;
    int v = (i < N) ? cnt[i] : 0;
    sm[t] = v;
    __syncthreads();
    for (int o = 1; o < SCAN_CHUNK; o <<= 1) {
        int add = (t >= o) ? sm[t - o] : 0;
        __syncthreads();
        sm[t] += add;
        __syncthreads();
    }
    excl[i] = sm[t] - v;
    if (t == SCAN_CHUNK - 1) bsum[blockIdx.x] = sm[t];
}

__global__ void scan2(const int* __restrict__ bsum, int* __restrict__ boff, int NB) {
    __shared__ int sm[256];
    int t = threadIdx.x;
    int v = (t < NB) ? bsum[t] : 0;
    sm[t] = v;
    __syncthreads();
    for (int o = 1; o < 256; o <<= 1) {
        int add = (t >= o) ? sm[t - o] : 0;
        __syncthreads();
        sm[t] += add;
        __syncthreads();
    }
    boff[t] = sm[t] - v;
}

__global__ void scan3(const int* __restrict__ excl, const int* __restrict__ boff,
                      int* __restrict__ rowp, int N, int E) {
    int i = blockIdx.x * blockDim.x + threadIdx.x;
    if (i < N) rowp[i] = excl[i] + boff[i / SCAN_CHUNK];
    if (i == N) rowp[N] = E;
}

__global__ void fill_csr(const int* __restrict__ src, const int* __restrict__ dst,
                         const int* __restrict__ rowp, int* __restrict__ cnt2,
                         int* __restrict__ col, int E) {
    int e = blockIdx.x * blockDim.x + threadIdx.x;
    if (e >= E) return;
    int d = dst[e];
    int k = atomicAdd(&cnt2[d], 1);
    col[rowp[d] + k] = src[e];
}

// ---------------- GEMM + fused attention-coefficient epilogue ---------------
// out[N,NOUT] = act(A[N,128] (+bias)) @ W[128,NOUT]
// als[n,h] = sum_c out[n, h*C+c] * a_s[h*C+c]   (likewise ald)
// Warp w owns rows [w*8, w*8+8); each row's NOUT cols live across the warp
// as col = lane + 32*q, so attention dots are butterfly reductions.
template<int NOUT, bool RELU_BIAS>
__global__ void gemm_k128(const float* __restrict__ A,
                          const float* __restrict__ W,
                          const float* __restrict__ bias,
                          const float* __restrict__ a_s,
                          const float* __restrict__ a_d,
                          float* __restrict__ out,
                          float* __restrict__ als,
                          float* __restrict__ ald, int N)
{
    extern __shared__ float smem[];
    float* sW = smem;               // 128*NOUT
    float* sA = smem + 128 * NOUT;  // 64*128
    const int tid  = threadIdx.x;
    const int warp = tid >> 5;
    const int lane = tid & 31;
    const int row0 = blockIdx.x * 64;

    for (int i = tid * 4; i < 128 * NOUT; i += 256 * 4)
        *reinterpret_cast<float4*>(sW + i) = *reinterpret_cast<const float4*>(W + i);
    for (int i = tid; i < 64 * 128 / 4; i += 256) {
        int idx = i * 4;
        int r   = idx >> 7;
        int k   = idx & 127;
        int gr  = row0 + r;
        float4 v = make_float4(0.f, 0.f, 0.f, 0.f);
        if (gr < N) {
            v = *reinterpret_cast<const float4*>(A + (size_t)gr * 128 + k);
            if (RELU_BIAS) {
                v.x = fmaxf(v.x + bias[k + 0], 0.f);
                v.y = fmaxf(v.y + bias[k + 1], 0.f);
                v.z = fmaxf(v.z + bias[k + 2], 0.f);
                v.w = fmaxf(v.w + bias[k + 3], 0.f);
            }
        }
        *reinterpret_cast<float4*>(sA + idx) = v;
    }
    __syncthreads();

    constexpr int Q = NOUT / 32;
    float acc[8][Q];
#pragma unroll
    for (int i = 0; i < 8; ++i)
#pragma unroll
        for (int q = 0; q < Q; ++q) acc[i][q] = 0.f;

    const float* sArow = sA + (warp * 8) * 128;
#pragma unroll 8
    for (int k = 0; k < 128; ++k) {
        float wv[Q];
#pragma unroll
        for (int q = 0; q < Q; ++q) wv[q] = sW[k * NOUT + lane + 32 * q];
#pragma unroll
        for (int i = 0; i < 8; ++i) {
            float a = sArow[i * 128 + k];
#pragma unroll
            for (int q = 0; q < Q; ++q) acc[i][q] = fmaf(a, wv[q], acc[i][q]);
        }
    }

    // per-warp attention vectors (small, L1-resident)
    float asv[Q], adv[Q];
#pragma unroll
    for (int q = 0; q < Q; ++q) {
        asv[q] = __ldg(&a_s[lane + 32 * q]);
        adv[q] = __ldg(&a_d[lane + 32 * q]);
    }

#pragma unroll
    for (int i = 0; i < 8; ++i) {
        int r = row0 + warp * 8 + i;
        if (r >= N) continue;
#pragma unroll
        for (int q = 0; q < Q; ++q)
            out[(size_t)r * NOUT + lane + 32 * q] = acc[i][q];

        if (NOUT == 128) {
            // head h == q exactly (C = 32)
#pragma unroll
            for (int h = 0; h < 4; ++h) {
                float vs = acc[i][h] * asv[h];
                float vd = acc[i][h] * adv[h];
#pragma unroll
                for (int o = 16; o; o >>= 1) {
                    vs += __shfl_xor_sync(0xffffffffu, vs, o);
                    vd += __shfl_xor_sync(0xffffffffu, vd, o);
                }
                if (lane == 0) {
                    als[(size_t)r * 4 + h] = vs;
                    ald[(size_t)r * 4 + h] = vd;
                }
            }
        } else {
            // NOUT = 160, C = 40: head(col) straddles q segments
            float ps0 = 0.f, ps1 = 0.f, ps2 = 0.f, ps3 = 0.f;
            float pd0 = 0.f, pd1 = 0.f, pd2 = 0.f, pd3 = 0.f;
            float x, z;
            x = acc[i][0] * asv[0]; z = acc[i][0] * adv[0];
            ps0 += x; pd0 += z;
            x = acc[i][1] * asv[1]; z = acc[i][1] * adv[1];
            if (lane < 8) { ps0 += x; pd0 += z; } else { ps1 += x; pd1 += z; }
            x = acc[i][2] * asv[2]; z = acc[i][2] * adv[2];
            if (lane < 16) { ps1 += x; pd1 += z; } else { ps2 += x; pd2 += z; }
            x = acc[i][3] * asv[3]; z = acc[i][3] * adv[3];
            if (lane < 24) { ps2 += x; pd2 += z; } else { ps3 += x; pd3 += z; }
            x = acc[i][4] * asv[4]; z = acc[i][4] * adv[4];
            ps3 += x; pd3 += z;

            float ps[4] = {ps0, ps1, ps2, ps3};
            float pd[4] = {pd0, pd1, pd2, pd3};
#pragma unroll
            for (int h = 0; h < 4; ++h) {
                float vs = ps[h], vd = pd[h];
#pragma unroll
                for (int o = 16; o; o >>= 1) {
                    vs += __shfl_xor_sync(0xffffffffu, vs, o);
                    vd += __shfl_xor_sync(0xffffffffu, vd, o);
                }
                if (lane == 0) {
                    als[(size_t)r * 4 + h] = vs;
                    ald[(size_t)r * 4 + h] = vd;
                }
            }
        }
    }
}

// ---------------- fused CSR aggregation, layer 1 (warp per dst node) ---------
__global__ void aggregate_csr_128(const int* __restrict__ rowp,
                                  const int* __restrict__ col,
                                  const float* __restrict__ als,
                                  const float* __restrict__ ald,
                                  const float* __restrict__ Hm,
                                  float* __restrict__ outm, int N)
{
    int n    = (int)((blockIdx.x * (size_t)blockDim.x + threadIdx.x) >> 5);
    int lane = threadIdx.x & 31;
    if (n >= N) return;
    int head = lane >> 3;
    float ald_h = ald[(size_t)n * 4 + head];
    int beg = rowp[n], end = rowp[n + 1];

    float4 acc = make_float4(0.f, 0.f, 0.f, 0.f);
    float den = 0.f;

    int i = beg;
    for (; i + 1 < end; i += 2) {
        int s0 = col[i], s1 = col[i + 1];
        float ex0 = __expf(lrelu(als[(size_t)s0 * 4 + head] + ald_h));
        float ex1 = __expf(lrelu(als[(size_t)s1 * 4 + head] + ald_h));
        float4 h0 = *reinterpret_cast<const float4*>(Hm + (size_t)s0 * 128 + lane * 4);
        float4 h1 = *reinterpret_cast<const float4*>(Hm + (size_t)s1 * 128 + lane * 4);
        acc.x = fmaf(ex0, h0.x, acc.x); acc.y = fmaf(ex0, h0.y, acc.y);
        acc.z = fmaf(ex0, h0.z, acc.z); acc.w = fmaf(ex0, h0.w, acc.w);
        acc.x = fmaf(ex1, h1.x, acc.x); acc.y = fmaf(ex1, h1.y, acc.y);
        acc.z = fmaf(ex1, h1.z, acc.z); acc.w = fmaf(ex1, h1.w, acc.w);
        den += ex0 + ex1;
    }
    if (i < end) {
        int s0 = col[i];
        float ex0 = __expf(lrelu(als[(size_t)s0 * 4 + head] + ald_h));
        float4 h0 = *reinterpret_cast<const float4*>(Hm + (size_t)s0 * 128 + lane * 4);
        acc.x = fmaf(ex0, h0.x, acc.x); acc.y = fmaf(ex0, h0.y, acc.y);
        acc.z = fmaf(ex0, h0.z, acc.z); acc.w = fmaf(ex0, h0.w, acc.w);
        den += ex0;
    }
    float inv = 1.f / (den + 1e-16f);
    *reinterpret_cast<float4*>(outm + (size_t)n * 128 + lane * 4) =
        make_float4(acc.x * inv, acc.y * inv, acc.z * inv, acc.w * inv);
}

// ---------------- fused layer-2 aggregation + head-mean + log_softmax --------
__global__ void aggregate_csr_160_final(const int* __restrict__ rowp,
                                        const int* __restrict__ col,
                                        const float* __restrict__ als,
                                        const float* __restrict__ ald,
                                        const float* __restrict__ Hm,
                                        const float* __restrict__ b2,
                                        float* __restrict__ y, int N)
{
    __shared__ __align__(16) float sbuf[8][160];
    int wid  = threadIdx.x >> 5;
    int n    = (int)((blockIdx.x * (size_t)blockDim.x + threadIdx.x) >> 5);
    int lane = threadIdx.x & 31;
    if (n >= N) return;
    int head = lane / 10;                       // chunk lane -> head
    bool two = (lane < 8);
    float ald_h = ald[(size_t)n * 4 + head];
    int beg = rowp[n], end = rowp[n + 1];

    float4 acc0 = make_float4(0.f, 0.f, 0.f, 0.f);
    float4 acc1 = make_float4(0.f, 0.f, 0.f, 0.f);
    float den = 0.f;

    for (int i = beg; i < end; ++i) {
        int s = col[i];
        float ex = __expf(lrelu(als[(size_t)s * 4 + head] + ald_h));
        float ex3 = __shfl_sync(0xffffffffu, ex, 31);   // head-3 weight
        const float* hrow = Hm + (size_t)s * 160;
        float4 h0 = *reinterpret_cast<const float4*>(hrow + lane * 4);
        acc0.x = fmaf(ex, h0.x, acc0.x); acc0.y = fmaf(ex, h0.y, acc0.y);
        acc0.z = fmaf(ex, h0.z, acc0.z); acc0.w = fmaf(ex, h0.w, acc0.w);
        if (two) {
            float4 h1 = *reinterpret_cast<const float4*>(hrow + 128 + lane * 4);
            acc1.x = fmaf(ex3, h1.x, acc1.x); acc1.y = fmaf(ex3, h1.y, acc1.y);
            acc1.z = fmaf(ex3, h1.z, acc1.z); acc1.w = fmaf(ex3, h1.w, acc1.w);
        }
        den += ex;
    }
    float den3 = __shfl_sync(0xffffffffu, den, 31);
    float inv  = 1.f / (den  + 1e-16f);
    float inv3 = 1.f / (den3 + 1e-16f);

    *reinterpret_cast<float4*>(&sbuf[wid][lane * 4]) =
        make_float4(acc0.x * inv, acc0.y * inv, acc0.z * inv, acc0.w * inv);
    if (two)
        *reinterpret_cast<float4*>(&sbuf[wid][128 + lane * 4]) =
            make_float4(acc1.x * inv3, acc1.y * inv3, acc1.z * inv3, acc1.w * inv3);
    __syncwarp();

    const float* S = sbuf[wid];
    int c0 = lane;              // < 40 always
    int c1 = lane + 32;         // valid for lane < 8
    bool has1 = (c1 < 40);

    float v0 = 0.25f * (S[c0] + S[40 + c0] + S[80 + c0] + S[120 + c0]) + __ldg(&b2[c0]);
    float v1 = -1e30f;
    if (has1)
        v1 = 0.25f * (S[c1] + S[40 + c1] + S[80 + c1] + S[120 + c1]) + __ldg(&b2[c1]);

    float m = fmaxf(v0, v1);
#pragma unroll
    for (int o = 16; o; o >>= 1) m = fmaxf(m, __shfl_xor_sync(0xffffffffu, m, o));
    float se = __expf(v0 - m) + (has1 ? __expf(v1 - m) : 0.f);
#pragma unroll
    for (int o = 16; o; o >>= 1) se += __shfl_xor_sync(0xffffffffu, se, o);
    float lse = logf(se) + m;

    y[(size_t)n * 40 + c0] = v0 - lse;
    if (has1) y[(size_t)n * 40 + c1] = v1 - lse;
}

// ---------------- host side --------------------------------------------------
extern "C" void kernel_launch(void* const* d_in, const int* in_sizes, int n_in,
                              void* d_out, int out_size)
{
    const float* x   = (const float*)d_in[0];
    const int*   ei  = (const int*)  d_in[1];
    const float* W1  = (const float*)d_in[2];
    const float* as1 = (const float*)d_in[3];
    const float* ad1 = (const float*)d_in[4];
    const float* b1  = (const float*)d_in[5];
    const float* W2  = (const float*)d_in[6];
    const float* as2 = (const float*)d_in[7];
    const float* ad2 = (const float*)d_in[8];
    const float* b2  = (const float*)d_in[9];
    float* y = (float*)d_out;

    const int N = in_sizes[0] / F1;
    const int E = in_sizes[1] / 2;
    const int* src = ei;
    const int* dst = ei + E;

    void* p;
    cudaGetSymbolAddress(&p, g_h1);   float* h1   = (float*)p;
    cudaGetSymbolAddress(&p, g_out1); float* o1   = (float*)p;
    cudaGetSymbolAddress(&p, g_h2);   float* h2   = (float*)p;
    cudaGetSymbolAddress(&p, g_als1); float* als1 = (float*)p;
    cudaGetSymbolAddress(&p, g_ald1); float* ald1 = (float*)p;
    cudaGetSymbolAddress(&p, g_als2); float* als2 = (float*)p;
    cudaGetSymbolAddress(&p, g_ald2); float* ald2 = (float*)p;
    cudaGetSymbolAddress(&p, g_cnt);  int* cnt  = (int*)p;
    cudaGetSymbolAddress(&p, g_rowp); int* rowp = (int*)p;
    cudaGetSymbolAddress(&p, g_excl); int* excl = (int*)p;
    cudaGetSymbolAddress(&p, g_bsum); int* bsum = (int*)p;
    cudaGetSymbolAddress(&p, g_boff); int* boff = (int*)p;
    cudaGetSymbolAddress(&p, g_col);  int* col  = (int*)p;
    int* cnt2 = cnt + MAXN;

    const int smem1 = (128 * F1 + 64 * 128) * sizeof(float);
    const int smem2 = (128 * F2 + 64 * 128) * sizeof(float);
    cudaFuncSetAttribute(gemm_k128<F1, false>,
                         cudaFuncAttributeMaxDynamicSharedMemorySize, smem1);
    cudaFuncSetAttribute(gemm_k128<F2, true>,
                         cudaFuncAttributeMaxDynamicSharedMemorySize, smem2);

    const int TB = 256;
    const int NB = (N + SCAN_CHUNK - 1) / SCAN_CHUNK;
    const int gemmBlocks  = (N + 63) / 64;
    const int nodeWBlocks = (int)(((size_t)N * 32 + TB - 1) / TB);

    // launches 0-4: CSR count + scan (gemm1 is launch #5 for ncu -s 5 -c 1)
    zero_int<<<(2 * MAXN + TB - 1) / TB, TB>>>(cnt, 2 * MAXN);
    count_deg<<<(E + TB - 1) / TB, TB>>>(dst, cnt, E);
    scan1<<<NB, SCAN_CHUNK>>>(cnt, excl, bsum, N);
    scan2<<<1, 256>>>(bsum, boff, NB);
    scan3<<<(N + 1 + TB - 1) / TB, TB>>>(excl, boff, rowp, N, E);

    // launch 5: layer-1 GEMM (+ fused attention coefficients)
    gemm_k128<F1, false><<<gemmBlocks, TB, smem1>>>(
        x, W1, nullptr, as1, ad1, h1, als1, ald1, N);

    // launch 6: CSR fill
    fill_csr<<<(E + TB - 1) / TB, TB>>>(src, dst, rowp, cnt2, col, E);

    // launch 7: layer-1 aggregation
    aggregate_csr_128<<<nodeWBlocks, TB>>>(rowp, col, als1, ald1, h1, o1, N);

    // launch 8: layer-2 GEMM (+ relu+bias on input, fused attention coefficients)
    gemm_k128<F2, true><<<gemmBlocks, TB, smem2>>>(
        o1, W2, b1, as2, ad2, h2, als2, ald2, N);

    // launch 9: layer-2 aggregation + head mean + log_softmax
    aggregate_csr_160_final<<<nodeWBlocks, TB>>>(rowp, col, als2, ald2, h2, b2, y, N);
}

// round 4
// speedup vs baseline: 2.2351x; 1.1439x over previous
#include <cuda_runtime.h>
#include <math.h>
#include <stdint.h>

static constexpr int MAXN = 100000;
static constexpr int MAXE = 1600000;
static constexpr int F1   = 128;   // F_in and H*HID
static constexpr int F2   = 160;   // H*NCLS
static constexpr int NH   = 4;
static constexpr float NEG_SLOPE = 0.2f;
static constexpr int SCAN_CHUNK = 512;

typedef unsigned long long ull;

// ---------------- scratch ----------------------------------------------------
__device__ float g_h1  [(size_t)MAXN * F1];
__device__ float g_out1[(size_t)MAXN * F1];
__device__ float g_h2  [(size_t)MAXN * F2];
__device__ float g_als1[(size_t)MAXN * NH];
__device__ float g_ald1[(size_t)MAXN * NH];
__device__ float g_als2[(size_t)MAXN * NH];
__device__ float g_ald2[(size_t)MAXN * NH];
__device__ int   g_cnt [2 * MAXN];
__device__ int   g_rowp[MAXN + 1];
__device__ int   g_excl[MAXN + SCAN_CHUNK];
__device__ int   g_bsum[256];
__device__ int   g_boff[256];
__device__ int   g_col [MAXE];

__device__ __forceinline__ float lrelu(float v) {
    return v > 0.f ? v : NEG_SLOPE * v;
}

// ---------------- packed f32x2 helpers (sm_103a FFMA2) -----------------------
__device__ __forceinline__ ull pack2(float a, float b) {
    ull r; asm("mov.b64 %0, {%1, %2};" : "=l"(r) : "f"(a), "f"(b)); return r;
}
__device__ __forceinline__ void unpack2(ull v, float& a, float& b) {
    asm("mov.b64 {%0, %1}, %2;" : "=f"(a), "=f"(b) : "l"(v));
}
__device__ __forceinline__ void fma2(ull& d, ull a, ull b) {
    asm("fma.rn.f32x2 %0, %1, %2, %0;" : "+l"(d) : "l"(a), "l"(b));
}

// ---------------- CSR build --------------------------------------------------
__global__ void zero_int(int* __restrict__ p, int n) {
    int i = blockIdx.x * blockDim.x + threadIdx.x;
    if (i < n) p[i] = 0;
}

__global__ void count_deg(const int* __restrict__ dst, int* __restrict__ cnt, int E) {
    int e = blockIdx.x * blockDim.x + threadIdx.x;
    if (e < E) atomicAdd(&cnt[dst[e]], 1);
}

__global__ void scan1(const int* __restrict__ cnt, int* __restrict__ excl,
                      int* __restrict__ bsum, int N) {
    __shared__ int sm[SCAN_CHUNK];
    int t = threadIdx.x;
    int i = blockIdx.x * SCAN_CHUNK + t;
    int v = (i < N) ? cnt[i] : 0;
    sm[t] = v;
    __syncthreads();
    for (int o = 1; o < SCAN_CHUNK; o <<= 1) {
        int add = (t >= o) ? sm[t - o] : 0;
        __syncthreads();
        sm[t] += add;
        __syncthreads();
    }
    excl[i] = sm[t] - v;
    if (t == SCAN_CHUNK - 1) bsum[blockIdx.x] = sm[t];
}

__global__ void scan2(const int* __restrict__ bsum, int* __restrict__ boff, int NB) {
    __shared__ int sm[256];
    int t = threadIdx.x;
    int v = (t < NB) ? bsum[t] : 0;
    sm[t] = v;
    __syncthreads();
    for (int o = 1; o < 256; o <<= 1) {
        int add = (t >= o) ? sm[t - o] : 0;
        __syncthreads();
        sm[t] += add;
        __syncthreads();
    }
    boff[t] = sm[t] - v;
}

__global__ void scan3(const int* __restrict__ excl, const int* __restrict__ boff,
                      int* __restrict__ rowp, int N, int E) {
    int i = blockIdx.x * blockDim.x + threadIdx.x;
    if (i < N) rowp[i] = excl[i] + boff[i / SCAN_CHUNK];
    if (i == N) rowp[N] = E;
}

__global__ void fill_csr(const int* __restrict__ src, const int* __restrict__ dst,
                         const int* __restrict__ rowp, int* __restrict__ cnt2,
                         int* __restrict__ col, int E) {
    int e = blockIdx.x * blockDim.x + threadIdx.x;
    if (e >= E) return;
    int d = dst[e];
    int k = atomicAdd(&cnt2[d], 1);
    col[rowp[d] + k] = src[e];
}

// ---------------- GEMM (f32x2 packed) + fused attention epilogue -------------
// out[N,NOUT] = act(A[N,128] (+bias)) @ W[128,NOUT]
// Lane owns column pairs col = 2*lane + 64*q (q < NOUT/64) and, for NOUT=160,
// a scalar column 128+lane. Warp w owns rows [w*8, w*8+8).
template<int NOUT, bool RELU_BIAS>
__global__ void __launch_bounds__(256, 2)
gemm_k128(const float* __restrict__ A,
          const float* __restrict__ W,
          const float* __restrict__ bias,
          const float* __restrict__ a_s,
          const float* __restrict__ a_d,
          float* __restrict__ out,
          float* __restrict__ als,
          float* __restrict__ ald, int N)
{
    extern __shared__ float smem[];
    float* sW = smem;               // 128*NOUT
    float* sA = smem + 128 * NOUT;  // 64*128
    const int tid  = threadIdx.x;
    const int warp = tid >> 5;
    const int lane = tid & 31;
    const int row0 = blockIdx.x * 64;

    for (int i = tid * 4; i < 128 * NOUT; i += 256 * 4)
        *reinterpret_cast<float4*>(sW + i) = *reinterpret_cast<const float4*>(W + i);
    for (int i = tid; i < 64 * 128 / 4; i += 256) {
        int idx = i * 4;
        int r   = idx >> 7;
        int k   = idx & 127;
        int gr  = row0 + r;
        float4 v = make_float4(0.f, 0.f, 0.f, 0.f);
        if (gr < N) {
            v = *reinterpret_cast<const float4*>(A + (size_t)gr * 128 + k);
            if (RELU_BIAS) {
                v.x = fmaxf(v.x + bias[k + 0], 0.f);
                v.y = fmaxf(v.y + bias[k + 1], 0.f);
                v.z = fmaxf(v.z + bias[k + 2], 0.f);
                v.w = fmaxf(v.w + bias[k + 3], 0.f);
            }
        }
        *reinterpret_cast<float4*>(sA + idx) = v;
    }
    __syncthreads();

    constexpr int P = NOUT / 64;          // packed pairs per lane (2 or 2)
    constexpr bool HAS_S = (NOUT == 160); // extra scalar column
    ull acc2[8][P];
    float accS[8];
#pragma unroll
    for (int i = 0; i < 8; ++i) {
#pragma unroll
        for (int p = 0; p < P; ++p) acc2[i][p] = 0ull;
        accS[i] = 0.f;
    }

    const float* sArow = sA + (warp * 8) * 128;
    const int c2 = 2 * lane;

    for (int k0 = 0; k0 < 128; k0 += 4) {
        float4 av[8];
#pragma unroll
        for (int i = 0; i < 8; ++i)
            av[i] = *reinterpret_cast<const float4*>(sArow + i * 128 + k0);
#pragma unroll
        for (int kk = 0; kk < 4; ++kk) {
            const float* wk = sW + (k0 + kk) * NOUT;
            ull w[P];
#pragma unroll
            for (int p = 0; p < P; ++p)
                w[p] = *reinterpret_cast<const ull*>(wk + c2 + 64 * p);
            float ws = HAS_S ? wk[128 + lane] : 0.f;
#pragma unroll
            for (int i = 0; i < 8; ++i) {
                float a = (kk == 0) ? av[i].x : (kk == 1) ? av[i].y
                        : (kk == 2) ? av[i].z : av[i].w;
                ull ap = pack2(a, a);
#pragma unroll
                for (int p = 0; p < P; ++p) fma2(acc2[i][p], ap, w[p]);
                if (HAS_S) accS[i] = fmaf(a, ws, accS[i]);
            }
        }
    }

    // attention vectors for owned columns
    float2 asp[P], adp[P];
#pragma unroll
    for (int p = 0; p < P; ++p) {
        asp[p] = *reinterpret_cast<const float2*>(a_s + c2 + 64 * p);
        adp[p] = *reinterpret_cast<const float2*>(a_d + c2 + 64 * p);
    }
    float asS = HAS_S ? a_s[128 + lane] : 0.f;
    float adS = HAS_S ? a_d[128 + lane] : 0.f;

#pragma unroll
    for (int i = 0; i < 8; ++i) {
        int r = row0 + warp * 8 + i;
        if (r >= N) continue;

        float a0, a1, b0, b1;
        unpack2(acc2[i][0], a0, a1);
        unpack2(acc2[i][1], b0, b1);

        // store (float2, coalesced)
        *reinterpret_cast<ull*>(out + (size_t)r * NOUT + c2)      = acc2[i][0];
        *reinterpret_cast<ull*>(out + (size_t)r * NOUT + 64 + c2) = acc2[i][1];
        if (HAS_S) out[(size_t)r * NOUT + 128 + lane] = accS[i];

        if (NOUT == 128) {
            // cols q=0: heads 0|1 split at lane 16; q=1: heads 2|3 split at 16.
            float vsA = a0 * asp[0].x + a1 * asp[0].y;
            float vdA = a0 * adp[0].x + a1 * adp[0].y;
            float vsB = b0 * asp[1].x + b1 * asp[1].y;
            float vdB = b0 * adp[1].x + b1 * adp[1].y;
#pragma unroll
            for (int o = 8; o; o >>= 1) {
                vsA += __shfl_xor_sync(0xffffffffu, vsA, o);
                vdA += __shfl_xor_sync(0xffffffffu, vdA, o);
                vsB += __shfl_xor_sync(0xffffffffu, vsB, o);
                vdB += __shfl_xor_sync(0xffffffffu, vdB, o);
            }
            if (lane == 0) {
                als[(size_t)r * 4 + 0] = vsA;
                ald[(size_t)r * 4 + 0] = vdA;
                als[(size_t)r * 4 + 2] = vsB;
                ald[(size_t)r * 4 + 2] = vdB;
            } else if (lane == 16) {
                als[(size_t)r * 4 + 1] = vsA;
                ald[(size_t)r * 4 + 1] = vdA;
                als[(size_t)r * 4 + 3] = vsB;
                ald[(size_t)r * 4 + 3] = vdB;
            }
        } else {
            // NOUT=160, C=40. Pair cols never straddle head boundaries (even).
            float s0 = 0.f, s1 = 0.f, s2 = 0.f, s3 = 0.f;
            float d0 = 0.f, d1 = 0.f, d2 = 0.f, d3 = 0.f;
            float vA_s = a0 * asp[0].x + a1 * asp[0].y;
            float vA_d = a0 * adp[0].x + a1 * adp[0].y;
            if (lane < 20) { s0 += vA_s; d0 += vA_d; } else { s1 += vA_s; d1 += vA_d; }
            float vB_s = b0 * asp[1].x + b1 * asp[1].y;
            float vB_d = b0 * adp[1].x + b1 * adp[1].y;
            if (lane < 8)       { s1 += vB_s; d1 += vB_d; }
            else if (lane < 28) { s2 += vB_s; d2 += vB_d; }
            else                { s3 += vB_s; d3 += vB_d; }
            s3 += accS[i] * asS;
            d3 += accS[i] * adS;
#pragma unroll
            for (int o = 16; o; o >>= 1) {
                s0 += __shfl_xor_sync(0xffffffffu, s0, o);
                d0 += __shfl_xor_sync(0xffffffffu, d0, o);
                s1 += __shfl_xor_sync(0xffffffffu, s1, o);
                d1 += __shfl_xor_sync(0xffffffffu, d1, o);
                s2 += __shfl_xor_sync(0xffffffffu, s2, o);
                d2 += __shfl_xor_sync(0xffffffffu, d2, o);
                s3 += __shfl_xor_sync(0xffffffffu, s3, o);
                d3 += __shfl_xor_sync(0xffffffffu, d3, o);
            }
            if (lane == 0) {
                als[(size_t)r * 4 + 0] = s0; ald[(size_t)r * 4 + 0] = d0;
                als[(size_t)r * 4 + 1] = s1; ald[(size_t)r * 4 + 1] = d1;
                als[(size_t)r * 4 + 2] = s2; ald[(size_t)r * 4 + 2] = d2;
                als[(size_t)r * 4 + 3] = s3; ald[(size_t)r * 4 + 3] = d3;
            }
        }
    }
}

// ---------------- fused CSR aggregation, layer 1 (warp per dst node) ---------
__global__ void aggregate_csr_128(const int* __restrict__ rowp,
                                  const int* __restrict__ col,
                                  const float* __restrict__ als,
                                  const float* __restrict__ ald,
                                  const float* __restrict__ Hm,
                                  float* __restrict__ outm, int N)
{
    int n    = (int)((blockIdx.x * (size_t)blockDim.x + threadIdx.x) >> 5);
    int lane = threadIdx.x & 31;
    if (n >= N) return;
    int head = lane >> 3;
    float ald_h = ald[(size_t)n * 4 + head];
    int beg = rowp[n], end = rowp[n + 1];

    float4 acc = make_float4(0.f, 0.f, 0.f, 0.f);
    float den = 0.f;

    int i = beg;
    for (; i + 1 < end; i += 2) {
        int s0 = col[i], s1 = col[i + 1];
        float ex0 = __expf(lrelu(als[(size_t)s0 * 4 + head] + ald_h));
        float ex1 = __expf(lrelu(als[(size_t)s1 * 4 + head] + ald_h));
        float4 h0 = *reinterpret_cast<const float4*>(Hm + (size_t)s0 * 128 + lane * 4);
        float4 h1 = *reinterpret_cast<const float4*>(Hm + (size_t)s1 * 128 + lane * 4);
        acc.x = fmaf(ex0, h0.x, acc.x); acc.y = fmaf(ex0, h0.y, acc.y);
        acc.z = fmaf(ex0, h0.z, acc.z); acc.w = fmaf(ex0, h0.w, acc.w);
        acc.x = fmaf(ex1, h1.x, acc.x); acc.y = fmaf(ex1, h1.y, acc.y);
        acc.z = fmaf(ex1, h1.z, acc.z); acc.w = fmaf(ex1, h1.w, acc.w);
        den += ex0 + ex1;
    }
    if (i < end) {
        int s0 = col[i];
        float ex0 = __expf(lrelu(als[(size_t)s0 * 4 + head] + ald_h));
        float4 h0 = *reinterpret_cast<const float4*>(Hm + (size_t)s0 * 128 + lane * 4);
        acc.x = fmaf(ex0, h0.x, acc.x); acc.y = fmaf(ex0, h0.y, acc.y);
        acc.z = fmaf(ex0, h0.z, acc.z); acc.w = fmaf(ex0, h0.w, acc.w);
        den += ex0;
    }
    float inv = 1.f / (den + 1e-16f);
    *reinterpret_cast<float4*>(outm + (size_t)n * 128 + lane * 4) =
        make_float4(acc.x * inv, acc.y * inv, acc.z * inv, acc.w * inv);
}

// ---------------- fused layer-2 aggregation + head-mean + log_softmax --------
__global__ void aggregate_csr_160_final(const int* __restrict__ rowp,
                                        const int* __restrict__ col,
                                        const float* __restrict__ als,
                                        const float* __restrict__ ald,
                                        const float* __restrict__ Hm,
                                        const float* __restrict__ b2,
                                        float* __restrict__ y, int N)
{
    __shared__ __align__(16) float sbuf[8][160];
    int wid  = threadIdx.x >> 5;
    int n    = (int)((blockIdx.x * (size_t)blockDim.x + threadIdx.x) >> 5);
    int lane = threadIdx.x & 31;
    if (n >= N) return;
    int head = lane / 10;
    bool two = (lane < 8);
    float ald_h = ald[(size_t)n * 4 + head];
    int beg = rowp[n], end = rowp[n + 1];

    float4 acc0 = make_float4(0.f, 0.f, 0.f, 0.f);
    float4 acc1 = make_float4(0.f, 0.f, 0.f, 0.f);
    float den = 0.f;

    for (int i = beg; i < end; ++i) {
        int s = col[i];
        float ex = __expf(lrelu(als[(size_t)s * 4 + head] + ald_h));
        float ex3 = __shfl_sync(0xffffffffu, ex, 31);
        const float* hrow = Hm + (size_t)s * 160;
        float4 h0 = *reinterpret_cast<const float4*>(hrow + lane * 4);
        acc0.x = fmaf(ex, h0.x, acc0.x); acc0.y = fmaf(ex, h0.y, acc0.y);
        acc0.z = fmaf(ex, h0.z, acc0.z); acc0.w = fmaf(ex, h0.w, acc0.w);
        if (two) {
            float4 h1 = *reinterpret_cast<const float4*>(hrow + 128 + lane * 4);
            acc1.x = fmaf(ex3, h1.x, acc1.x); acc1.y = fmaf(ex3, h1.y, acc1.y);
            acc1.z = fmaf(ex3, h1.z, acc1.z); acc1.w = fmaf(ex3, h1.w, acc1.w);
        }
        den += ex;
    }
    float den3 = __shfl_sync(0xffffffffu, den, 31);
    float inv  = 1.f / (den  + 1e-16f);
    float inv3 = 1.f / (den3 + 1e-16f);

    *reinterpret_cast<float4*>(&sbuf[wid][lane * 4]) =
        make_float4(acc0.x * inv, acc0.y * inv, acc0.z * inv, acc0.w * inv);
    if (two)
        *reinterpret_cast<float4*>(&sbuf[wid][128 + lane * 4]) =
            make_float4(acc1.x * inv3, acc1.y * inv3, acc1.z * inv3, acc1.w * inv3);
    __syncwarp();

    const float* S = sbuf[wid];
    int c0 = lane;
    int c1 = lane + 32;
    bool has1 = (c1 < 40);

    float v0 = 0.25f * (S[c0] + S[40 + c0] + S[80 + c0] + S[120 + c0]) + __ldg(&b2[c0]);
    float v1 = -1e30f;
    if (has1)
        v1 = 0.25f * (S[c1] + S[40 + c1] + S[80 + c1] + S[120 + c1]) + __ldg(&b2[c1]);

    float m = fmaxf(v0, v1);
#pragma unroll
    for (int o = 16; o; o >>= 1) m = fmaxf(m, __shfl_xor_sync(0xffffffffu, m, o));
    float se = __expf(v0 - m) + (has1 ? __expf(v1 - m) : 0.f);
#pragma unroll
    for (int o = 16; o; o >>= 1) se += __shfl_xor_sync(0xffffffffu, se, o);
    float lse = logf(se) + m;

    y[(size_t)n * 40 + c0] = v0 - lse;
    if (has1) y[(size_t)n * 40 + c1] = v1 - lse;
}

// ---------------- host side --------------------------------------------------
extern "C" void kernel_launch(void* const* d_in, const int* in_sizes, int n_in,
                              void* d_out, int out_size)
{
    const float* x   = (const float*)d_in[0];
    const int*   ei  = (const int*)  d_in[1];
    const float* W1  = (const float*)d_in[2];
    const float* as1 = (const float*)d_in[3];
    const float* ad1 = (const float*)d_in[4];
    const float* b1  = (const float*)d_in[5];
    const float* W2  = (const float*)d_in[6];
    const float* as2 = (const float*)d_in[7];
    const float* ad2 = (const float*)d_in[8];
    const float* b2  = (const float*)d_in[9];
    float* y = (float*)d_out;

    const int N = in_sizes[0] / F1;
    const int E = in_sizes[1] / 2;
    const int* src = ei;
    const int* dst = ei + E;

    void* p;
    cudaGetSymbolAddress(&p, g_h1);   float* h1   = (float*)p;
    cudaGetSymbolAddress(&p, g_out1); float* o1   = (float*)p;
    cudaGetSymbolAddress(&p, g_h2);   float* h2   = (float*)p;
    cudaGetSymbolAddress(&p, g_als1); float* als1 = (float*)p;
    cudaGetSymbolAddress(&p, g_ald1); float* ald1 = (float*)p;
    cudaGetSymbolAddress(&p, g_als2); float* als2 = (float*)p;
    cudaGetSymbolAddress(&p, g_ald2); float* ald2 = (float*)p;
    cudaGetSymbolAddress(&p, g_cnt);  int* cnt  = (int*)p;
    cudaGetSymbolAddress(&p, g_rowp); int* rowp = (int*)p;
    cudaGetSymbolAddress(&p, g_excl); int* excl = (int*)p;
    cudaGetSymbolAddress(&p, g_bsum); int* bsum = (int*)p;
    cudaGetSymbolAddress(&p, g_boff); int* boff = (int*)p;
    cudaGetSymbolAddress(&p, g_col);  int* col  = (int*)p;
    int* cnt2 = cnt + MAXN;

    const int smem1 = (128 * F1 + 64 * 128) * sizeof(float);
    const int smem2 = (128 * F2 + 64 * 128) * sizeof(float);
    cudaFuncSetAttribute(gemm_k128<F1, false>,
                         cudaFuncAttributeMaxDynamicSharedMemorySize, smem1);
    cudaFuncSetAttribute(gemm_k128<F2, true>,
                         cudaFuncAttributeMaxDynamicSharedMemorySize, smem2);

    const int TB = 256;
    const int NB = (N + SCAN_CHUNK - 1) / SCAN_CHUNK;
    const int gemmBlocks  = (N + 63) / 64;
    const int nodeWBlocks = (int)(((size_t)N * 32 + TB - 1) / TB);

    // CSR count + scans
    zero_int<<<(2 * MAXN + TB - 1) / TB, TB>>>(cnt, 2 * MAXN);
    count_deg<<<(E + TB - 1) / TB, TB>>>(dst, cnt, E);
    scan1<<<NB, SCAN_CHUNK>>>(cnt, excl, bsum, N);
    scan2<<<1, 256>>>(bsum, boff, NB);
    scan3<<<(N + 1 + TB - 1) / TB, TB>>>(excl, boff, rowp, N, E);

    // layer-1 GEMM (+ fused attention coefficients)
    gemm_k128<F1, false><<<gemmBlocks, TB, smem1>>>(
        x, W1, nullptr, as1, ad1, h1, als1, ald1, N);

    // CSR fill
    fill_csr<<<(E + TB - 1) / TB, TB>>>(src, dst, rowp, cnt2, col, E);

    // layer-1 aggregation
    aggregate_csr_128<<<nodeWBlocks, TB>>>(rowp, col, als1, ald1, h1, o1, N);

    // layer-2 GEMM (+ relu+bias on input, fused attention coefficients)
    gemm_k128<F2, true><<<gemmBlocks, TB, smem2>>>(
        o1, W2, b1, as2, ad2, h2, als2, ald2, N);

    // layer-2 aggregation + head mean + log_softmax
    aggregate_csr_160_final<<<nodeWBlocks, TB>>>(rowp, col, als2, ald2, h2, b2, y, N);
}

// round 6
// speedup vs baseline: 2.5715x; 1.1505x over previous
#include <cuda_runtime.h>
#include <cuda_fp16.h>
#include <math.h>
#include <stdint.h>

static constexpr int MAXN = 100000;
static constexpr int MAXE = 1600000;
static constexpr int F1   = 128;   // F_in and H*HID
static constexpr int F2   = 160;   // H*NCLS
static constexpr int NH   = 4;
static constexpr float NEG_SLOPE = 0.2f;
static constexpr int SCAN_CHUNK = 512;

typedef unsigned long long ull;

// ---------------- scratch ----------------------------------------------------
// h matrices stored as fp16 (gather-path), 8B-aligned via ull backing
__device__ ull   g_h1h [(size_t)MAXN * F1 / 4];   // 128 halves / row
__device__ ull   g_h2h [(size_t)MAXN * F2 / 4];   // 160 halves / row
__device__ float g_out1[(size_t)MAXN * F1];
__device__ float g_als1[(size_t)MAXN * NH];
__device__ float g_ald1[(size_t)MAXN * NH];
__device__ float g_als2[(size_t)MAXN * NH];
__device__ float g_ald2[(size_t)MAXN * NH];
__device__ int   g_cnt [2 * MAXN];
__device__ int   g_rowp[MAXN + 1];
__device__ int   g_excl[MAXN + SCAN_CHUNK];
__device__ int   g_bsum[256];
__device__ int   g_boff[256];
__device__ int   g_col [MAXE];

__device__ __forceinline__ float lrelu(float v) {
    return v > 0.f ? v : NEG_SLOPE * v;
}

// ---------------- packed f32x2 helpers (sm_103a FFMA2) -----------------------
__device__ __forceinline__ ull pack2(float a, float b) {
    ull r; asm("mov.b64 %0, {%1, %2};" : "=l"(r) : "f"(a), "f"(b)); return r;
}
__device__ __forceinline__ void unpack2(ull v, float& a, float& b) {
    asm("mov.b64 {%0, %1}, %2;" : "=f"(a), "=f"(b) : "l"(v));
}
__device__ __forceinline__ void fma2(ull& d, ull a, ull b) {
    asm("fma.rn.f32x2 %0, %1, %2, %0;" : "+l"(d) : "l"(a), "l"(b));
}

// ---------------- CSR build --------------------------------------------------
__global__ void scan1(const int* __restrict__ cnt, int* __restrict__ excl,
                      int* __restrict__ bsum, int N) {
    __shared__ int sm[SCAN_CHUNK];
    int t = threadIdx.x;
    int i = blockIdx.x * SCAN_CHUNK + t;
    int v = (i < N) ? cnt[i] : 0;
    sm[t] = v;
    __syncthreads();
    for (int o = 1; o < SCAN_CHUNK; o <<= 1) {
        int add = (t >= o) ? sm[t - o] : 0;
        __syncthreads();
        sm[t] += add;
        __syncthreads();
    }
    excl[i] = sm[t] - v;
    if (t == SCAN_CHUNK - 1) bsum[blockIdx.x] = sm[t];
}

__global__ void scan2(const int* __restrict__ bsum, int* __restrict__ boff, int NB) {
    __shared__ int sm[256];
    int t = threadIdx.x;
    int v = (t < NB) ? bsum[t] : 0;
    sm[t] = v;
    __syncthreads();
    for (int o = 1; o < 256; o <<= 1) {
        int add = (t >= o) ? sm[t - o] : 0;
        __syncthreads();
        sm[t] += add;
        __syncthreads();
    }
    boff[t] = sm[t] - v;
}

__global__ void scan3(const int* __restrict__ excl, const int* __restrict__ boff,
                      int* __restrict__ rowp, int N, int E) {
    int i = blockIdx.x * blockDim.x + threadIdx.x;
    if (i < N) rowp[i] = excl[i] + boff[i / SCAN_CHUNK];
    if (i == N) rowp[N] = E;
}

__global__ void fill_csr(const int* __restrict__ src, const int* __restrict__ dst,
                         const int* __restrict__ rowp, int* __restrict__ cnt2,
                         int* __restrict__ col, int E) {
    int e = blockIdx.x * blockDim.x + threadIdx.x;
    if (e >= E) return;
    int d = dst[e];
    int k = atomicAdd(&cnt2[d], 1);
    col[rowp[d] + k] = src[e];
}

// ---------------- GEMM (f32x2) + fused attention epilogue + fp16 h store -----
// out_h[N,NOUT] (fp16) = act(A[N,128] (+bias)) @ W[128,NOUT]
// Lane owns column pairs col = 2*lane + 64*q, plus scalar col 128+lane (NOUT=160).
// DO_COUNT: fused degree counting (fire-and-forget REDs, hidden under compute).
template<int NOUT, bool RELU_BIAS, bool DO_COUNT>
__global__ void __launch_bounds__(256, 2)
gemm_k128(const float* __restrict__ A,
          const float* __restrict__ W,
          const float* __restrict__ bias,
          const float* __restrict__ a_s,
          const float* __restrict__ a_d,
          __half* __restrict__ outh,
          float* __restrict__ als,
          float* __restrict__ ald, int N,
          const int* __restrict__ dstE, int* __restrict__ cnt, int E)
{
    extern __shared__ float smem[];
    float* sW = smem;               // 128*NOUT
    float* sA = smem + 128 * NOUT;  // 64*128
    const int tid  = threadIdx.x;
    const int warp = tid >> 5;
    const int lane = tid & 31;
    const int row0 = blockIdx.x * 64;

    if (DO_COUNT) {
        int stride = gridDim.x * 256;
        for (int e = blockIdx.x * 256 + tid; e < E; e += stride)
            atomicAdd(&cnt[dstE[e]], 1);   // RED, no return wait
    }

    for (int i = tid * 4; i < 128 * NOUT; i += 256 * 4)
        *reinterpret_cast<float4*>(sW + i) = *reinterpret_cast<const float4*>(W + i);
    for (int i = tid; i < 64 * 128 / 4; i += 256) {
        int idx = i * 4;
        int r   = idx >> 7;
        int k   = idx & 127;
        int gr  = row0 + r;
        float4 v = make_float4(0.f, 0.f, 0.f, 0.f);
        if (gr < N) {
            v = *reinterpret_cast<const float4*>(A + (size_t)gr * 128 + k);
            if (RELU_BIAS) {
                v.x = fmaxf(v.x + bias[k + 0], 0.f);
                v.y = fmaxf(v.y + bias[k + 1], 0.f);
                v.z = fmaxf(v.z + bias[k + 2], 0.f);
                v.w = fmaxf(v.w + bias[k + 3], 0.f);
            }
        }
        *reinterpret_cast<float4*>(sA + idx) = v;
    }
    __syncthreads();

    constexpr int P = NOUT / 64;
    constexpr bool HAS_S = (NOUT == 160);
    ull acc2[8][P];
    float accS[8];
#pragma unroll
    for (int i = 0; i < 8; ++i) {
#pragma unroll
        for (int p = 0; p < P; ++p) acc2[i][p] = 0ull;
        accS[i] = 0.f;
    }

    const float* sArow = sA + (warp * 8) * 128;
    const int c2 = 2 * lane;

    for (int k0 = 0; k0 < 128; k0 += 4) {
        float4 av[8];
#pragma unroll
        for (int i = 0; i < 8; ++i)
            av[i] = *reinterpret_cast<const float4*>(sArow + i * 128 + k0);
#pragma unroll
        for (int kk = 0; kk < 4; ++kk) {
            const float* wk = sW + (k0 + kk) * NOUT;
            ull w[P];
#pragma unroll
            for (int p = 0; p < P; ++p)
                w[p] = *reinterpret_cast<const ull*>(wk + c2 + 64 * p);
            float ws = HAS_S ? wk[128 + lane] : 0.f;
#pragma unroll
            for (int i = 0; i < 8; ++i) {
                float a = (kk == 0) ? av[i].x : (kk == 1) ? av[i].y
                        : (kk == 2) ? av[i].z : av[i].w;
                ull ap = pack2(a, a);
#pragma unroll
                for (int p = 0; p < P; ++p) fma2(acc2[i][p], ap, w[p]);
                if (HAS_S) accS[i] = fmaf(a, ws, accS[i]);
            }
        }
    }

    float2 asp[P], adp[P];
#pragma unroll
    for (int p = 0; p < P; ++p) {
        asp[p] = *reinterpret_cast<const float2*>(a_s + c2 + 64 * p);
        adp[p] = *reinterpret_cast<const float2*>(a_d + c2 + 64 * p);
    }
    float asS = HAS_S ? a_s[128 + lane] : 0.f;
    float adS = HAS_S ? a_d[128 + lane] : 0.f;

#pragma unroll
    for (int i = 0; i < 8; ++i) {
        int r = row0 + warp * 8 + i;
        if (r >= N) continue;

        float a0, a1, b0, b1;
        unpack2(acc2[i][0], a0, a1);
        unpack2(acc2[i][1], b0, b1);

        // fp16 stores (coalesced 4B per pair)
        *reinterpret_cast<__half2*>(outh + (size_t)r * NOUT + c2) =
            __floats2half2_rn(a0, a1);
        *reinterpret_cast<__half2*>(outh + (size_t)r * NOUT + 64 + c2) =
            __floats2half2_rn(b0, b1);
        if (HAS_S) outh[(size_t)r * NOUT + 128 + lane] = __float2half_rn(accS[i]);

        if (NOUT == 128) {
            float vsA = a0 * asp[0].x + a1 * asp[0].y;
            float vdA = a0 * adp[0].x + a1 * adp[0].y;
            float vsB = b0 * asp[1].x + b1 * asp[1].y;
            float vdB = b0 * adp[1].x + b1 * adp[1].y;
#pragma unroll
            for (int o = 8; o; o >>= 1) {
                vsA += __shfl_xor_sync(0xffffffffu, vsA, o);
                vdA += __shfl_xor_sync(0xffffffffu, vdA, o);
                vsB += __shfl_xor_sync(0xffffffffu, vsB, o);
                vdB += __shfl_xor_sync(0xffffffffu, vdB, o);
            }
            if (lane == 0) {
                als[(size_t)r * 4 + 0] = vsA;
                ald[(size_t)r * 4 + 0] = vdA;
                als[(size_t)r * 4 + 2] = vsB;
                ald[(size_t)r * 4 + 2] = vdB;
            } else if (lane == 16) {
                als[(size_t)r * 4 + 1] = vsA;
                ald[(size_t)r * 4 + 1] = vdA;
                als[(size_t)r * 4 + 3] = vsB;
                ald[(size_t)r * 4 + 3] = vdB;
            }
        } else {
            float s0 = 0.f, s1 = 0.f, s2 = 0.f, s3 = 0.f;
            float d0 = 0.f, d1 = 0.f, d2 = 0.f, d3 = 0.f;
            float vA_s = a0 * asp[0].x + a1 * asp[0].y;
            float vA_d = a0 * adp[0].x + a1 * adp[0].y;
            if (lane < 20) { s0 += vA_s; d0 += vA_d; } else { s1 += vA_s; d1 += vA_d; }
            float vB_s = b0 * asp[1].x + b1 * asp[1].y;
            float vB_d = b0 * adp[1].x + b1 * adp[1].y;
            if (lane < 8)       { s1 += vB_s; d1 += vB_d; }
            else if (lane < 28) { s2 += vB_s; d2 += vB_d; }
            else                { s3 += vB_s; d3 += vB_d; }
            s3 += accS[i] * asS;
            d3 += accS[i] * adS;
#pragma unroll
            for (int o = 16; o; o >>= 1) {
                s0 += __shfl_xor_sync(0xffffffffu, s0, o);
                d0 += __shfl_xor_sync(0xffffffffu, d0, o);
                s1 += __shfl_xor_sync(0xffffffffu, s1, o);
                d1 += __shfl_xor_sync(0xffffffffu, d1, o);
                s2 += __shfl_xor_sync(0xffffffffu, s2, o);
                d2 += __shfl_xor_sync(0xffffffffu, d2, o);
                s3 += __shfl_xor_sync(0xffffffffu, s3, o);
                d3 += __shfl_xor_sync(0xffffffffu, d3, o);
            }
            if (lane == 0) {
                als[(size_t)r * 4 + 0] = s0; ald[(size_t)r * 4 + 0] = d0;
                als[(size_t)r * 4 + 1] = s1; ald[(size_t)r * 4 + 1] = d1;
                als[(size_t)r * 4 + 2] = s2; ald[(size_t)r * 4 + 2] = d2;
                als[(size_t)r * 4 + 3] = s3; ald[(size_t)r * 4 + 3] = d3;
            }
        }
    }
}

// ---------------- fused CSR aggregation, layer 1 (warp per dst node) ---------
// h rows gathered as fp16 (256B/row); 4-wide pipelined for MLP.
__device__ __forceinline__ void acc_h16(float4& acc, uint2 u, float e) {
    float2 f0 = __half22float2(*reinterpret_cast<__half2*>(&u.x));
    float2 f1 = __half22float2(*reinterpret_cast<__half2*>(&u.y));
    acc.x = fmaf(e, f0.x, acc.x); acc.y = fmaf(e, f0.y, acc.y);
    acc.z = fmaf(e, f1.x, acc.z); acc.w = fmaf(e, f1.y, acc.w);
}

__global__ void aggregate_csr_128(const int* __restrict__ rowp,
                                  const int* __restrict__ col,
                                  const float* __restrict__ als,
                                  const float* __restrict__ ald,
                                  const __half* __restrict__ Hh,
                                  float* __restrict__ outm, int N)
{
    int n    = (int)((blockIdx.x * (size_t)blockDim.x + threadIdx.x) >> 5);
    int lane = threadIdx.x & 31;
    if (n >= N) return;
    int head = lane >> 3;
    float ald_h = ald[(size_t)n * 4 + head];
    int beg = rowp[n], end = rowp[n + 1];

    float4 acc = make_float4(0.f, 0.f, 0.f, 0.f);
    float den = 0.f;

    int i = beg;
    for (; i + 4 <= end; i += 4) {
        int s0 = __ldg(col + i), s1 = __ldg(col + i + 1);
        int s2 = __ldg(col + i + 2), s3 = __ldg(col + i + 3);
        float al0 = __ldg(als + (size_t)s0 * 4 + head);
        float al1 = __ldg(als + (size_t)s1 * 4 + head);
        float al2 = __ldg(als + (size_t)s2 * 4 + head);
        float al3 = __ldg(als + (size_t)s3 * 4 + head);
        uint2 u0 = *reinterpret_cast<const uint2*>(Hh + (size_t)s0 * 128 + lane * 4);
        uint2 u1 = *reinterpret_cast<const uint2*>(Hh + (size_t)s1 * 128 + lane * 4);
        uint2 u2 = *reinterpret_cast<const uint2*>(Hh + (size_t)s2 * 128 + lane * 4);
        uint2 u3 = *reinterpret_cast<const uint2*>(Hh + (size_t)s3 * 128 + lane * 4);
        float e0 = __expf(lrelu(al0 + ald_h));
        float e1 = __expf(lrelu(al1 + ald_h));
        float e2 = __expf(lrelu(al2 + ald_h));
        float e3 = __expf(lrelu(al3 + ald_h));
        acc_h16(acc, u0, e0);
        acc_h16(acc, u1, e1);
        acc_h16(acc, u2, e2);
        acc_h16(acc, u3, e3);
        den += (e0 + e1) + (e2 + e3);
    }
    for (; i < end; ++i) {
        int s0 = __ldg(col + i);
        float e0 = __expf(lrelu(__ldg(als + (size_t)s0 * 4 + head) + ald_h));
        uint2 u0 = *reinterpret_cast<const uint2*>(Hh + (size_t)s0 * 128 + lane * 4);
        acc_h16(acc, u0, e0);
        den += e0;
    }
    float inv = 1.f / (den + 1e-16f);
    *reinterpret_cast<float4*>(outm + (size_t)n * 128 + lane * 4) =
        make_float4(acc.x * inv, acc.y * inv, acc.z * inv, acc.w * inv);
}

// ---------------- fused layer-2 aggregation + head-mean + log_softmax --------
__global__ void aggregate_csr_160_final(const int* __restrict__ rowp,
                                        const int* __restrict__ col,
                                        const float* __restrict__ als,
                                        const float* __restrict__ ald,
                                        const __half* __restrict__ Hh,
                                        const float* __restrict__ b2,
                                        float* __restrict__ y, int N)
{
    __shared__ __align__(16) float sbuf[8][160];
    int wid  = threadIdx.x >> 5;
    int n    = (int)((blockIdx.x * (size_t)blockDim.x + threadIdx.x) >> 5);
    int lane = threadIdx.x & 31;
    if (n >= N) return;
    int head = lane / 10;
    bool two = (lane < 8);
    float ald_h = ald[(size_t)n * 4 + head];
    int beg = rowp[n], end = rowp[n + 1];

    float4 acc0 = make_float4(0.f, 0.f, 0.f, 0.f);
    float4 acc1 = make_float4(0.f, 0.f, 0.f, 0.f);
    float den = 0.f;

    int i = beg;
    for (; i + 2 <= end; i += 2) {
        int s0 = __ldg(col + i), s1 = __ldg(col + i + 1);
        float al0 = __ldg(als + (size_t)s0 * 4 + head);
        float al1 = __ldg(als + (size_t)s1 * 4 + head);
        uint2 u0 = *reinterpret_cast<const uint2*>(Hh + (size_t)s0 * 160 + lane * 4);
        uint2 u1 = *reinterpret_cast<const uint2*>(Hh + (size_t)s1 * 160 + lane * 4);
        float e0 = __expf(lrelu(al0 + ald_h));
        float e1 = __expf(lrelu(al1 + ald_h));
        float e0_3 = __shfl_sync(0xffffffffu, e0, 31);
        float e1_3 = __shfl_sync(0xffffffffu, e1, 31);
        acc_h16(acc0, u0, e0);
        acc_h16(acc0, u1, e1);
        if (two) {
            uint2 v0 = *reinterpret_cast<const uint2*>(Hh + (size_t)s0 * 160 + 128 + lane * 4);
            uint2 v1 = *reinterpret_cast<const uint2*>(Hh + (size_t)s1 * 160 + 128 + lane * 4);
            acc_h16(acc1, v0, e0_3);
            acc_h16(acc1, v1, e1_3);
        }
        den += e0 + e1;
    }
    for (; i < end; ++i) {
        int s0 = __ldg(col + i);
        float e0 = __expf(lrelu(__ldg(als + (size_t)s0 * 4 + head) + ald_h));
        float e0_3 = __shfl_sync(0xffffffffu, e0, 31);
        uint2 u0 = *reinterpret_cast<const uint2*>(Hh + (size_t)s0 * 160 + lane * 4);
        acc_h16(acc0, u0, e0);
        if (two) {
            uint2 v0 = *reinterpret_cast<const uint2*>(Hh + (size_t)s0 * 160 + 128 + lane * 4);
            acc_h16(acc1, v0, e0_3);
        }
        den += e0;
    }
    float den3 = __shfl_sync(0xffffffffu, den, 31);
    float inv  = 1.f / (den  + 1e-16f);
    float inv3 = 1.f / (den3 + 1e-16f);

    *reinterpret_cast<float4*>(&sbuf[wid][lane * 4]) =
        make_float4(acc0.x * inv, acc0.y * inv, acc0.z * inv, acc0.w * inv);
    if (two)
        *reinterpret_cast<float4*>(&sbuf[wid][128 + lane * 4]) =
            make_float4(acc1.x * inv3, acc1.y * inv3, acc1.z * inv3, acc1.w * inv3);
    __syncwarp();

    const float* S = sbuf[wid];
    int c0 = lane;
    int c1 = lane + 32;
    bool has1 = (c1 < 40);

    float v0 = 0.25f * (S[c0] + S[40 + c0] + S[80 + c0] + S[120 + c0]) + __ldg(&b2[c0]);
    float v1 = -1e30f;
    if (has1)
        v1 = 0.25f * (S[c1] + S[40 + c1] + S[80 + c1] + S[120 + c1]) + __ldg(&b2[c1]);

    float m = fmaxf(v0, v1);
#pragma unroll
    for (int o = 16; o; o >>= 1) m = fmaxf(m, __shfl_xor_sync(0xffffffffu, m, o));
    float se = __expf(v0 - m) + (has1 ? __expf(v1 - m) : 0.f);
#pragma unroll
    for (int o = 16; o; o >>= 1) se += __shfl_xor_sync(0xffffffffu, se, o);
    float lse = logf(se) + m;

    y[(size_t)n * 40 + c0] = v0 - lse;
    if (has1) y[(size_t)n * 40 + c1] = v1 - lse;
}

// ---------------- host side --------------------------------------------------
extern "C" void kernel_launch(void* const* d_in, const int* in_sizes, int n_in,
                              void* d_out, int out_size)
{
    const float* x   = (const float*)d_in[0];
    const int*   ei  = (const int*)  d_in[1];
    const float* W1  = (const float*)d_in[2];
    const float* as1 = (const float*)d_in[3];
    const float* ad1 = (const float*)d_in[4];
    const float* b1  = (const float*)d_in[5];
    const float* W2  = (const float*)d_in[6];
    const float* as2 = (const float*)d_in[7];
    const float* ad2 = (const float*)d_in[8];
    const float* b2  = (const float*)d_in[9];
    float* y = (float*)d_out;

    const int N = in_sizes[0] / F1;
    const int E = in_sizes[1] / 2;
    const int* src = ei;
    const int* dst = ei + E;

    void* p;
    cudaGetSymbolAddress(&p, g_h1h);  __half* h1h = (__half*)p;
    cudaGetSymbolAddress(&p, g_h2h);  __half* h2h = (__half*)p;
    cudaGetSymbolAddress(&p, g_out1); float* o1   = (float*)p;
    cudaGetSymbolAddress(&p, g_als1); float* als1 = (float*)p;
    cudaGetSymbolAddress(&p, g_ald1); float* ald1 = (float*)p;
    cudaGetSymbolAddress(&p, g_als2); float* als2 = (float*)p;
    cudaGetSymbolAddress(&p, g_ald2); float* ald2 = (float*)p;
    cudaGetSymbolAddress(&p, g_cnt);  int* cnt  = (int*)p;
    cudaGetSymbolAddress(&p, g_rowp); int* rowp = (int*)p;
    cudaGetSymbolAddress(&p, g_excl); int* excl = (int*)p;
    cudaGetSymbolAddress(&p, g_bsum); int* bsum = (int*)p;
    cudaGetSymbolAddress(&p, g_boff); int* boff = (int*)p;
    cudaGetSymbolAddress(&p, g_col);  int* col  = (int*)p;
    int* cnt2 = cnt + MAXN;

    const int smem1 = (128 * F1 + 64 * 128) * sizeof(float);
    const int smem2 = (128 * F2 + 64 * 128) * sizeof(float);
    cudaFuncSetAttribute(gemm_k128<F1, false, true>,
                         cudaFuncAttributeMaxDynamicSharedMemorySize, smem1);
    cudaFuncSetAttribute(gemm_k128<F2, true, false>,
                         cudaFuncAttributeMaxDynamicSharedMemorySize, smem2);

    const int TB = 256;
    const int NB = (N + SCAN_CHUNK - 1) / SCAN_CHUNK;
    const int gemmBlocks  = (N + 63) / 64;
    const int nodeWBlocks = (int)(((size_t)N * 32 + TB - 1) / TB);

    // memset (not a kernel launch): zero both counter arrays
    cudaMemsetAsync(cnt, 0, 2 * (size_t)MAXN * sizeof(int));

    // k0: layer-1 GEMM + fused attention coefficients + fused degree count
    gemm_k128<F1, false, true><<<gemmBlocks, TB, smem1>>>(
        x, W1, nullptr, as1, ad1, h1h, als1, ald1, N, dst, cnt, E);

    // k1-k3: scans
    scan1<<<NB, SCAN_CHUNK>>>(cnt, excl, bsum, N);
    scan2<<<1, 256>>>(bsum, boff, NB);
    scan3<<<(N + 1 + TB - 1) / TB, TB>>>(excl, boff, rowp, N, E);

    // k4: CSR fill
    fill_csr<<<(E + TB - 1) / TB, TB>>>(src, dst, rowp, cnt2, col, E);

    // k5: layer-1 aggregation (ncu -s 5 profiles this)
    aggregate_csr_128<<<nodeWBlocks, TB>>>(rowp, col, als1, ald1, h1h, o1, N);

    // k6: layer-2 GEMM
    gemm_k128<F2, true, false><<<gemmBlocks, TB, smem2>>>(
        o1, W2, b1, as2, ad2, h2h, als2, ald2, N, nullptr, nullptr, 0);

    // k7: layer-2 aggregation + head mean + log_softmax
    aggregate_csr_160_final<<<nodeWBlocks, TB>>>(rowp, col, als2, ald2, h2h, b2, y, N);
}

// round 7
// speedup vs baseline: 2.5991x; 1.0107x over previous
#include <cuda_runtime.h>
#include <cuda_fp16.h>
#include <math.h>
#include <stdint.h>

static constexpr int MAXN = 100000;
static constexpr int MAXE = 1600000;
static constexpr int F1   = 128;   // F_in and H*HID
static constexpr int F2   = 160;   // H*NCLS
static constexpr int NH   = 4;
static constexpr float NEG_SLOPE = 0.2f;

typedef unsigned long long ull;

// ---------------- scratch ----------------------------------------------------
__device__ ull   g_h1h [(size_t)MAXN * F1 / 4];   // fp16 h1, 128 halves/row
__device__ ull   g_h2h [(size_t)MAXN * F2 / 4];   // fp16 h2, 160 halves/row
__device__ float g_out1[(size_t)MAXN * F1];
__device__ float g_als1[(size_t)MAXN * NH];
__device__ float g_ald1[(size_t)MAXN * NH];
__device__ float g_als2[(size_t)MAXN * NH];
__device__ float g_ald2[(size_t)MAXN * NH];
__device__ int   g_cnt [2 * MAXN];
__device__ int   g_rowp[MAXN + 1];
__device__ int   g_col [MAXE];
__device__ ull   g_state[256];       // decoupled-lookback state
__device__ int   g_ticket;

__device__ __forceinline__ float lrelu(float v) {
    return v > 0.f ? v : NEG_SLOPE * v;
}

// ---------------- packed f32x2 helpers (sm_103a FFMA2) -----------------------
__device__ __forceinline__ ull pack2(float a, float b) {
    ull r; asm("mov.b64 %0, {%1, %2};" : "=l"(r) : "f"(a), "f"(b)); return r;
}
__device__ __forceinline__ void unpack2(ull v, float& a, float& b) {
    asm("mov.b64 {%0, %1}, %2;" : "=f"(a), "=f"(b) : "l"(v));
}
__device__ __forceinline__ void fma2(ull& d, ull a, ull b) {
    asm("fma.rn.f32x2 %0, %1, %2, %0;" : "+l"(d) : "l"(a), "l"(b));
}

// ---------------- single-pass scan (decoupled lookback) ----------------------
static constexpr ull FLG_AGG = 1ull << 62;
static constexpr ull FLG_PRE = 2ull << 62;

__global__ void scan_one(const int* __restrict__ cnt, int* __restrict__ rowp,
                         ull* __restrict__ state, int* __restrict__ ticket,
                         int N, int E)
{
    __shared__ int sm[512];
    __shared__ int sbid, sprefix;
    int t = threadIdx.x;
    if (t == 0) sbid = atomicAdd(ticket, 1);
    __syncthreads();
    int b = sbid;
    int i = b * 512 + t;
    int v = (i < N) ? cnt[i] : 0;
    sm[t] = v;
    __syncthreads();
    for (int o = 1; o < 512; o <<= 1) {
        int add = (t >= o) ? sm[t - o] : 0;
        __syncthreads();
        sm[t] += add;
        __syncthreads();
    }
    int incl  = sm[t];
    int total = sm[511];
    if (t == 0) {
        if (b == 0) {
            atomicExch(&state[0], FLG_PRE | (unsigned)total);
            sprefix = 0;
        } else {
            atomicExch(&state[b], FLG_AGG | (unsigned)total);
            int run = 0, j = b - 1;
            while (true) {
                ull s;
                do { s = atomicAdd(&state[j], 0ull); } while ((s >> 62) == 0);
                run += (int)(s & 0xffffffffu);
                if (s & FLG_PRE) break;
                --j;
            }
            atomicExch(&state[b], FLG_PRE | (unsigned)(run + total));
            sprefix = run;
        }
    }
    __syncthreads();
    if (i < N) rowp[i] = sprefix + incl - v;
    if (b == 0 && t == 0) rowp[N] = E;
}

__global__ void fill_csr(const int* __restrict__ src, const int* __restrict__ dst,
                         const int* __restrict__ rowp, int* __restrict__ cnt2,
                         int* __restrict__ col, int E) {
    int e = blockIdx.x * blockDim.x + threadIdx.x;
    if (e >= E) return;
    int d = dst[e];
    int k = atomicAdd(&cnt2[d], 1);
    col[rowp[d] + k] = src[e];
}

// ---------------- GEMM (f32x2) + fused attention epilogue + fp16 h store -----
template<int NOUT, bool RELU_BIAS, bool DO_COUNT>
__global__ void __launch_bounds__(256, 2)
gemm_k128(const float* __restrict__ A,
          const float* __restrict__ W,
          const float* __restrict__ bias,
          const float* __restrict__ a_s,
          const float* __restrict__ a_d,
          __half* __restrict__ outh,
          float* __restrict__ als,
          float* __restrict__ ald, int N,
          const int* __restrict__ dstE, int* __restrict__ cnt, int E)
{
    extern __shared__ float smem[];
    float* sW = smem;               // 128*NOUT
    float* sA = smem + 128 * NOUT;  // 64*128
    const int tid  = threadIdx.x;
    const int warp = tid >> 5;
    const int lane = tid & 31;
    const int row0 = blockIdx.x * 64;

    if (DO_COUNT) {
        int stride = gridDim.x * 256;
        for (int e = blockIdx.x * 256 + tid; e < E; e += stride)
            atomicAdd(&cnt[dstE[e]], 1);
    }

    for (int i = tid * 4; i < 128 * NOUT; i += 256 * 4)
        *reinterpret_cast<float4*>(sW + i) = *reinterpret_cast<const float4*>(W + i);
    for (int i = tid; i < 64 * 128 / 4; i += 256) {
        int idx = i * 4;
        int r   = idx >> 7;
        int k   = idx & 127;
        int gr  = row0 + r;
        float4 v = make_float4(0.f, 0.f, 0.f, 0.f);
        if (gr < N) {
            v = *reinterpret_cast<const float4*>(A + (size_t)gr * 128 + k);
            if (RELU_BIAS) {
                v.x = fmaxf(v.x + bias[k + 0], 0.f);
                v.y = fmaxf(v.y + bias[k + 1], 0.f);
                v.z = fmaxf(v.z + bias[k + 2], 0.f);
                v.w = fmaxf(v.w + bias[k + 3], 0.f);
            }
        }
        *reinterpret_cast<float4*>(sA + idx) = v;
    }
    __syncthreads();

    constexpr int P = NOUT / 64;
    constexpr bool HAS_S = (NOUT == 160);
    ull acc2[8][P];
    float accS[8];
#pragma unroll
    for (int i = 0; i < 8; ++i) {
#pragma unroll
        for (int p = 0; p < P; ++p) acc2[i][p] = 0ull;
        accS[i] = 0.f;
    }

    const float* sArow = sA + (warp * 8) * 128;
    const int c2 = 2 * lane;

    for (int k0 = 0; k0 < 128; k0 += 4) {
        float4 av[8];
#pragma unroll
        for (int i = 0; i < 8; ++i)
            av[i] = *reinterpret_cast<const float4*>(sArow + i * 128 + k0);
#pragma unroll
        for (int kk = 0; kk < 4; ++kk) {
            const float* wk = sW + (k0 + kk) * NOUT;
            ull w[P];
#pragma unroll
            for (int p = 0; p < P; ++p)
                w[p] = *reinterpret_cast<const ull*>(wk + c2 + 64 * p);
            float ws = HAS_S ? wk[128 + lane] : 0.f;
#pragma unroll
            for (int i = 0; i < 8; ++i) {
                float a = (kk == 0) ? av[i].x : (kk == 1) ? av[i].y
                        : (kk == 2) ? av[i].z : av[i].w;
                ull ap = pack2(a, a);
#pragma unroll
                for (int p = 0; p < P; ++p) fma2(acc2[i][p], ap, w[p]);
                if (HAS_S) accS[i] = fmaf(a, ws, accS[i]);
            }
        }
    }

    float2 asp[P], adp[P];
#pragma unroll
    for (int p = 0; p < P; ++p) {
        asp[p] = *reinterpret_cast<const float2*>(a_s + c2 + 64 * p);
        adp[p] = *reinterpret_cast<const float2*>(a_d + c2 + 64 * p);
    }
    float asS = HAS_S ? a_s[128 + lane] : 0.f;
    float adS = HAS_S ? a_d[128 + lane] : 0.f;

#pragma unroll
    for (int i = 0; i < 8; ++i) {
        int r = row0 + warp * 8 + i;
        if (r >= N) continue;

        float a0, a1, b0, b1;
        unpack2(acc2[i][0], a0, a1);
        unpack2(acc2[i][1], b0, b1);

        *reinterpret_cast<__half2*>(outh + (size_t)r * NOUT + c2) =
            __floats2half2_rn(a0, a1);
        *reinterpret_cast<__half2*>(outh + (size_t)r * NOUT + 64 + c2) =
            __floats2half2_rn(b0, b1);
        if (HAS_S) outh[(size_t)r * NOUT + 128 + lane] = __float2half_rn(accS[i]);

        if (NOUT == 128) {
            float vsA = a0 * asp[0].x + a1 * asp[0].y;
            float vdA = a0 * adp[0].x + a1 * adp[0].y;
            float vsB = b0 * asp[1].x + b1 * asp[1].y;
            float vdB = b0 * adp[1].x + b1 * adp[1].y;
#pragma unroll
            for (int o = 8; o; o >>= 1) {
                vsA += __shfl_xor_sync(0xffffffffu, vsA, o);
                vdA += __shfl_xor_sync(0xffffffffu, vdA, o);
                vsB += __shfl_xor_sync(0xffffffffu, vsB, o);
                vdB += __shfl_xor_sync(0xffffffffu, vdB, o);
            }
            if (lane == 0) {
                als[(size_t)r * 4 + 0] = vsA;
                ald[(size_t)r * 4 + 0] = vdA;
                als[(size_t)r * 4 + 2] = vsB;
                ald[(size_t)r * 4 + 2] = vdB;
            } else if (lane == 16) {
                als[(size_t)r * 4 + 1] = vsA;
                ald[(size_t)r * 4 + 1] = vdA;
                als[(size_t)r * 4 + 3] = vsB;
                ald[(size_t)r * 4 + 3] = vdB;
            }
        } else {
            float s0 = 0.f, s1 = 0.f, s2 = 0.f, s3 = 0.f;
            float d0 = 0.f, d1 = 0.f, d2 = 0.f, d3 = 0.f;
            float vA_s = a0 * asp[0].x + a1 * asp[0].y;
            float vA_d = a0 * adp[0].x + a1 * adp[0].y;
            if (lane < 20) { s0 += vA_s; d0 += vA_d; } else { s1 += vA_s; d1 += vA_d; }
            float vB_s = b0 * asp[1].x + b1 * asp[1].y;
            float vB_d = b0 * adp[1].x + b1 * adp[1].y;
            if (lane < 8)       { s1 += vB_s; d1 += vB_d; }
            else if (lane < 28) { s2 += vB_s; d2 += vB_d; }
            else                { s3 += vB_s; d3 += vB_d; }
            s3 += accS[i] * asS;
            d3 += accS[i] * adS;
#pragma unroll
            for (int o = 16; o; o >>= 1) {
                s0 += __shfl_xor_sync(0xffffffffu, s0, o);
                d0 += __shfl_xor_sync(0xffffffffu, d0, o);
                s1 += __shfl_xor_sync(0xffffffffu, s1, o);
                d1 += __shfl_xor_sync(0xffffffffu, d1, o);
                s2 += __shfl_xor_sync(0xffffffffu, s2, o);
                d2 += __shfl_xor_sync(0xffffffffu, d2, o);
                s3 += __shfl_xor_sync(0xffffffffu, s3, o);
                d3 += __shfl_xor_sync(0xffffffffu, d3, o);
            }
            if (lane == 0) {
                als[(size_t)r * 4 + 0] = s0; ald[(size_t)r * 4 + 0] = d0;
                als[(size_t)r * 4 + 1] = s1; ald[(size_t)r * 4 + 1] = d1;
                als[(size_t)r * 4 + 2] = s2; ald[(size_t)r * 4 + 2] = d2;
                als[(size_t)r * 4 + 3] = s3; ald[(size_t)r * 4 + 3] = d3;
            }
        }
    }
}

// ---------------- layer-1 aggregation: 2 nodes per warp ----------------------
// Half-warp (16 lanes) owns one node; lane loads uint4 = 8 halves (16B);
// 16 lanes cover the full 256B fp16 row. head = hl>>2 (4 lanes per head).
__device__ __forceinline__ void acc_h16x8(float4& p, float4& q, uint4 u, float e) {
    float2 f0 = __half22float2(*reinterpret_cast<__half2*>(&u.x));
    float2 f1 = __half22float2(*reinterpret_cast<__half2*>(&u.y));
    float2 f2 = __half22float2(*reinterpret_cast<__half2*>(&u.z));
    float2 f3 = __half22float2(*reinterpret_cast<__half2*>(&u.w));
    p.x = fmaf(e, f0.x, p.x); p.y = fmaf(e, f0.y, p.y);
    p.z = fmaf(e, f1.x, p.z); p.w = fmaf(e, f1.y, p.w);
    q.x = fmaf(e, f2.x, q.x); q.y = fmaf(e, f2.y, q.y);
    q.z = fmaf(e, f3.x, q.z); q.w = fmaf(e, f3.y, q.w);
}

__global__ void aggregate_csr_128(const int* __restrict__ rowp,
                                  const int* __restrict__ col,
                                  const float* __restrict__ als,
                                  const float* __restrict__ ald,
                                  const __half* __restrict__ Hh,
                                  float* __restrict__ outm, int N)
{
    int w    = (int)((blockIdx.x * (size_t)blockDim.x + threadIdx.x) >> 5);
    int lane = threadIdx.x & 31;
    int hw   = lane >> 4;          // which node in the warp
    int hl   = lane & 15;          // lane within half-warp
    int n = w * 2 + hw;
    if (n >= N) return;
    int head = hl >> 2;
    float ald_h = __ldg(ald + (size_t)n * 4 + head);
    int beg = __ldg(rowp + n), end = __ldg(rowp + n + 1);

    float4 accP = make_float4(0.f, 0.f, 0.f, 0.f);
    float4 accQ = make_float4(0.f, 0.f, 0.f, 0.f);
    float den = 0.f;

    int i = beg;
    for (; i + 4 <= end; i += 4) {
        int s0 = __ldg(col + i),     s1 = __ldg(col + i + 1);
        int s2 = __ldg(col + i + 2), s3 = __ldg(col + i + 3);
        float al0 = __ldg(als + (size_t)s0 * 4 + head);
        float al1 = __ldg(als + (size_t)s1 * 4 + head);
        float al2 = __ldg(als + (size_t)s2 * 4 + head);
        float al3 = __ldg(als + (size_t)s3 * 4 + head);
        uint4 u0 = *reinterpret_cast<const uint4*>(Hh + (size_t)s0 * 128 + hl * 8);
        uint4 u1 = *reinterpret_cast<const uint4*>(Hh + (size_t)s1 * 128 + hl * 8);
        uint4 u2 = *reinterpret_cast<const uint4*>(Hh + (size_t)s2 * 128 + hl * 8);
        uint4 u3 = *reinterpret_cast<const uint4*>(Hh + (size_t)s3 * 128 + hl * 8);
        float e0 = __expf(lrelu(al0 + ald_h));
        float e1 = __expf(lrelu(al1 + ald_h));
        float e2 = __expf(lrelu(al2 + ald_h));
        float e3 = __expf(lrelu(al3 + ald_h));
        acc_h16x8(accP, accQ, u0, e0);
        acc_h16x8(accP, accQ, u1, e1);
        acc_h16x8(accP, accQ, u2, e2);
        acc_h16x8(accP, accQ, u3, e3);
        den += (e0 + e1) + (e2 + e3);
    }
    for (; i < end; ++i) {
        int s0 = __ldg(col + i);
        float e0 = __expf(lrelu(__ldg(als + (size_t)s0 * 4 + head) + ald_h));
        uint4 u0 = *reinterpret_cast<const uint4*>(Hh + (size_t)s0 * 128 + hl * 8);
        acc_h16x8(accP, accQ, u0, e0);
        den += e0;
    }
    float inv = 1.f / (den + 1e-16f);
    float* orow = outm + (size_t)n * 128 + hl * 8;
    *reinterpret_cast<float4*>(orow) =
        make_float4(accP.x * inv, accP.y * inv, accP.z * inv, accP.w * inv);
    *reinterpret_cast<float4*>(orow + 4) =
        make_float4(accQ.x * inv, accQ.y * inv, accQ.z * inv, accQ.w * inv);
}

// ---------------- fused layer-2 aggregation + head-mean + log_softmax --------
__device__ __forceinline__ void acc_h16(float4& acc, uint2 u, float e) {
    float2 f0 = __half22float2(*reinterpret_cast<__half2*>(&u.x));
    float2 f1 = __half22float2(*reinterpret_cast<__half2*>(&u.y));
    acc.x = fmaf(e, f0.x, acc.x); acc.y = fmaf(e, f0.y, acc.y);
    acc.z = fmaf(e, f1.x, acc.z); acc.w = fmaf(e, f1.y, acc.w);
}

__global__ void aggregate_csr_160_final(const int* __restrict__ rowp,
                                        const int* __restrict__ col,
                                        const float* __restrict__ als,
                                        const float* __restrict__ ald,
                                        const __half* __restrict__ Hh,
                                        const float* __restrict__ b2,
                                        float* __restrict__ y, int N)
{
    __shared__ __align__(16) float sbuf[8][160];
    int wid  = threadIdx.x >> 5;
    int n    = (int)((blockIdx.x * (size_t)blockDim.x + threadIdx.x) >> 5);
    int lane = threadIdx.x & 31;
    if (n >= N) return;
    int head = lane / 10;
    bool two = (lane < 8);
    float ald_h = __ldg(ald + (size_t)n * 4 + head);
    int beg = __ldg(rowp + n), end = __ldg(rowp + n + 1);

    float4 acc0 = make_float4(0.f, 0.f, 0.f, 0.f);
    float4 acc1 = make_float4(0.f, 0.f, 0.f, 0.f);
    float den = 0.f;

    int i = beg;
    for (; i + 2 <= end; i += 2) {
        int s0 = __ldg(col + i), s1 = __ldg(col + i + 1);
        float al0 = __ldg(als + (size_t)s0 * 4 + head);
        float al1 = __ldg(als + (size_t)s1 * 4 + head);
        uint2 u0 = *reinterpret_cast<const uint2*>(Hh + (size_t)s0 * 160 + lane * 4);
        uint2 u1 = *reinterpret_cast<const uint2*>(Hh + (size_t)s1 * 160 + lane * 4);
        float e0 = __expf(lrelu(al0 + ald_h));
        float e1 = __expf(lrelu(al1 + ald_h));
        float e0_3 = __shfl_sync(0xffffffffu, e0, 31);
        float e1_3 = __shfl_sync(0xffffffffu, e1, 31);
        acc_h16(acc0, u0, e0);
        acc_h16(acc0, u1, e1);
        if (two) {
            uint2 v0 = *reinterpret_cast<const uint2*>(Hh + (size_t)s0 * 160 + 128 + lane * 4);
            uint2 v1 = *reinterpret_cast<const uint2*>(Hh + (size_t)s1 * 160 + 128 + lane * 4);
            acc_h16(acc1, v0, e0_3);
            acc_h16(acc1, v1, e1_3);
        }
        den += e0 + e1;
    }
    for (; i < end; ++i) {
        int s0 = __ldg(col + i);
        float e0 = __expf(lrelu(__ldg(als + (size_t)s0 * 4 + head) + ald_h));
        float e0_3 = __shfl_sync(0xffffffffu, e0, 31);
        uint2 u0 = *reinterpret_cast<const uint2*>(Hh + (size_t)s0 * 160 + lane * 4);
        acc_h16(acc0, u0, e0);
        if (two) {
            uint2 v0 = *reinterpret_cast<const uint2*>(Hh + (size_t)s0 * 160 + 128 + lane * 4);
            acc_h16(acc1, v0, e0_3);
        }
        den += e0;
    }
    float den3 = __shfl_sync(0xffffffffu, den, 31);
    float inv  = 1.f / (den  + 1e-16f);
    float inv3 = 1.f / (den3 + 1e-16f);

    *reinterpret_cast<float4*>(&sbuf[wid][lane * 4]) =
        make_float4(acc0.x * inv, acc0.y * inv, acc0.z * inv, acc0.w * inv);
    if (two)
        *reinterpret_cast<float4*>(&sbuf[wid][128 + lane * 4]) =
            make_float4(acc1.x * inv3, acc1.y * inv3, acc1.z * inv3, acc1.w * inv3);
    __syncwarp();

    const float* S = sbuf[wid];
    int c0 = lane;
    int c1 = lane + 32;
    bool has1 = (c1 < 40);

    float v0 = 0.25f * (S[c0] + S[40 + c0] + S[80 + c0] + S[120 + c0]) + __ldg(&b2[c0]);
    float v1 = -1e30f;
    if (has1)
        v1 = 0.25f * (S[c1] + S[40 + c1] + S[80 + c1] + S[120 + c1]) + __ldg(&b2[c1]);

    float m = fmaxf(v0, v1);
#pragma unroll
    for (int o = 16; o; o >>= 1) m = fmaxf(m, __shfl_xor_sync(0xffffffffu, m, o));
    float se = __expf(v0 - m) + (has1 ? __expf(v1 - m) : 0.f);
#pragma unroll
    for (int o = 16; o; o >>= 1) se += __shfl_xor_sync(0xffffffffu, se, o);
    float lse = logf(se) + m;

    y[(size_t)n * 40 + c0] = v0 - lse;
    if (has1) y[(size_t)n * 40 + c1] = v1 - lse;
}

// ---------------- host side --------------------------------------------------
extern "C" void kernel_launch(void* const* d_in, const int* in_sizes, int n_in,
                              void* d_out, int out_size)
{
    const float* x   = (const float*)d_in[0];
    const int*   ei  = (const int*)  d_in[1];
    const float* W1  = (const float*)d_in[2];
    const float* as1 = (const float*)d_in[3];
    const float* ad1 = (const float*)d_in[4];
    const float* b1  = (const float*)d_in[5];
    const float* W2  = (const float*)d_in[6];
    const float* as2 = (const float*)d_in[7];
    const float* ad2 = (const float*)d_in[8];
    const float* b2  = (const float*)d_in[9];
    float* y = (float*)d_out;

    const int N = in_sizes[0] / F1;
    const int E = in_sizes[1] / 2;
    const int* src = ei;
    const int* dst = ei + E;

    void* p;
    cudaGetSymbolAddress(&p, g_h1h);   __half* h1h = (__half*)p;
    cudaGetSymbolAddress(&p, g_h2h);   __half* h2h = (__half*)p;
    cudaGetSymbolAddress(&p, g_out1);  float* o1   = (float*)p;
    cudaGetSymbolAddress(&p, g_als1);  float* als1 = (float*)p;
    cudaGetSymbolAddress(&p, g_ald1);  float* ald1 = (float*)p;
    cudaGetSymbolAddress(&p, g_als2);  float* als2 = (float*)p;
    cudaGetSymbolAddress(&p, g_ald2);  float* ald2 = (float*)p;
    cudaGetSymbolAddress(&p, g_cnt);   int* cnt  = (int*)p;
    cudaGetSymbolAddress(&p, g_rowp);  int* rowp = (int*)p;
    cudaGetSymbolAddress(&p, g_col);   int* col  = (int*)p;
    cudaGetSymbolAddress(&p, g_state); ull* state = (ull*)p;
    cudaGetSymbolAddress(&p, g_ticket); int* ticket = (int*)p;
    int* cnt2 = cnt + MAXN;

    const int smem1 = (128 * F1 + 64 * 128) * sizeof(float);
    const int smem2 = (128 * F2 + 64 * 128) * sizeof(float);
    cudaFuncSetAttribute(gemm_k128<F1, false, true>,
                         cudaFuncAttributeMaxDynamicSharedMemorySize, smem1);
    cudaFuncSetAttribute(gemm_k128<F2, true, false>,
                         cudaFuncAttributeMaxDynamicSharedMemorySize, smem2);

    const int TB = 256;
    const int NB = (N + 511) / 512;   // 196 blocks, all co-resident (no deadlock)
    const int gemmBlocks   = (N + 63) / 64;
    const int nodeWBlocks  = (int)(((size_t)N * 32 + TB - 1) / TB);
    const int node2WBlocks = (int)((((size_t)(N + 1) / 2) * 32 + TB - 1) / TB);

    // memset nodes (not kernel launches)
    cudaMemsetAsync(cnt, 0, 2 * (size_t)MAXN * sizeof(int));
    cudaMemsetAsync(state, 0, 256 * sizeof(ull));
    cudaMemsetAsync(ticket, 0, sizeof(int));

    // k0: layer-1 GEMM + fused attention coefficients + fused degree count
    gemm_k128<F1, false, true><<<gemmBlocks, TB, smem1>>>(
        x, W1, nullptr, as1, ad1, h1h, als1, ald1, N, dst, cnt, E);

    // k1: single-pass scan (decoupled lookback)
    scan_one<<<NB, 512>>>(cnt, rowp, state, ticket, N, E);

    // k2: CSR fill
    fill_csr<<<(E + TB - 1) / TB, TB>>>(src, dst, rowp, cnt2, col, E);

    // k3: layer-1 aggregation (ncu samples this index)
    aggregate_csr_128<<<node2WBlocks, TB>>>(rowp, col, als1, ald1, h1h, o1, N);

    // k4: layer-2 GEMM
    gemm_k128<F2, true, false><<<gemmBlocks, TB, smem2>>>(
        o1, W2, b1, as2, ad2, h2h, als2, ald2, N, nullptr, nullptr, 0);

    // k5: layer-2 aggregation + head mean + log_softmax
    aggregate_csr_160_final<<<nodeWBlocks, TB>>>(rowp, col, als2, ald2, h2h, b2, y, N);
}

// round 8
// speedup vs baseline: 2.7155x; 1.0448x over previous
#include <cuda_runtime.h>
#include <cuda_fp16.h>
#include <math.h>
#include <stdint.h>

static constexpr int MAXN = 100000;
static constexpr int MAXE = 1600000;
static constexpr int F1   = 128;   // F_in and H*HID
static constexpr int F2   = 160;   // H*NCLS
static constexpr int NH   = 4;
static constexpr float NEG_SLOPE = 0.2f;

typedef unsigned long long ull;

// ---------------- scratch ----------------------------------------------------
__device__ ull   g_h1h [(size_t)MAXN * F1 / 4];   // fp16 h1, 128 halves/row
__device__ ull   g_h2h [(size_t)MAXN * F2 / 4];   // fp16 h2, 160 halves/row
__device__ float g_out1[(size_t)MAXN * F1];
__device__ float g_als1[(size_t)MAXN * NH];
__device__ float g_ald1[(size_t)MAXN * NH];
__device__ float g_als2[(size_t)MAXN * NH];
__device__ float g_ald2[(size_t)MAXN * NH];
__device__ int   g_cnt [2 * MAXN];
__device__ int   g_rowp[MAXN + 1];
__device__ int   g_col [MAXE];
__device__ ull   g_state[256];       // decoupled-lookback state
__device__ int   g_ticket;

__device__ __forceinline__ float lrelu(float v) {
    return v > 0.f ? v : NEG_SLOPE * v;
}

// ---------------- packed f32x2 helpers (sm_103a FFMA2) -----------------------
__device__ __forceinline__ ull pack2(float a, float b) {
    ull r; asm("mov.b64 %0, {%1, %2};" : "=l"(r) : "f"(a), "f"(b)); return r;
}
__device__ __forceinline__ void unpack2(ull v, float& a, float& b) {
    asm("mov.b64 {%0, %1}, %2;" : "=f"(a), "=f"(b) : "l"(v));
}
__device__ __forceinline__ void fma2(ull& d, ull a, ull b) {
    asm("fma.rn.f32x2 %0, %1, %2, %0;" : "+l"(d) : "l"(a), "l"(b));
}

// ---------------- CSR build --------------------------------------------------
__global__ void count_deg(const int* __restrict__ dst, int* __restrict__ cnt, int E) {
    int e = blockIdx.x * blockDim.x + threadIdx.x;
    if (e < E) atomicAdd(&cnt[dst[e]], 1);
}

static constexpr ull FLG_AGG = 1ull << 62;
static constexpr ull FLG_PRE = 2ull << 62;

__global__ void scan_one(const int* __restrict__ cnt, int* __restrict__ rowp,
                         ull* __restrict__ state, int* __restrict__ ticket,
                         int N, int E)
{
    __shared__ int sm[512];
    __shared__ int sbid, sprefix;
    int t = threadIdx.x;
    if (t == 0) sbid = atomicAdd(ticket, 1);
    __syncthreads();
    int b = sbid;
    int i = b * 512 + t;
    int v = (i < N) ? cnt[i] : 0;
    sm[t] = v;
    __syncthreads();
    for (int o = 1; o < 512; o <<= 1) {
        int add = (t >= o) ? sm[t - o] : 0;
        __syncthreads();
        sm[t] += add;
        __syncthreads();
    }
    int incl  = sm[t];
    int total = sm[511];
    if (t == 0) {
        if (b == 0) {
            atomicExch(&state[0], FLG_PRE | (unsigned)total);
            sprefix = 0;
        } else {
            atomicExch(&state[b], FLG_AGG | (unsigned)total);
            int run = 0, j = b - 1;
            while (true) {
                ull s;
                do { s = atomicAdd(&state[j], 0ull); } while ((s >> 62) == 0);
                run += (int)(s & 0xffffffffu);
                if (s & FLG_PRE) break;
                --j;
            }
            atomicExch(&state[b], FLG_PRE | (unsigned)(run + total));
            sprefix = run;
        }
    }
    __syncthreads();
    if (i < N) rowp[i] = sprefix + incl - v;
    if (b == 0 && t == 0) rowp[N] = E;
}

__global__ void fill_csr(const int* __restrict__ src, const int* __restrict__ dst,
                         const int* __restrict__ rowp, int* __restrict__ cnt2,
                         int* __restrict__ col, int E) {
    int e = blockIdx.x * blockDim.x + threadIdx.x;
    if (e >= E) return;
    int d = __ldg(dst + e);
    int k = atomicAdd(&cnt2[d], 1);
    col[__ldg(rowp + d) + k] = __ldg(src + e);
}

// ---------------- GEMM (f32x2) + fused attention epilogue + fp16 h store -----
template<int NOUT, bool RELU_BIAS>
__global__ void __launch_bounds__(256, 2)
gemm_k128(const float* __restrict__ A,
          const float* __restrict__ W,
          const float* __restrict__ bias,
          const float* __restrict__ a_s,
          const float* __restrict__ a_d,
          __half* __restrict__ outh,
          float* __restrict__ als,
          float* __restrict__ ald, int N)
{
    extern __shared__ float smem[];
    float* sW = smem;               // 128*NOUT
    float* sA = smem + 128 * NOUT;  // 64*128
    const int tid  = threadIdx.x;
    const int warp = tid >> 5;
    const int lane = tid & 31;
    const int row0 = blockIdx.x * 64;

    for (int i = tid * 4; i < 128 * NOUT; i += 256 * 4)
        *reinterpret_cast<float4*>(sW + i) = *reinterpret_cast<const float4*>(W + i);
    for (int i = tid; i < 64 * 128 / 4; i += 256) {
        int idx = i * 4;
        int r   = idx >> 7;
        int k   = idx & 127;
        int gr  = row0 + r;
        float4 v = make_float4(0.f, 0.f, 0.f, 0.f);
        if (gr < N) {
            v = *reinterpret_cast<const float4*>(A + (size_t)gr * 128 + k);
            if (RELU_BIAS) {
                v.x = fmaxf(v.x + bias[k + 0], 0.f);
                v.y = fmaxf(v.y + bias[k + 1], 0.f);
                v.z = fmaxf(v.z + bias[k + 2], 0.f);
                v.w = fmaxf(v.w + bias[k + 3], 0.f);
            }
        }
        *reinterpret_cast<float4*>(sA + idx) = v;
    }
    __syncthreads();

    constexpr int P = NOUT / 64;
    constexpr bool HAS_S = (NOUT == 160);
    ull acc2[8][P];
    float accS[8];
#pragma unroll
    for (int i = 0; i < 8; ++i) {
#pragma unroll
        for (int p = 0; p < P; ++p) acc2[i][p] = 0ull;
        accS[i] = 0.f;
    }

    const float* sArow = sA + (warp * 8) * 128;
    const int c2 = 2 * lane;

    for (int k0 = 0; k0 < 128; k0 += 4) {
        float4 av[8];
#pragma unroll
        for (int i = 0; i < 8; ++i)
            av[i] = *reinterpret_cast<const float4*>(sArow + i * 128 + k0);
#pragma unroll
        for (int kk = 0; kk < 4; ++kk) {
            const float* wk = sW + (k0 + kk) * NOUT;
            ull w[P];
#pragma unroll
            for (int p = 0; p < P; ++p)
                w[p] = *reinterpret_cast<const ull*>(wk + c2 + 64 * p);
            float ws = HAS_S ? wk[128 + lane] : 0.f;
#pragma unroll
            for (int i = 0; i < 8; ++i) {
                float a = (kk == 0) ? av[i].x : (kk == 1) ? av[i].y
                        : (kk == 2) ? av[i].z : av[i].w;
                ull ap = pack2(a, a);
#pragma unroll
                for (int p = 0; p < P; ++p) fma2(acc2[i][p], ap, w[p]);
                if (HAS_S) accS[i] = fmaf(a, ws, accS[i]);
            }
        }
    }

    float2 asp[P], adp[P];
#pragma unroll
    for (int p = 0; p < P; ++p) {
        asp[p] = *reinterpret_cast<const float2*>(a_s + c2 + 64 * p);
        adp[p] = *reinterpret_cast<const float2*>(a_d + c2 + 64 * p);
    }
    float asS = HAS_S ? a_s[128 + lane] : 0.f;
    float adS = HAS_S ? a_d[128 + lane] : 0.f;

#pragma unroll
    for (int i = 0; i < 8; ++i) {
        int r = row0 + warp * 8 + i;
        if (r >= N) continue;

        float a0, a1, b0, b1;
        unpack2(acc2[i][0], a0, a1);
        unpack2(acc2[i][1], b0, b1);

        *reinterpret_cast<__half2*>(outh + (size_t)r * NOUT + c2) =
            __floats2half2_rn(a0, a1);
        *reinterpret_cast<__half2*>(outh + (size_t)r * NOUT + 64 + c2) =
            __floats2half2_rn(b0, b1);
        if (HAS_S) outh[(size_t)r * NOUT + 128 + lane] = __float2half_rn(accS[i]);

        if (NOUT == 128) {
            float vsA = a0 * asp[0].x + a1 * asp[0].y;
            float vdA = a0 * adp[0].x + a1 * adp[0].y;
            float vsB = b0 * asp[1].x + b1 * asp[1].y;
            float vdB = b0 * adp[1].x + b1 * adp[1].y;
#pragma unroll
            for (int o = 8; o; o >>= 1) {
                vsA += __shfl_xor_sync(0xffffffffu, vsA, o);
                vdA += __shfl_xor_sync(0xffffffffu, vdA, o);
                vsB += __shfl_xor_sync(0xffffffffu, vsB, o);
                vdB += __shfl_xor_sync(0xffffffffu, vdB, o);
            }
            if (lane == 0) {
                als[(size_t)r * 4 + 0] = vsA;
                ald[(size_t)r * 4 + 0] = vdA;
                als[(size_t)r * 4 + 2] = vsB;
                ald[(size_t)r * 4 + 2] = vdB;
            } else if (lane == 16) {
                als[(size_t)r * 4 + 1] = vsA;
                ald[(size_t)r * 4 + 1] = vdA;
                als[(size_t)r * 4 + 3] = vsB;
                ald[(size_t)r * 4 + 3] = vdB;
            }
        } else {
            float s0 = 0.f, s1 = 0.f, s2 = 0.f, s3 = 0.f;
            float d0 = 0.f, d1 = 0.f, d2 = 0.f, d3 = 0.f;
            float vA_s = a0 * asp[0].x + a1 * asp[0].y;
            float vA_d = a0 * adp[0].x + a1 * adp[0].y;
            if (lane < 20) { s0 += vA_s; d0 += vA_d; } else { s1 += vA_s; d1 += vA_d; }
            float vB_s = b0 * asp[1].x + b1 * asp[1].y;
            float vB_d = b0 * adp[1].x + b1 * adp[1].y;
            if (lane < 8)       { s1 += vB_s; d1 += vB_d; }
            else if (lane < 28) { s2 += vB_s; d2 += vB_d; }
            else                { s3 += vB_s; d3 += vB_d; }
            s3 += accS[i] * asS;
            d3 += accS[i] * adS;
#pragma unroll
            for (int o = 16; o; o >>= 1) {
                s0 += __shfl_xor_sync(0xffffffffu, s0, o);
                d0 += __shfl_xor_sync(0xffffffffu, d0, o);
                s1 += __shfl_xor_sync(0xffffffffu, s1, o);
                d1 += __shfl_xor_sync(0xffffffffu, d1, o);
                s2 += __shfl_xor_sync(0xffffffffu, s2, o);
                d2 += __shfl_xor_sync(0xffffffffu, d2, o);
                s3 += __shfl_xor_sync(0xffffffffu, s3, o);
                d3 += __shfl_xor_sync(0xffffffffu, d3, o);
            }
            if (lane == 0) {
                als[(size_t)r * 4 + 0] = s0; ald[(size_t)r * 4 + 0] = d0;
                als[(size_t)r * 4 + 1] = s1; ald[(size_t)r * 4 + 1] = d1;
                als[(size_t)r * 4 + 2] = s2; ald[(size_t)r * 4 + 2] = d2;
                als[(size_t)r * 4 + 3] = s3; ald[(size_t)r * 4 + 3] = d3;
            }
        }
    }
}

// ---------------- layer-1 aggregation: 2 nodes per warp ----------------------
__device__ __forceinline__ void acc_h16x8(float4& p, float4& q, uint4 u, float e) {
    float2 f0 = __half22float2(*reinterpret_cast<__half2*>(&u.x));
    float2 f1 = __half22float2(*reinterpret_cast<__half2*>(&u.y));
    float2 f2 = __half22float2(*reinterpret_cast<__half2*>(&u.z));
    float2 f3 = __half22float2(*reinterpret_cast<__half2*>(&u.w));
    p.x = fmaf(e, f0.x, p.x); p.y = fmaf(e, f0.y, p.y);
    p.z = fmaf(e, f1.x, p.z); p.w = fmaf(e, f1.y, p.w);
    q.x = fmaf(e, f2.x, q.x); q.y = fmaf(e, f2.y, q.y);
    q.z = fmaf(e, f3.x, q.z); q.w = fmaf(e, f3.y, q.w);
}

__global__ void aggregate_csr_128(const int* __restrict__ rowp,
                                  const int* __restrict__ col,
                                  const float* __restrict__ als,
                                  const float* __restrict__ ald,
                                  const __half* __restrict__ Hh,
                                  float* __restrict__ outm, int N)
{
    int w    = (int)((blockIdx.x * (size_t)blockDim.x + threadIdx.x) >> 5);
    int lane = threadIdx.x & 31;
    int hw   = lane >> 4;
    int hl   = lane & 15;
    int n = w * 2 + hw;
    if (n >= N) return;
    int head = hl >> 2;
    float ald_h = __ldg(ald + (size_t)n * 4 + head);
    int beg = __ldg(rowp + n), end = __ldg(rowp + n + 1);

    float4 accP = make_float4(0.f, 0.f, 0.f, 0.f);
    float4 accQ = make_float4(0.f, 0.f, 0.f, 0.f);
    float den = 0.f;

    int i = beg;
    for (; i + 4 <= end; i += 4) {
        int s0 = __ldg(col + i),     s1 = __ldg(col + i + 1);
        int s2 = __ldg(col + i + 2), s3 = __ldg(col + i + 3);
        float al0 = __ldg(als + (size_t)s0 * 4 + head);
        float al1 = __ldg(als + (size_t)s1 * 4 + head);
        float al2 = __ldg(als + (size_t)s2 * 4 + head);
        float al3 = __ldg(als + (size_t)s3 * 4 + head);
        uint4 u0 = *reinterpret_cast<const uint4*>(Hh + (size_t)s0 * 128 + hl * 8);
        uint4 u1 = *reinterpret_cast<const uint4*>(Hh + (size_t)s1 * 128 + hl * 8);
        uint4 u2 = *reinterpret_cast<const uint4*>(Hh + (size_t)s2 * 128 + hl * 8);
        uint4 u3 = *reinterpret_cast<const uint4*>(Hh + (size_t)s3 * 128 + hl * 8);
        float e0 = __expf(lrelu(al0 + ald_h));
        float e1 = __expf(lrelu(al1 + ald_h));
        float e2 = __expf(lrelu(al2 + ald_h));
        float e3 = __expf(lrelu(al3 + ald_h));
        acc_h16x8(accP, accQ, u0, e0);
        acc_h16x8(accP, accQ, u1, e1);
        acc_h16x8(accP, accQ, u2, e2);
        acc_h16x8(accP, accQ, u3, e3);
        den += (e0 + e1) + (e2 + e3);
    }
    for (; i < end; ++i) {
        int s0 = __ldg(col + i);
        float e0 = __expf(lrelu(__ldg(als + (size_t)s0 * 4 + head) + ald_h));
        uint4 u0 = *reinterpret_cast<const uint4*>(Hh + (size_t)s0 * 128 + hl * 8);
        acc_h16x8(accP, accQ, u0, e0);
        den += e0;
    }
    float inv = 1.f / (den + 1e-16f);
    float* orow = outm + (size_t)n * 128 + hl * 8;
    *reinterpret_cast<float4*>(orow) =
        make_float4(accP.x * inv, accP.y * inv, accP.z * inv, accP.w * inv);
    *reinterpret_cast<float4*>(orow + 4) =
        make_float4(accQ.x * inv, accQ.y * inv, accQ.z * inv, accQ.w * inv);
}

// ---------------- layer-2 aggregation + head-mean + log_softmax --------------
// 20 active lanes x uint4 (8 halves) cover the 320B fp16 row exactly.
// 40 = 5*8, so each lane's 8 halves lie in one head: head = lane/5. No shuffles.
__global__ void aggregate_csr_160_final(const int* __restrict__ rowp,
                                        const int* __restrict__ col,
                                        const float* __restrict__ als,
                                        const float* __restrict__ ald,
                                        const __half* __restrict__ Hh,
                                        const float* __restrict__ b2,
                                        float* __restrict__ y, int N)
{
    __shared__ __align__(16) float sbuf[8][160];
    int wid  = threadIdx.x >> 5;
    int n    = (int)((blockIdx.x * (size_t)blockDim.x + threadIdx.x) >> 5);
    int lane = threadIdx.x & 31;
    if (n >= N) return;
    bool act = (lane < 20);
    int head = act ? (lane / 5) : 0;
    float ald_h = __ldg(ald + (size_t)n * 4 + head);
    int beg = __ldg(rowp + n), end = __ldg(rowp + n + 1);

    float4 accP = make_float4(0.f, 0.f, 0.f, 0.f);
    float4 accQ = make_float4(0.f, 0.f, 0.f, 0.f);
    float den = 0.f;
    const uint4 uz = make_uint4(0u, 0u, 0u, 0u);

    int i = beg;
    for (; i + 4 <= end; i += 4) {
        int s0 = __ldg(col + i),     s1 = __ldg(col + i + 1);
        int s2 = __ldg(col + i + 2), s3 = __ldg(col + i + 3);
        float al0 = __ldg(als + (size_t)s0 * 4 + head);
        float al1 = __ldg(als + (size_t)s1 * 4 + head);
        float al2 = __ldg(als + (size_t)s2 * 4 + head);
        float al3 = __ldg(als + (size_t)s3 * 4 + head);
        uint4 u0 = act ? *reinterpret_cast<const uint4*>(Hh + (size_t)s0 * 160 + lane * 8) : uz;
        uint4 u1 = act ? *reinterpret_cast<const uint4*>(Hh + (size_t)s1 * 160 + lane * 8) : uz;
        uint4 u2 = act ? *reinterpret_cast<const uint4*>(Hh + (size_t)s2 * 160 + lane * 8) : uz;
        uint4 u3 = act ? *reinterpret_cast<const uint4*>(Hh + (size_t)s3 * 160 + lane * 8) : uz;
        float e0 = __expf(lrelu(al0 + ald_h));
        float e1 = __expf(lrelu(al1 + ald_h));
        float e2 = __expf(lrelu(al2 + ald_h));
        float e3 = __expf(lrelu(al3 + ald_h));
        acc_h16x8(accP, accQ, u0, e0);
        acc_h16x8(accP, accQ, u1, e1);
        acc_h16x8(accP, accQ, u2, e2);
        acc_h16x8(accP, accQ, u3, e3);
        den += (e0 + e1) + (e2 + e3);
    }
    for (; i < end; ++i) {
        int s0 = __ldg(col + i);
        float e0 = __expf(lrelu(__ldg(als + (size_t)s0 * 4 + head) + ald_h));
        uint4 u0 = act ? *reinterpret_cast<const uint4*>(Hh + (size_t)s0 * 160 + lane * 8) : uz;
        acc_h16x8(accP, accQ, u0, e0);
        den += e0;
    }
    float inv = 1.f / (den + 1e-16f);
    if (act) {
        *reinterpret_cast<float4*>(&sbuf[wid][lane * 8]) =
            make_float4(accP.x * inv, accP.y * inv, accP.z * inv, accP.w * inv);
        *reinterpret_cast<float4*>(&sbuf[wid][lane * 8 + 4]) =
            make_float4(accQ.x * inv, accQ.y * inv, accQ.z * inv, accQ.w * inv);
    }
    __syncwarp();

    const float* S = sbuf[wid];
    int c0 = lane;
    int c1 = lane + 32;
    bool has1 = (c1 < 40);

    float v0 = 0.25f * (S[c0] + S[40 + c0] + S[80 + c0] + S[120 + c0]) + __ldg(&b2[c0]);
    float v1 = -1e30f;
    if (has1)
        v1 = 0.25f * (S[c1] + S[40 + c1] + S[80 + c1] + S[120 + c1]) + __ldg(&b2[c1]);

    float m = fmaxf(v0, v1);
#pragma unroll
    for (int o = 16; o; o >>= 1) m = fmaxf(m, __shfl_xor_sync(0xffffffffu, m, o));
    float se = __expf(v0 - m) + (has1 ? __expf(v1 - m) : 0.f);
#pragma unroll
    for (int o = 16; o; o >>= 1) se += __shfl_xor_sync(0xffffffffu, se, o);
    float lse = logf(se) + m;

    y[(size_t)n * 40 + c0] = v0 - lse;
    if (has1) y[(size_t)n * 40 + c1] = v1 - lse;
}

// ---------------- host side --------------------------------------------------
extern "C" void kernel_launch(void* const* d_in, const int* in_sizes, int n_in,
                              void* d_out, int out_size)
{
    const float* x   = (const float*)d_in[0];
    const int*   ei  = (const int*)  d_in[1];
    const float* W1  = (const float*)d_in[2];
    const float* as1 = (const float*)d_in[3];
    const float* ad1 = (const float*)d_in[4];
    const float* b1  = (const float*)d_in[5];
    const float* W2  = (const float*)d_in[6];
    const float* as2 = (const float*)d_in[7];
    const float* ad2 = (const float*)d_in[8];
    const float* b2  = (const float*)d_in[9];
    float* y = (float*)d_out;

    const int N = in_sizes[0] / F1;
    const int E = in_sizes[1] / 2;
    const int* src = ei;
    const int* dst = ei + E;

    void* p;
    cudaGetSymbolAddress(&p, g_h1h);   __half* h1h = (__half*)p;
    cudaGetSymbolAddress(&p, g_h2h);   __half* h2h = (__half*)p;
    cudaGetSymbolAddress(&p, g_out1);  float* o1   = (float*)p;
    cudaGetSymbolAddress(&p, g_als1);  float* als1 = (float*)p;
    cudaGetSymbolAddress(&p, g_ald1);  float* ald1 = (float*)p;
    cudaGetSymbolAddress(&p, g_als2);  float* als2 = (float*)p;
    cudaGetSymbolAddress(&p, g_ald2);  float* ald2 = (float*)p;
    cudaGetSymbolAddress(&p, g_cnt);   int* cnt  = (int*)p;
    cudaGetSymbolAddress(&p, g_rowp);  int* rowp = (int*)p;
    cudaGetSymbolAddress(&p, g_col);   int* col  = (int*)p;
    cudaGetSymbolAddress(&p, g_state); ull* state = (ull*)p;
    cudaGetSymbolAddress(&p, g_ticket); int* ticket = (int*)p;
    int* cnt2 = cnt + MAXN;

    // persistent side stream + events (created once, outside graph capture —
    // first harness call is the uncaptured correctness run)
    static cudaStream_t s2 = nullptr;
    static cudaEvent_t evFork = nullptr, evJoin = nullptr;
    if (!s2) {
        cudaStreamCreateWithFlags(&s2, cudaStreamNonBlocking);
        cudaEventCreateWithFlags(&evFork, cudaEventDisableTiming);
        cudaEventCreateWithFlags(&evJoin, cudaEventDisableTiming);
    }

    const int smem1 = (128 * F1 + 64 * 128) * sizeof(float);
    const int smem2 = (128 * F2 + 64 * 128) * sizeof(float);
    cudaFuncSetAttribute(gemm_k128<F1, false>,
                         cudaFuncAttributeMaxDynamicSharedMemorySize, smem1);
    cudaFuncSetAttribute(gemm_k128<F2, true>,
                         cudaFuncAttributeMaxDynamicSharedMemorySize, smem2);

    const int TB = 256;
    const int NB = (N + 511) / 512;   // 196 blocks, ticket-ordered lookback
    const int gemmBlocks   = (N + 63) / 64;
    const int nodeWBlocks  = (int)(((size_t)N * 32 + TB - 1) / TB);
    const int node2WBlocks = (int)((((size_t)(N + 1) / 2) * 32 + TB - 1) / TB);

    // zero scratch (graph memset nodes, main stream)
    cudaMemsetAsync(cnt, 0, 2 * (size_t)MAXN * sizeof(int));
    cudaMemsetAsync(state, 0, 256 * sizeof(ull));
    cudaMemsetAsync(ticket, 0, sizeof(int));

    // fork: CSR build on s2 runs concurrently with gemm1 on the main stream
    cudaEventRecord(evFork, 0);
    cudaStreamWaitEvent(s2, evFork, 0);

    // s2 branch: count -> scan -> fill   (k0, k1, k2 in submission order)
    count_deg<<<(E + TB - 1) / TB, TB, 0, s2>>>(dst, cnt, E);
    scan_one<<<NB, 512, 0, s2>>>(cnt, rowp, state, ticket, N, E);
    fill_csr<<<(E + TB - 1) / TB, TB, 0, s2>>>(src, dst, rowp, cnt2, col, E);
    cudaEventRecord(evJoin, s2);

    // main stream: layer-1 GEMM (k3 — ncu samples this index)
    gemm_k128<F1, false><<<gemmBlocks, TB, smem1>>>(
        x, W1, nullptr, as1, ad1, h1h, als1, ald1, N);

    // join: aggregation needs both the CSR and h1/als1/ald1
    cudaStreamWaitEvent(0, evJoin, 0);

    // k4: layer-1 aggregation
    aggregate_csr_128<<<node2WBlocks, TB>>>(rowp, col, als1, ald1, h1h, o1, N);

    // k5: layer-2 GEMM
    gemm_k128<F2, true><<<gemmBlocks, TB, smem2>>>(
        o1, W2, b1, as2, ad2, h2h, als2, ald2, N);

    // k6: layer-2 aggregation + head mean + log_softmax
    aggregate_csr_160_final<<<nodeWBlocks, TB>>>(rowp, col, als2, ald2, h2h, b2, y, N);
}

// round 10
// speedup vs baseline: 2.8491x; 1.0492x over previous
#include <cuda_runtime.h>
#include <cuda_fp16.h>
#include <math.h>
#include <stdint.h>

static constexpr int MAXN = 100000;
static constexpr int MAXE = 1600000;
static constexpr int F1   = 128;   // F_in and H*HID
static constexpr int F2   = 160;   // H*NCLS
static constexpr int NH   = 4;
static constexpr float NEG_SLOPE = 0.2f;

typedef unsigned long long ull;

// ---------------- scratch ----------------------------------------------------
__device__ ull   g_h1h [(size_t)MAXN * F1 / 4];   // fp16 h1, 128 halves/row
__device__ ull   g_h2h [(size_t)MAXN * F2 / 4];   // fp16 h2, 160 halves/row
__device__ float g_out1[(size_t)MAXN * F1];
__device__ float g_als1[(size_t)MAXN * NH];
__device__ float g_ald1[(size_t)MAXN * NH];
__device__ float g_als2[(size_t)MAXN * NH];
__device__ float g_ald2[(size_t)MAXN * NH];
__device__ int   g_cnt [2 * MAXN];
__device__ int   g_rowp[MAXN + 1];
__device__ int   g_col [MAXE];
__device__ ull   g_state[256];       // decoupled-lookback state
__device__ int   g_ticket;

__device__ __forceinline__ float lrelu(float v) {
    return v > 0.f ? v : NEG_SLOPE * v;
}

// ---------------- packed f32x2 helpers (sm_103a FFMA2) -----------------------
__device__ __forceinline__ ull pack2(float a, float b) {
    ull r; asm("mov.b64 %0, {%1, %2};" : "=l"(r) : "f"(a), "f"(b)); return r;
}
__device__ __forceinline__ void unpack2(ull v, float& a, float& b) {
    asm("mov.b64 {%0, %1}, %2;" : "=f"(a), "=f"(b) : "l"(v));
}
__device__ __forceinline__ void fma2(ull& d, ull a, ull b) {
    asm("fma.rn.f32x2 %0, %1, %2, %0;" : "+l"(d) : "l"(a), "l"(b));
}

// ---------------- CSR build --------------------------------------------------
__global__ void count_deg(const int* __restrict__ dst, int* __restrict__ cnt, int E) {
    int e = blockIdx.x * blockDim.x + threadIdx.x;
    if (e < E) atomicAdd(&cnt[dst[e]], 1);
}

static constexpr ull FLG_AGG = 1ull << 62;
static constexpr ull FLG_PRE = 2ull << 62;

__global__ void scan_one(const int* __restrict__ cnt, int* __restrict__ rowp,
                         ull* __restrict__ state, int* __restrict__ ticket,
                         int N, int E)
{
    __shared__ int sm[512];
    __shared__ int sbid, sprefix;
    int t = threadIdx.x;
    if (t == 0) sbid = atomicAdd(ticket, 1);
    __syncthreads();
    int b = sbid;
    int i = b * 512 + t;
    int v = (i < N) ? cnt[i] : 0;
    sm[t] = v;
    __syncthreads();
    for (int o = 1; o < 512; o <<= 1) {
        int add = (t >= o) ? sm[t - o] : 0;
        __syncthreads();
        sm[t] += add;
        __syncthreads();
    }
    int incl  = sm[t];
    int total = sm[511];
    if (t == 0) {
        if (b == 0) {
            atomicExch(&state[0], FLG_PRE | (unsigned)total);
            sprefix = 0;
        } else {
            atomicExch(&state[b], FLG_AGG | (unsigned)total);
            int run = 0, j = b - 1;
            while (true) {
                ull s;
                do { s = atomicAdd(&state[j], 0ull); } while ((s >> 62) == 0);
                run += (int)(s & 0xffffffffu);
                if (s & FLG_PRE) break;
                --j;
            }
            atomicExch(&state[b], FLG_PRE | (unsigned)(run + total));
            sprefix = run;
        }
    }
    __syncthreads();
    if (i < N) rowp[i] = sprefix + incl - v;
    if (b == 0 && t == 0) rowp[N] = E;
}

__global__ void fill_csr(const int* __restrict__ src, const int* __restrict__ dst,
                         const int* __restrict__ rowp, int* __restrict__ cnt2,
                         int* __restrict__ col, int E) {
    int e = blockIdx.x * blockDim.x + threadIdx.x;
    if (e >= E) return;
    int d = __ldg(dst + e);
    int k = atomicAdd(&cnt2[d], 1);
    col[__ldg(rowp + d) + k] = __ldg(src + e);
}

// ---------------- GEMM (f32x2, k-split W tile) + fused attention epilogue ----
// smem = 64-row W half (64*NOUT) + full A tile (64*128). 3 CTAs/SM.
template<int NOUT, bool RELU_BIAS>
__global__ void __launch_bounds__(256, 3)
gemm_k128(const float* __restrict__ A,
          const float* __restrict__ W,
          const float* __restrict__ bias,
          const float* __restrict__ a_s,
          const float* __restrict__ a_d,
          __half* __restrict__ outh,
          float* __restrict__ als,
          float* __restrict__ ald, int N)
{
    extern __shared__ float smem[];
    float* sW = smem;               // 64*NOUT (one k-half of W)
    float* sA = smem + 64 * NOUT;   // 64*128
    const int tid  = threadIdx.x;
    const int warp = tid >> 5;
    const int lane = tid & 31;
    const int row0 = blockIdx.x * 64;

    // load A tile (once)
    for (int i = tid; i < 64 * 128 / 4; i += 256) {
        int idx = i * 4;
        int r   = idx >> 7;
        int k   = idx & 127;
        int gr  = row0 + r;
        float4 v = make_float4(0.f, 0.f, 0.f, 0.f);
        if (gr < N) {
            v = *reinterpret_cast<const float4*>(A + (size_t)gr * 128 + k);
            if (RELU_BIAS) {
                v.x = fmaxf(v.x + bias[k + 0], 0.f);
                v.y = fmaxf(v.y + bias[k + 1], 0.f);
                v.z = fmaxf(v.z + bias[k + 2], 0.f);
                v.w = fmaxf(v.w + bias[k + 3], 0.f);
            }
        }
        *reinterpret_cast<float4*>(sA + idx) = v;
    }

    constexpr int P = NOUT / 64;
    constexpr bool HAS_S = (NOUT == 160);
    ull acc2[8][P];
    float accS[8];
#pragma unroll
    for (int i = 0; i < 8; ++i) {
#pragma unroll
        for (int p = 0; p < P; ++p) acc2[i][p] = 0ull;
        accS[i] = 0.f;
    }

    const float* sArow = sA + (warp * 8) * 128;
    const int c2 = 2 * lane;

#pragma unroll
    for (int kh = 0; kh < 2; ++kh) {
        if (kh) __syncthreads();      // all warps done with previous W half
        // load W k-half [kh*64, kh*64+64)
        for (int i = tid * 4; i < 64 * NOUT; i += 256 * 4)
            *reinterpret_cast<float4*>(sW + i) =
                *reinterpret_cast<const float4*>(W + kh * 64 * NOUT + i);
        __syncthreads();

        for (int k0 = 0; k0 < 64; k0 += 4) {
            float4 av[8];
#pragma unroll
            for (int i = 0; i < 8; ++i)
                av[i] = *reinterpret_cast<const float4*>(sArow + i * 128 + kh * 64 + k0);
#pragma unroll
            for (int kk = 0; kk < 4; ++kk) {
                const float* wk = sW + (k0 + kk) * NOUT;
                ull w[P];
#pragma unroll
                for (int p = 0; p < P; ++p)
                    w[p] = *reinterpret_cast<const ull*>(wk + c2 + 64 * p);
                float ws = HAS_S ? wk[128 + lane] : 0.f;
#pragma unroll
                for (int i = 0; i < 8; ++i) {
                    float a = (kk == 0) ? av[i].x : (kk == 1) ? av[i].y
                            : (kk == 2) ? av[i].z : av[i].w;
                    ull ap = pack2(a, a);
#pragma unroll
                    for (int p = 0; p < P; ++p) fma2(acc2[i][p], ap, w[p]);
                    if (HAS_S) accS[i] = fmaf(a, ws, accS[i]);
                }
            }
        }
    }

    float2 asp[P], adp[P];
#pragma unroll
    for (int p = 0; p < P; ++p) {
        asp[p] = *reinterpret_cast<const float2*>(a_s + c2 + 64 * p);
        adp[p] = *reinterpret_cast<const float2*>(a_d + c2 + 64 * p);
    }
    float asS = HAS_S ? a_s[128 + lane] : 0.f;
    float adS = HAS_S ? a_d[128 + lane] : 0.f;

#pragma unroll
    for (int i = 0; i < 8; ++i) {
        int r = row0 + warp * 8 + i;
        if (r >= N) continue;

        float a0, a1, b0, b1;
        unpack2(acc2[i][0], a0, a1);
        unpack2(acc2[i][1], b0, b1);

        *reinterpret_cast<__half2*>(outh + (size_t)r * NOUT + c2) =
            __floats2half2_rn(a0, a1);
        *reinterpret_cast<__half2*>(outh + (size_t)r * NOUT + 64 + c2) =
            __floats2half2_rn(b0, b1);
        if (HAS_S) outh[(size_t)r * NOUT + 128 + lane] = __float2half_rn(accS[i]);

        if (NOUT == 128) {
            float vsA = a0 * asp[0].x + a1 * asp[0].y;
            float vdA = a0 * adp[0].x + a1 * adp[0].y;
            float vsB = b0 * asp[1].x + b1 * asp[1].y;
            float vdB = b0 * adp[1].x + b1 * adp[1].y;
#pragma unroll
            for (int o = 8; o; o >>= 1) {
                vsA += __shfl_xor_sync(0xffffffffu, vsA, o);
                vdA += __shfl_xor_sync(0xffffffffu, vdA, o);
                vsB += __shfl_xor_sync(0xffffffffu, vsB, o);
                vdB += __shfl_xor_sync(0xffffffffu, vdB, o);
            }
            if (lane == 0) {
                als[(size_t)r * 4 + 0] = vsA;
                ald[(size_t)r * 4 + 0] = vdA;
                als[(size_t)r * 4 + 2] = vsB;
                ald[(size_t)r * 4 + 2] = vdB;
            } else if (lane == 16) {
                als[(size_t)r * 4 + 1] = vsA;
                ald[(size_t)r * 4 + 1] = vdA;
                als[(size_t)r * 4 + 3] = vsB;
                ald[(size_t)r * 4 + 3] = vdB;
            }
        } else {
            float s0 = 0.f, s1 = 0.f, s2 = 0.f, s3 = 0.f;
            float d0 = 0.f, d1 = 0.f, d2 = 0.f, d3 = 0.f;
            float vA_s = a0 * asp[0].x + a1 * asp[0].y;
            float vA_d = a0 * adp[0].x + a1 * adp[0].y;
            if (lane < 20) { s0 += vA_s; d0 += vA_d; } else { s1 += vA_s; d1 += vA_d; }
            float vB_s = b0 * asp[1].x + b1 * asp[1].y;
            float vB_d = b0 * adp[1].x + b1 * adp[1].y;
            if (lane < 8)       { s1 += vB_s; d1 += vB_d; }
            else if (lane < 28) { s2 += vB_s; d2 += vB_d; }
            else                { s3 += vB_s; d3 += vB_d; }
            s3 += accS[i] * asS;
            d3 += accS[i] * adS;
#pragma unroll
            for (int o = 16; o; o >>= 1) {
                s0 += __shfl_xor_sync(0xffffffffu, s0, o);
                d0 += __shfl_xor_sync(0xffffffffu, d0, o);
                s1 += __shfl_xor_sync(0xffffffffu, s1, o);
                d1 += __shfl_xor_sync(0xffffffffu, d1, o);
                s2 += __shfl_xor_sync(0xffffffffu, s2, o);
                d2 += __shfl_xor_sync(0xffffffffu, d2, o);
                s3 += __shfl_xor_sync(0xffffffffu, s3, o);
                d3 += __shfl_xor_sync(0xffffffffu, d3, o);
            }
            if (lane == 0) {
                als[(size_t)r * 4 + 0] = s0; ald[(size_t)r * 4 + 0] = d0;
                als[(size_t)r * 4 + 1] = s1; ald[(size_t)r * 4 + 1] = d1;
                als[(size_t)r * 4 + 2] = s2; ald[(size_t)r * 4 + 2] = d2;
                als[(size_t)r * 4 + 3] = s3; ald[(size_t)r * 4 + 3] = d3;
            }
        }
    }
}

// ---------------- layer-1 aggregation: 2 nodes per warp ----------------------
__device__ __forceinline__ void acc_h16x8(float4& p, float4& q, uint4 u, float e) {
    float2 f0 = __half22float2(*reinterpret_cast<__half2*>(&u.x));
    float2 f1 = __half22float2(*reinterpret_cast<__half2*>(&u.y));
    float2 f2 = __half22float2(*reinterpret_cast<__half2*>(&u.z));
    float2 f3 = __half22float2(*reinterpret_cast<__half2*>(&u.w));
    p.x = fmaf(e, f0.x, p.x); p.y = fmaf(e, f0.y, p.y);
    p.z = fmaf(e, f1.x, p.z); p.w = fmaf(e, f1.y, p.w);
    q.x = fmaf(e, f2.x, q.x); q.y = fmaf(e, f2.y, q.y);
    q.z = fmaf(e, f3.x, q.z); q.w = fmaf(e, f3.y, q.w);
}

__global__ void aggregate_csr_128(const int* __restrict__ rowp,
                                  const int* __restrict__ col,
                                  const float* __restrict__ als,
                                  const float* __restrict__ ald,
                                  const __half* __restrict__ Hh,
                                  float* __restrict__ outm, int N)
{
    int w    = (int)((blockIdx.x * (size_t)blockDim.x + threadIdx.x) >> 5);
    int lane = threadIdx.x & 31;
    int hw   = lane >> 4;
    int hl   = lane & 15;
    int n = w * 2 + hw;
    if (n >= N) return;
    int head = hl >> 2;
    float ald_h = __ldg(ald + (size_t)n * 4 + head);
    int beg = __ldg(rowp + n), end = __ldg(rowp + n + 1);

    float4 accP = make_float4(0.f, 0.f, 0.f, 0.f);
    float4 accQ = make_float4(0.f, 0.f, 0.f, 0.f);
    float den = 0.f;

    int i = beg;
    for (; i + 4 <= end; i += 4) {
        int s0 = __ldg(col + i),     s1 = __ldg(col + i + 1);
        int s2 = __ldg(col + i + 2), s3 = __ldg(col + i + 3);
        float al0 = __ldg(als + (size_t)s0 * 4 + head);
        float al1 = __ldg(als + (size_t)s1 * 4 + head);
        float al2 = __ldg(als + (size_t)s2 * 4 + head);
        float al3 = __ldg(als + (size_t)s3 * 4 + head);
        uint4 u0 = *reinterpret_cast<const uint4*>(Hh + (size_t)s0 * 128 + hl * 8);
        uint4 u1 = *reinterpret_cast<const uint4*>(Hh + (size_t)s1 * 128 + hl * 8);
        uint4 u2 = *reinterpret_cast<const uint4*>(Hh + (size_t)s2 * 128 + hl * 8);
        uint4 u3 = *reinterpret_cast<const uint4*>(Hh + (size_t)s3 * 128 + hl * 8);
        float e0 = __expf(lrelu(al0 + ald_h));
        float e1 = __expf(lrelu(al1 + ald_h));
        float e2 = __expf(lrelu(al2 + ald_h));
        float e3 = __expf(lrelu(al3 + ald_h));
        acc_h16x8(accP, accQ, u0, e0);
        acc_h16x8(accP, accQ, u1, e1);
        acc_h16x8(accP, accQ, u2, e2);
        acc_h16x8(accP, accQ, u3, e3);
        den += (e0 + e1) + (e2 + e3);
    }
    for (; i < end; ++i) {
        int s0 = __ldg(col + i);
        float e0 = __expf(lrelu(__ldg(als + (size_t)s0 * 4 + head) + ald_h));
        uint4 u0 = *reinterpret_cast<const uint4*>(Hh + (size_t)s0 * 128 + hl * 8);
        acc_h16x8(accP, accQ, u0, e0);
        den += e0;
    }
    float inv = 1.f / (den + 1e-16f);
    float* orow = outm + (size_t)n * 128 + hl * 8;
    *reinterpret_cast<float4*>(orow) =
        make_float4(accP.x * inv, accP.y * inv, accP.z * inv, accP.w * inv);
    *reinterpret_cast<float4*>(orow + 4) =
        make_float4(accQ.x * inv, accQ.y * inv, accQ.z * inv, accQ.w * inv);
}

// ---------------- layer-2 aggregation + head-mean + log_softmax --------------
__global__ void aggregate_csr_160_final(const int* __restrict__ rowp,
                                        const int* __restrict__ col,
                                        const float* __restrict__ als,
                                        const float* __restrict__ ald,
                                        const __half* __restrict__ Hh,
                                        const float* __restrict__ b2,
                                        float* __restrict__ y, int N)
{
    __shared__ __align__(16) float sbuf[8][160];
    int wid  = threadIdx.x >> 5;
    int n    = (int)((blockIdx.x * (size_t)blockDim.x + threadIdx.x) >> 5);
    int lane = threadIdx.x & 31;
    if (n >= N) return;
    bool act = (lane < 20);
    int head = act ? (lane / 5) : 0;
    float ald_h = __ldg(ald + (size_t)n * 4 + head);
    int beg = __ldg(rowp + n), end = __ldg(rowp + n + 1);

    float4 accP = make_float4(0.f, 0.f, 0.f, 0.f);
    float4 accQ = make_float4(0.f, 0.f, 0.f, 0.f);
    float den = 0.f;
    const uint4 uz = make_uint4(0u, 0u, 0u, 0u);

    int i = beg;
    for (; i + 4 <= end; i += 4) {
        int s0 = __ldg(col + i),     s1 = __ldg(col + i + 1);
        int s2 = __ldg(col + i + 2), s3 = __ldg(col + i + 3);
        float al0 = __ldg(als + (size_t)s0 * 4 + head);
        float al1 = __ldg(als + (size_t)s1 * 4 + head);
        float al2 = __ldg(als + (size_t)s2 * 4 + head);
        float al3 = __ldg(als + (size_t)s3 * 4 + head);
        uint4 u0 = act ? *reinterpret_cast<const uint4*>(Hh + (size_t)s0 * 160 + lane * 8) : uz;
        uint4 u1 = act ? *reinterpret_cast<const uint4*>(Hh + (size_t)s1 * 160 + lane * 8) : uz;
        uint4 u2 = act ? *reinterpret_cast<const uint4*>(Hh + (size_t)s2 * 160 + lane * 8) : uz;
        uint4 u3 = act ? *reinterpret_cast<const uint4*>(Hh + (size_t)s3 * 160 + lane * 8) : uz;
        float e0 = __expf(lrelu(al0 + ald_h));
        float e1 = __expf(lrelu(al1 + ald_h));
        float e2 = __expf(lrelu(al2 + ald_h));
        float e3 = __expf(lrelu(al3 + ald_h));
        acc_h16x8(accP, accQ, u0, e0);
        acc_h16x8(accP, accQ, u1, e1);
        acc_h16x8(accP, accQ, u2, e2);
        acc_h16x8(accP, accQ, u3, e3);
        den += (e0 + e1) + (e2 + e3);
    }
    for (; i < end; ++i) {
        int s0 = __ldg(col + i);
        float e0 = __expf(lrelu(__ldg(als + (size_t)s0 * 4 + head) + ald_h));
        uint4 u0 = act ? *reinterpret_cast<const uint4*>(Hh + (size_t)s0 * 160 + lane * 8) : uz;
        acc_h16x8(accP, accQ, u0, e0);
        den += e0;
    }
    float inv = 1.f / (den + 1e-16f);
    if (act) {
        *reinterpret_cast<float4*>(&sbuf[wid][lane * 8]) =
            make_float4(accP.x * inv, accP.y * inv, accP.z * inv, accP.w * inv);
        *reinterpret_cast<float4*>(&sbuf[wid][lane * 8 + 4]) =
            make_float4(accQ.x * inv, accQ.y * inv, accQ.z * inv, accQ.w * inv);
    }
    __syncwarp();

    const float* S = sbuf[wid];
    int c0 = lane;
    int c1 = lane + 32;
    bool has1 = (c1 < 40);

    float v0 = 0.25f * (S[c0] + S[40 + c0] + S[80 + c0] + S[120 + c0]) + __ldg(&b2[c0]);
    float v1 = -1e30f;
    if (has1)
        v1 = 0.25f * (S[c1] + S[40 + c1] + S[80 + c1] + S[120 + c1]) + __ldg(&b2[c1]);

    float m = fmaxf(v0, v1);
#pragma unroll
    for (int o = 16; o; o >>= 1) m = fmaxf(m, __shfl_xor_sync(0xffffffffu, m, o));
    float se = __expf(v0 - m) + (has1 ? __expf(v1 - m) : 0.f);
#pragma unroll
    for (int o = 16; o; o >>= 1) se += __shfl_xor_sync(0xffffffffu, se, o);
    float lse = logf(se) + m;

    y[(size_t)n * 40 + c0] = v0 - lse;
    if (has1) y[(size_t)n * 40 + c1] = v1 - lse;
}

// ---------------- host side --------------------------------------------------
extern "C" void kernel_launch(void* const* d_in, const int* in_sizes, int n_in,
                              void* d_out, int out_size)
{
    const float* x   = (const float*)d_in[0];
    const int*   ei  = (const int*)  d_in[1];
    const float* W1  = (const float*)d_in[2];
    const float* as1 = (const float*)d_in[3];
    const float* ad1 = (const float*)d_in[4];
    const float* b1  = (const float*)d_in[5];
    const float* W2  = (const float*)d_in[6];
    const float* as2 = (const float*)d_in[7];
    const float* ad2 = (const float*)d_in[8];
    const float* b2  = (const float*)d_in[9];
    float* y = (float*)d_out;

    const int N = in_sizes[0] / F1;
    const int E = in_sizes[1] / 2;
    const int* src = ei;
    const int* dst = ei + E;

    void* p;
    cudaGetSymbolAddress(&p, g_h1h);   __half* h1h = (__half*)p;
    cudaGetSymbolAddress(&p, g_h2h);   __half* h2h = (__half*)p;
    cudaGetSymbolAddress(&p, g_out1);  float* o1   = (float*)p;
    cudaGetSymbolAddress(&p, g_als1);  float* als1 = (float*)p;
    cudaGetSymbolAddress(&p, g_ald1);  float* ald1 = (float*)p;
    cudaGetSymbolAddress(&p, g_als2);  float* als2 = (float*)p;
    cudaGetSymbolAddress(&p, g_ald2);  float* ald2 = (float*)p;
    cudaGetSymbolAddress(&p, g_cnt);   int* cnt  = (int*)p;
    cudaGetSymbolAddress(&p, g_rowp);  int* rowp = (int*)p;
    cudaGetSymbolAddress(&p, g_col);   int* col  = (int*)p;
    cudaGetSymbolAddress(&p, g_state); ull* state = (ull*)p;
    cudaGetSymbolAddress(&p, g_ticket); int* ticket = (int*)p;
    int* cnt2 = cnt + MAXN;

    static cudaStream_t s2 = nullptr;
    static cudaEvent_t evFork = nullptr, evJoin = nullptr;
    if (!s2) {
        cudaStreamCreateWithFlags(&s2, cudaStreamNonBlocking);
        cudaEventCreateWithFlags(&evFork, cudaEventDisableTiming);
        cudaEventCreateWithFlags(&evJoin, cudaEventDisableTiming);
    }

    const int smem1 = (64 * F1 + 64 * 128) * sizeof(float);   // 64 KB
    const int smem2 = (64 * F2 + 64 * 128) * sizeof(float);   // 72 KB
    cudaFuncSetAttribute(gemm_k128<F1, false>,
                         cudaFuncAttributeMaxDynamicSharedMemorySize, smem1);
    cudaFuncSetAttribute(gemm_k128<F2, true>,
                         cudaFuncAttributeMaxDynamicSharedMemorySize, smem2);

    const int TB = 256;
    const int NB = (N + 511) / 512;   // 196 blocks, ticket-ordered lookback
    const int gemmBlocks   = (N + 63) / 64;
    const int nodeWBlocks  = (int)(((size_t)N * 32 + TB - 1) / TB);
    const int node2WBlocks = (int)((((size_t)(N + 1) / 2) * 32 + TB - 1) / TB);

    cudaMemsetAsync(cnt, 0, 2 * (size_t)MAXN * sizeof(int));
    cudaMemsetAsync(state, 0, 256 * sizeof(ull));
    cudaMemsetAsync(ticket, 0, sizeof(int));

    // fork: CSR build on s2 concurrent with gemm1
    cudaEventRecord(evFork, 0);
    cudaStreamWaitEvent(s2, evFork, 0);

    count_deg<<<(E + TB - 1) / TB, TB, 0, s2>>>(dst, cnt, E);
    scan_one<<<NB, 512, 0, s2>>>(cnt, rowp, state, ticket, N, E);
    fill_csr<<<(E + TB - 1) / TB, TB, 0, s2>>>(src, dst, rowp, cnt2, col, E);
    cudaEventRecord(evJoin, s2);

    // main stream: layer-1 GEMM (k3 — ncu samples this index)
    gemm_k128<F1, false><<<gemmBlocks, TB, smem1>>>(
        x, W1, nullptr, as1, ad1, h1h, als1, ald1, N);

    cudaStreamWaitEvent(0, evJoin, 0);

    aggregate_csr_128<<<node2WBlocks, TB>>>(rowp, col, als1, ald1, h1h, o1, N);

    gemm_k128<F2, true><<<gemmBlocks, TB, smem2>>>(
        o1, W2, b1, as2, ad2, h2h, als2, ald2, N);

    aggregate_csr_160_final<<<nodeWBlocks, TB>>>(rowp, col, als2, ald2, h2h, b2, y, N);
}

// round 11
// speedup vs baseline: 3.1416x; 1.1027x over previous
#include <cuda_runtime.h>
#include <cuda_fp16.h>
#include <math.h>
#include <stdint.h>

static constexpr int MAXN = 100000;
static constexpr int MAXE = 1600000;
static constexpr int F1   = 128;   // F_in and H*HID
static constexpr int F2   = 160;   // H*NCLS
static constexpr int NH   = 4;
static constexpr float NEG_SLOPE = 0.2f;

typedef unsigned long long ull;

// ---------------- scratch ----------------------------------------------------
__device__ ull   g_h1h [(size_t)MAXN * F1 / 4];   // fp16 h1, 128 halves/row
__device__ ull   g_h2h [(size_t)MAXN * F2 / 4];   // fp16 h2, 160 halves/row
__device__ float g_out1[(size_t)MAXN * F1];
__device__ float g_als1[(size_t)MAXN * NH];
__device__ float g_ald1[(size_t)MAXN * NH];
__device__ float g_als2[(size_t)MAXN * NH];
__device__ float g_ald2[(size_t)MAXN * NH];
__device__ int   g_cnt [2 * MAXN];
__device__ int   g_rowp[MAXN + 1];
__device__ int   g_col [MAXE];
__device__ ull   g_state[256];
__device__ int   g_ticket;

__device__ __forceinline__ float lrelu(float v) {
    return v > 0.f ? v : NEG_SLOPE * v;
}

__device__ __forceinline__ uint32_t f2tf32(float f) {
    uint32_t u;
    asm("cvt.rna.tf32.f32 %0, %1;" : "=r"(u) : "f"(f));
    return u;
}

__device__ __forceinline__ void mma_tf32(float& c0, float& c1, float& c2, float& c3,
                                         uint32_t a0, uint32_t a1, uint32_t a2, uint32_t a3,
                                         uint32_t b0, uint32_t b1) {
    asm volatile(
        "mma.sync.aligned.m16n8k8.row.col.f32.tf32.tf32.f32 "
        "{%0,%1,%2,%3}, {%4,%5,%6,%7}, {%8,%9}, {%0,%1,%2,%3};"
        : "+f"(c0), "+f"(c1), "+f"(c2), "+f"(c3)
        : "r"(a0), "r"(a1), "r"(a2), "r"(a3), "r"(b0), "r"(b1));
}

// ---------------- CSR build --------------------------------------------------
__global__ void count_deg(const int* __restrict__ dst, int* __restrict__ cnt, int E) {
    int e = blockIdx.x * blockDim.x + threadIdx.x;
    if (e < E) atomicAdd(&cnt[dst[e]], 1);
}

static constexpr ull FLG_AGG = 1ull << 62;
static constexpr ull FLG_PRE = 2ull << 62;

__global__ void scan_one(const int* __restrict__ cnt, int* __restrict__ rowp,
                         ull* __restrict__ state, int* __restrict__ ticket,
                         int N, int E)
{
    __shared__ int sm[512];
    __shared__ int sbid, sprefix;
    int t = threadIdx.x;
    if (t == 0) sbid = atomicAdd(ticket, 1);
    __syncthreads();
    int b = sbid;
    int i = b * 512 + t;
    int v = (i < N) ? cnt[i] : 0;
    sm[t] = v;
    __syncthreads();
    for (int o = 1; o < 512; o <<= 1) {
        int add = (t >= o) ? sm[t - o] : 0;
        __syncthreads();
        sm[t] += add;
        __syncthreads();
    }
    int incl  = sm[t];
    int total = sm[511];
    if (t == 0) {
        if (b == 0) {
            atomicExch(&state[0], FLG_PRE | (unsigned)total);
            sprefix = 0;
        } else {
            atomicExch(&state[b], FLG_AGG | (unsigned)total);
            int run = 0, j = b - 1;
            while (true) {
                ull s;
                do { s = atomicAdd(&state[j], 0ull); } while ((s >> 62) == 0);
                run += (int)(s & 0xffffffffu);
                if (s & FLG_PRE) break;
                --j;
            }
            atomicExch(&state[b], FLG_PRE | (unsigned)(run + total));
            sprefix = run;
        }
    }
    __syncthreads();
    if (i < N) rowp[i] = sprefix + incl - v;
    if (b == 0 && t == 0) rowp[N] = E;
}

__global__ void fill_csr(const int* __restrict__ src, const int* __restrict__ dst,
                         const int* __restrict__ rowp, int* __restrict__ cnt2,
                         int* __restrict__ col, int E) {
    int e = blockIdx.x * blockDim.x + threadIdx.x;
    if (e >= E) return;
    int d = __ldg(dst + e);
    int k = atomicAdd(&cnt2[d], 1);
    col[__ldg(rowp + d) + k] = __ldg(src + e);
}

// ---------------- GEMM via mma.sync tf32 (tensor pipe) -----------------------
// Block tile 64 rows x NOUT cols, 8 warps: 4 row-warps (16 rows) x 2 col-warps
// (NOUT/2 cols). W k-split into two 64-row halves. A stride 132, W stride
// NOUT+4 (conflict-free fragment LDS). fp16 output.
template<int NOUT, bool RELU_BIAS>
__global__ void __launch_bounds__(256, 3)
gemm_mma(const float* __restrict__ A,
         const float* __restrict__ W,
         const float* __restrict__ bias,
         __half* __restrict__ outh, int N)
{
    constexpr int SA_STRIDE = 132;
    constexpr int SW_STRIDE = NOUT + 4;
    constexpr int NTILE = NOUT / 16;            // n-tiles of 8 per warp (8 or 10)
    extern __shared__ uint32_t usmem[];
    uint32_t* sA = usmem;                       // 64 x 132
    uint32_t* sW = usmem + 64 * SA_STRIDE;      // 64 x (NOUT+4)

    const int tid  = threadIdx.x;
    const int warp = tid >> 5;
    const int lane = tid & 31;
    const int g    = lane >> 2;                 // groupID (0..7)
    const int tg   = lane & 3;                  // thread in group (0..3)
    const int warp_r = warp & 3;
    const int warp_c = warp >> 2;
    const int r0   = warp_r * 16;
    const int row0 = blockIdx.x * 64;
    const int nbase = warp_c * (NOUT / 2);

    // load A tile (once), fp32 -> tf32
    for (int i = tid; i < 64 * 128 / 4; i += 256) {
        int idx = i * 4;
        int r   = idx >> 7;
        int k   = idx & 127;
        int gr  = row0 + r;
        float4 v = make_float4(0.f, 0.f, 0.f, 0.f);
        if (gr < N) {
            v = *reinterpret_cast<const float4*>(A + (size_t)gr * 128 + k);
            if (RELU_BIAS) {
                v.x = fmaxf(v.x + bias[k + 0], 0.f);
                v.y = fmaxf(v.y + bias[k + 1], 0.f);
                v.z = fmaxf(v.z + bias[k + 2], 0.f);
                v.w = fmaxf(v.w + bias[k + 3], 0.f);
            }
        }
        uint32_t* d = sA + r * SA_STRIDE + k;
        d[0] = f2tf32(v.x); d[1] = f2tf32(v.y);
        d[2] = f2tf32(v.z); d[3] = f2tf32(v.w);
    }

    float c[NTILE][4];
#pragma unroll
    for (int j = 0; j < NTILE; ++j) {
        c[j][0] = 0.f; c[j][1] = 0.f; c[j][2] = 0.f; c[j][3] = 0.f;
    }

#pragma unroll
    for (int kh = 0; kh < 2; ++kh) {
        if (kh) __syncthreads();
        // load W k-half [kh*64, kh*64+64), fp32 -> tf32
        for (int i = tid; i < 64 * NOUT / 4; i += 256) {
            int idx = i * 4;
            int kk  = idx / NOUT;
            int cc  = idx % NOUT;
            float4 v = *reinterpret_cast<const float4*>(
                W + (size_t)(kh * 64 + kk) * NOUT + cc);
            uint32_t* d = sW + kk * SW_STRIDE + cc;
            d[0] = f2tf32(v.x); d[1] = f2tf32(v.y);
            d[2] = f2tf32(v.z); d[3] = f2tf32(v.w);
        }
        __syncthreads();

#pragma unroll
        for (int k8 = 0; k8 < 64; k8 += 8) {
            int kabs = kh * 64 + k8;
            uint32_t a0 = sA[(r0 + g)     * SA_STRIDE + kabs + tg];
            uint32_t a1 = sA[(r0 + g + 8) * SA_STRIDE + kabs + tg];
            uint32_t a2 = sA[(r0 + g)     * SA_STRIDE + kabs + tg + 4];
            uint32_t a3 = sA[(r0 + g + 8) * SA_STRIDE + kabs + tg + 4];
#pragma unroll
            for (int j = 0; j < NTILE; ++j) {
                int n0 = nbase + j * 8;
                uint32_t b0 = sW[(k8 + tg)     * SW_STRIDE + n0 + g];
                uint32_t b1 = sW[(k8 + tg + 4) * SW_STRIDE + n0 + g];
                mma_tf32(c[j][0], c[j][1], c[j][2], c[j][3],
                         a0, a1, a2, a3, b0, b1);
            }
        }
    }

    // store C as fp16 (half2 per fragment row)
    int rA = row0 + r0 + g;
    int rB = rA + 8;
#pragma unroll
    for (int j = 0; j < NTILE; ++j) {
        int colp = nbase + j * 8 + 2 * tg;
        if (rA < N)
            *reinterpret_cast<__half2*>(outh + (size_t)rA * NOUT + colp) =
                __floats2half2_rn(c[j][0], c[j][1]);
        if (rB < N)
            *reinterpret_cast<__half2*>(outh + (size_t)rB * NOUT + colp) =
                __floats2half2_rn(c[j][2], c[j][3]);
    }
}

// ---------------- attention coefficients from fp16 h -------------------------
// Layer 1 (128 cols, C=32): warp per node; lane covers cols {2l,2l+1} and
// {64+2l, 64+2l+1}; head boundary at lane 16; width-16 butterflies.
__global__ void attn_coef_128(const __half* __restrict__ Hh,
                              const float* __restrict__ a_s,
                              const float* __restrict__ a_d,
                              float* __restrict__ als,
                              float* __restrict__ ald, int N)
{
    int n    = (int)((blockIdx.x * (size_t)blockDim.x + threadIdx.x) >> 5);
    int lane = threadIdx.x & 31;
    if (n >= N) return;
    const __half* row = Hh + (size_t)n * 128;
    float2 hA = __half22float2(*reinterpret_cast<const __half2*>(row + 2 * lane));
    float2 hB = __half22float2(*reinterpret_cast<const __half2*>(row + 64 + 2 * lane));
    float2 sA = *reinterpret_cast<const float2*>(a_s + 2 * lane);
    float2 sB = *reinterpret_cast<const float2*>(a_s + 64 + 2 * lane);
    float2 dA = *reinterpret_cast<const float2*>(a_d + 2 * lane);
    float2 dB = *reinterpret_cast<const float2*>(a_d + 64 + 2 * lane);
    float vsA = hA.x * sA.x + hA.y * sA.y;
    float vdA = hA.x * dA.x + hA.y * dA.y;
    float vsB = hB.x * sB.x + hB.y * sB.y;
    float vdB = hB.x * dB.x + hB.y * dB.y;
#pragma unroll
    for (int o = 8; o; o >>= 1) {
        vsA += __shfl_xor_sync(0xffffffffu, vsA, o);
        vdA += __shfl_xor_sync(0xffffffffu, vdA, o);
        vsB += __shfl_xor_sync(0xffffffffu, vsB, o);
        vdB += __shfl_xor_sync(0xffffffffu, vdB, o);
    }
    if (lane == 0) {
        als[(size_t)n * 4 + 0] = vsA;
        ald[(size_t)n * 4 + 0] = vdA;
        als[(size_t)n * 4 + 2] = vsB;
        ald[(size_t)n * 4 + 2] = vdB;
    } else if (lane == 16) {
        als[(size_t)n * 4 + 1] = vsA;
        ald[(size_t)n * 4 + 1] = vdA;
        als[(size_t)n * 4 + 3] = vsB;
        ald[(size_t)n * 4 + 3] = vdB;
    }
}

// Layer 2 (160 cols, C=40): lane<20 loads 8 halves (cols 8l..8l+7, head=l/5);
// 4 masked accumulators, full-warp butterfly.
__global__ void attn_coef_160(const __half* __restrict__ Hh,
                              const float* __restrict__ a_s,
                              const float* __restrict__ a_d,
                              float* __restrict__ als,
                              float* __restrict__ ald, int N)
{
    int n    = (int)((blockIdx.x * (size_t)blockDim.x + threadIdx.x) >> 5);
    int lane = threadIdx.x & 31;
    if (n >= N) return;
    float ps = 0.f, pd = 0.f;
    int head = 0;
    if (lane < 20) {
        head = lane / 5;
        const __half* row = Hh + (size_t)n * 160 + lane * 8;
        uint4 u = *reinterpret_cast<const uint4*>(row);
        float2 f0 = __half22float2(*reinterpret_cast<__half2*>(&u.x));
        float2 f1 = __half22float2(*reinterpret_cast<__half2*>(&u.y));
        float2 f2 = __half22float2(*reinterpret_cast<__half2*>(&u.z));
        float2 f3 = __half22float2(*reinterpret_cast<__half2*>(&u.w));
        float4 s0 = *reinterpret_cast<const float4*>(a_s + lane * 8);
        float4 s1 = *reinterpret_cast<const float4*>(a_s + lane * 8 + 4);
        float4 d0 = *reinterpret_cast<const float4*>(a_d + lane * 8);
        float4 d1 = *reinterpret_cast<const float4*>(a_d + lane * 8 + 4);
        ps = f0.x * s0.x + f0.y * s0.y + f1.x * s0.z + f1.y * s0.w
           + f2.x * s1.x + f2.y * s1.y + f3.x * s1.z + f3.y * s1.w;
        pd = f0.x * d0.x + f0.y * d0.y + f1.x * d0.z + f1.y * d0.w
           + f2.x * d1.x + f2.y * d1.y + f3.x * d1.z + f3.y * d1.w;
    }
    float s0a = (head == 0) ? ps : 0.f, d0a = (head == 0) ? pd : 0.f;
    float s1a = (head == 1) ? ps : 0.f, d1a = (head == 1) ? pd : 0.f;
    float s2a = (head == 2) ? ps : 0.f, d2a = (head == 2) ? pd : 0.f;
    float s3a = (head == 3) ? ps : 0.f, d3a = (head == 3) ? pd : 0.f;
    if (lane >= 20) { s0a = d0a = s1a = d1a = s2a = d2a = s3a = d3a = 0.f; }
#pragma unroll
    for (int o = 16; o; o >>= 1) {
        s0a += __shfl_xor_sync(0xffffffffu, s0a, o);
        d0a += __shfl_xor_sync(0xffffffffu, d0a, o);
        s1a += __shfl_xor_sync(0xffffffffu, s1a, o);
        d1a += __shfl_xor_sync(0xffffffffu, d1a, o);
        s2a += __shfl_xor_sync(0xffffffffu, s2a, o);
        d2a += __shfl_xor_sync(0xffffffffu, d2a, o);
        s3a += __shfl_xor_sync(0xffffffffu, s3a, o);
        d3a += __shfl_xor_sync(0xffffffffu, d3a, o);
    }
    if (lane == 0) {
        als[(size_t)n * 4 + 0] = s0a; ald[(size_t)n * 4 + 0] = d0a;
        als[(size_t)n * 4 + 1] = s1a; ald[(size_t)n * 4 + 1] = d1a;
        als[(size_t)n * 4 + 2] = s2a; ald[(size_t)n * 4 + 2] = d2a;
        als[(size_t)n * 4 + 3] = s3a; ald[(size_t)n * 4 + 3] = d3a;
    }
}

// ---------------- layer-1 aggregation: 2 nodes per warp ----------------------
__device__ __forceinline__ void acc_h16x8(float4& p, float4& q, uint4 u, float e) {
    float2 f0 = __half22float2(*reinterpret_cast<__half2*>(&u.x));
    float2 f1 = __half22float2(*reinterpret_cast<__half2*>(&u.y));
    float2 f2 = __half22float2(*reinterpret_cast<__half2*>(&u.z));
    float2 f3 = __half22float2(*reinterpret_cast<__half2*>(&u.w));
    p.x = fmaf(e, f0.x, p.x); p.y = fmaf(e, f0.y, p.y);
    p.z = fmaf(e, f1.x, p.z); p.w = fmaf(e, f1.y, p.w);
    q.x = fmaf(e, f2.x, q.x); q.y = fmaf(e, f2.y, q.y);
    q.z = fmaf(e, f3.x, q.z); q.w = fmaf(e, f3.y, q.w);
}

__global__ void aggregate_csr_128(const int* __restrict__ rowp,
                                  const int* __restrict__ col,
                                  const float* __restrict__ als,
                                  const float* __restrict__ ald,
                                  const __half* __restrict__ Hh,
                                  float* __restrict__ outm, int N)
{
    int w    = (int)((blockIdx.x * (size_t)blockDim.x + threadIdx.x) >> 5);
    int lane = threadIdx.x & 31;
    int hw   = lane >> 4;
    int hl   = lane & 15;
    int n = w * 2 + hw;
    if (n >= N) return;
    int head = hl >> 2;
    float ald_h = __ldg(ald + (size_t)n * 4 + head);
    int beg = __ldg(rowp + n), end = __ldg(rowp + n + 1);

    float4 accP = make_float4(0.f, 0.f, 0.f, 0.f);
    float4 accQ = make_float4(0.f, 0.f, 0.f, 0.f);
    float den = 0.f;

    int i = beg;
    for (; i + 4 <= end; i += 4) {
        int s0 = __ldg(col + i),     s1 = __ldg(col + i + 1);
        int s2 = __ldg(col + i + 2), s3 = __ldg(col + i + 3);
        float al0 = __ldg(als + (size_t)s0 * 4 + head);
        float al1 = __ldg(als + (size_t)s1 * 4 + head);
        float al2 = __ldg(als + (size_t)s2 * 4 + head);
        float al3 = __ldg(als + (size_t)s3 * 4 + head);
        uint4 u0 = *reinterpret_cast<const uint4*>(Hh + (size_t)s0 * 128 + hl * 8);
        uint4 u1 = *reinterpret_cast<const uint4*>(Hh + (size_t)s1 * 128 + hl * 8);
        uint4 u2 = *reinterpret_cast<const uint4*>(Hh + (size_t)s2 * 128 + hl * 8);
        uint4 u3 = *reinterpret_cast<const uint4*>(Hh + (size_t)s3 * 128 + hl * 8);
        float e0 = __expf(lrelu(al0 + ald_h));
        float e1 = __expf(lrelu(al1 + ald_h));
        float e2 = __expf(lrelu(al2 + ald_h));
        float e3 = __expf(lrelu(al3 + ald_h));
        acc_h16x8(accP, accQ, u0, e0);
        acc_h16x8(accP, accQ, u1, e1);
        acc_h16x8(accP, accQ, u2, e2);
        acc_h16x8(accP, accQ, u3, e3);
        den += (e0 + e1) + (e2 + e3);
    }
    for (; i < end; ++i) {
        int s0 = __ldg(col + i);
        float e0 = __expf(lrelu(__ldg(als + (size_t)s0 * 4 + head) + ald_h));
        uint4 u0 = *reinterpret_cast<const uint4*>(Hh + (size_t)s0 * 128 + hl * 8);
        acc_h16x8(accP, accQ, u0, e0);
        den += e0;
    }
    float inv = 1.f / (den + 1e-16f);
    float* orow = outm + (size_t)n * 128 + hl * 8;
    *reinterpret_cast<float4*>(orow) =
        make_float4(accP.x * inv, accP.y * inv, accP.z * inv, accP.w * inv);
    *reinterpret_cast<float4*>(orow + 4) =
        make_float4(accQ.x * inv, accQ.y * inv, accQ.z * inv, accQ.w * inv);
}

// ---------------- layer-2 aggregation + head-mean + log_softmax --------------
__global__ void aggregate_csr_160_final(const int* __restrict__ rowp,
                                        const int* __restrict__ col,
                                        const float* __restrict__ als,
                                        const float* __restrict__ ald,
                                        const __half* __restrict__ Hh,
                                        const float* __restrict__ b2,
                                        float* __restrict__ y, int N)
{
    __shared__ __align__(16) float sbuf[8][160];
    int wid  = threadIdx.x >> 5;
    int n    = (int)((blockIdx.x * (size_t)blockDim.x + threadIdx.x) >> 5);
    int lane = threadIdx.x & 31;
    if (n >= N) return;
    bool act = (lane < 20);
    int head = act ? (lane / 5) : 0;
    float ald_h = __ldg(ald + (size_t)n * 4 + head);
    int beg = __ldg(rowp + n), end = __ldg(rowp + n + 1);

    float4 accP = make_float4(0.f, 0.f, 0.f, 0.f);
    float4 accQ = make_float4(0.f, 0.f, 0.f, 0.f);
    float den = 0.f;
    const uint4 uz = make_uint4(0u, 0u, 0u, 0u);

    int i = beg;
    for (; i + 4 <= end; i += 4) {
        int s0 = __ldg(col + i),     s1 = __ldg(col + i + 1);
        int s2 = __ldg(col + i + 2), s3 = __ldg(col + i + 3);
        float al0 = __ldg(als + (size_t)s0 * 4 + head);
        float al1 = __ldg(als + (size_t)s1 * 4 + head);
        float al2 = __ldg(als + (size_t)s2 * 4 + head);
        float al3 = __ldg(als + (size_t)s3 * 4 + head);
        uint4 u0 = act ? *reinterpret_cast<const uint4*>(Hh + (size_t)s0 * 160 + lane * 8) : uz;
        uint4 u1 = act ? *reinterpret_cast<const uint4*>(Hh + (size_t)s1 * 160 + lane * 8) : uz;
        uint4 u2 = act ? *reinterpret_cast<const uint4*>(Hh + (size_t)s2 * 160 + lane * 8) : uz;
        uint4 u3 = act ? *reinterpret_cast<const uint4*>(Hh + (size_t)s3 * 160 + lane * 8) : uz;
        float e0 = __expf(lrelu(al0 + ald_h));
        float e1 = __expf(lrelu(al1 + ald_h));
        float e2 = __expf(lrelu(al2 + ald_h));
        float e3 = __expf(lrelu(al3 + ald_h));
        acc_h16x8(accP, accQ, u0, e0);
        acc_h16x8(accP, accQ, u1, e1);
        acc_h16x8(accP, accQ, u2, e2);
        acc_h16x8(accP, accQ, u3, e3);
        den += (e0 + e1) + (e2 + e3);
    }
    for (; i < end; ++i) {
        int s0 = __ldg(col + i);
        float e0 = __expf(lrelu(__ldg(als + (size_t)s0 * 4 + head) + ald_h));
        uint4 u0 = act ? *reinterpret_cast<const uint4*>(Hh + (size_t)s0 * 160 + lane * 8) : uz;
        acc_h16x8(accP, accQ, u0, e0);
        den += e0;
    }
    float inv = 1.f / (den + 1e-16f);
    if (act) {
        *reinterpret_cast<float4*>(&sbuf[wid][lane * 8]) =
            make_float4(accP.x * inv, accP.y * inv, accP.z * inv, accP.w * inv);
        *reinterpret_cast<float4*>(&sbuf[wid][lane * 8 + 4]) =
            make_float4(accQ.x * inv, accQ.y * inv, accQ.z * inv, accQ.w * inv);
    }
    __syncwarp();

    const float* S = sbuf[wid];
    int c0 = lane;
    int c1 = lane + 32;
    bool has1 = (c1 < 40);

    float v0 = 0.25f * (S[c0] + S[40 + c0] + S[80 + c0] + S[120 + c0]) + __ldg(&b2[c0]);
    float v1 = -1e30f;
    if (has1)
        v1 = 0.25f * (S[c1] + S[40 + c1] + S[80 + c1] + S[120 + c1]) + __ldg(&b2[c1]);

    float m = fmaxf(v0, v1);
#pragma unroll
    for (int o = 16; o; o >>= 1) m = fmaxf(m, __shfl_xor_sync(0xffffffffu, m, o));
    float se = __expf(v0 - m) + (has1 ? __expf(v1 - m) : 0.f);
#pragma unroll
    for (int o = 16; o; o >>= 1) se += __shfl_xor_sync(0xffffffffu, se, o);
    float lse = logf(se) + m;

    y[(size_t)n * 40 + c0] = v0 - lse;
    if (has1) y[(size_t)n * 40 + c1] = v1 - lse;
}

// ---------------- host side --------------------------------------------------
extern "C" void kernel_launch(void* const* d_in, const int* in_sizes, int n_in,
                              void* d_out, int out_size)
{
    const float* x   = (const float*)d_in[0];
    const int*   ei  = (const int*)  d_in[1];
    const float* W1  = (const float*)d_in[2];
    const float* as1 = (const float*)d_in[3];
    const float* ad1 = (const float*)d_in[4];
    const float* b1  = (const float*)d_in[5];
    const float* W2  = (const float*)d_in[6];
    const float* as2 = (const float*)d_in[7];
    const float* ad2 = (const float*)d_in[8];
    const float* b2  = (const float*)d_in[9];
    float* y = (float*)d_out;

    const int N = in_sizes[0] / F1;
    const int E = in_sizes[1] / 2;
    const int* src = ei;
    const int* dst = ei + E;

    void* p;
    cudaGetSymbolAddress(&p, g_h1h);   __half* h1h = (__half*)p;
    cudaGetSymbolAddress(&p, g_h2h);   __half* h2h = (__half*)p;
    cudaGetSymbolAddress(&p, g_out1);  float* o1   = (float*)p;
    cudaGetSymbolAddress(&p, g_als1);  float* als1 = (float*)p;
    cudaGetSymbolAddress(&p, g_ald1);  float* ald1 = (float*)p;
    cudaGetSymbolAddress(&p, g_als2);  float* als2 = (float*)p;
    cudaGetSymbolAddress(&p, g_ald2);  float* ald2 = (float*)p;
    cudaGetSymbolAddress(&p, g_cnt);   int* cnt  = (int*)p;
    cudaGetSymbolAddress(&p, g_rowp);  int* rowp = (int*)p;
    cudaGetSymbolAddress(&p, g_col);   int* col  = (int*)p;
    cudaGetSymbolAddress(&p, g_state); ull* state = (ull*)p;
    cudaGetSymbolAddress(&p, g_ticket); int* ticket = (int*)p;
    int* cnt2 = cnt + MAXN;

    static cudaStream_t s2 = nullptr;
    static cudaEvent_t evFork = nullptr, evJoin = nullptr;
    if (!s2) {
        cudaStreamCreateWithFlags(&s2, cudaStreamNonBlocking);
        cudaEventCreateWithFlags(&evFork, cudaEventDisableTiming);
        cudaEventCreateWithFlags(&evJoin, cudaEventDisableTiming);
    }

    const int smem1 = (64 * 132 + 64 * (F1 + 4)) * 4;   // ~67.6 KB
    const int smem2 = (64 * 132 + 64 * (F2 + 4)) * 4;   // ~75.8 KB
    cudaFuncSetAttribute(gemm_mma<F1, false>,
                         cudaFuncAttributeMaxDynamicSharedMemorySize, smem1);
    cudaFuncSetAttribute(gemm_mma<F2, true>,
                         cudaFuncAttributeMaxDynamicSharedMemorySize, smem2);

    const int TB = 256;
    const int NB = (N + 511) / 512;
    const int gemmBlocks   = (N + 63) / 64;
    const int nodeWBlocks  = (int)(((size_t)N * 32 + TB - 1) / TB);
    const int node2WBlocks = (int)((((size_t)(N + 1) / 2) * 32 + TB - 1) / TB);

    cudaMemsetAsync(cnt, 0, 2 * (size_t)MAXN * sizeof(int));
    cudaMemsetAsync(state, 0, 256 * sizeof(ull));
    cudaMemsetAsync(ticket, 0, sizeof(int));

    // fork: CSR build on s2 concurrent with gemm1 + attn1
    cudaEventRecord(evFork, 0);
    cudaStreamWaitEvent(s2, evFork, 0);

    count_deg<<<(E + TB - 1) / TB, TB, 0, s2>>>(dst, cnt, E);
    scan_one<<<NB, 512, 0, s2>>>(cnt, rowp, state, ticket, N, E);
    fill_csr<<<(E + TB - 1) / TB, TB, 0, s2>>>(src, dst, rowp, cnt2, col, E);
    cudaEventRecord(evJoin, s2);

    // main stream: layer-1 GEMM (k3 — ncu samples this index)
    gemm_mma<F1, false><<<gemmBlocks, TB, smem1>>>(x, W1, nullptr, h1h, N);
    attn_coef_128<<<nodeWBlocks, TB>>>(h1h, as1, ad1, als1, ald1, N);

    cudaStreamWaitEvent(0, evJoin, 0);

    aggregate_csr_128<<<node2WBlocks, TB>>>(rowp, col, als1, ald1, h1h, o1, N);

    gemm_mma<F2, true><<<gemmBlocks, TB, smem2>>>(o1, W2, b1, h2h, N);
    attn_coef_160<<<nodeWBlocks, TB>>>(h2h, as2, ad2, als2, ald2, N);

    aggregate_csr_160_final<<<nodeWBlocks, TB>>>(rowp, col, als2, ald2, h2h, b2, y, N);
}

// round 12
// speedup vs baseline: 3.2231x; 1.0259x over previous
#include <cuda_runtime.h>
#include <cuda_fp16.h>
#include <math.h>
#include <stdint.h>

static constexpr int MAXN = 100000;
static constexpr int MAXE = 1600000;
static constexpr int F1   = 128;   // F_in and H*HID
static constexpr int F2   = 160;   // H*NCLS
static constexpr int NH   = 4;
static constexpr float NEG_SLOPE = 0.2f;

typedef unsigned long long ull;

// ---------------- scratch ----------------------------------------------------
__device__ ull   g_h1h [(size_t)MAXN * F1 / 4];   // fp16 h1, 128 halves/row
__device__ ull   g_h2h [(size_t)MAXN * F2 / 4];   // fp16 h2, 160 halves/row
__device__ float g_out1[(size_t)MAXN * F1];
__device__ float g_als1[(size_t)MAXN * NH];
__device__ float g_ald1[(size_t)MAXN * NH];
__device__ float g_als2[(size_t)MAXN * NH];
__device__ float g_ald2[(size_t)MAXN * NH];
__device__ int   g_cnt [2 * MAXN];
__device__ int   g_rowp[MAXN + 1];
__device__ int   g_col [MAXE];
__device__ ull   g_state[256];
__device__ int   g_ticket;

__device__ __forceinline__ float lrelu(float v) {
    return v > 0.f ? v : NEG_SLOPE * v;
}

__device__ __forceinline__ uint32_t f2tf32(float f) {
    uint32_t u;
    asm("cvt.rna.tf32.f32 %0, %1;" : "=r"(u) : "f"(f));
    return u;
}

__device__ __forceinline__ void mma_tf32(float& c0, float& c1, float& c2, float& c3,
                                         uint32_t a0, uint32_t a1, uint32_t a2, uint32_t a3,
                                         uint32_t b0, uint32_t b1) {
    asm volatile(
        "mma.sync.aligned.m16n8k8.row.col.f32.tf32.tf32.f32 "
        "{%0,%1,%2,%3}, {%4,%5,%6,%7}, {%8,%9}, {%0,%1,%2,%3};"
        : "+f"(c0), "+f"(c1), "+f"(c2), "+f"(c3)
        : "r"(a0), "r"(a1), "r"(a2), "r"(a3), "r"(b0), "r"(b1));
}

// ---------------- CSR build --------------------------------------------------
__global__ void count_deg(const int* __restrict__ dst, int* __restrict__ cnt, int E) {
    int e = blockIdx.x * blockDim.x + threadIdx.x;
    if (e < E) atomicAdd(&cnt[dst[e]], 1);
}

static constexpr ull FLG_AGG = 1ull << 62;
static constexpr ull FLG_PRE = 2ull << 62;

__global__ void scan_one(const int* __restrict__ cnt, int* __restrict__ rowp,
                         ull* __restrict__ state, int* __restrict__ ticket,
                         int N, int E)
{
    __shared__ int sm[512];
    __shared__ int sbid, sprefix;
    int t = threadIdx.x;
    if (t == 0) sbid = atomicAdd(ticket, 1);
    __syncthreads();
    int b = sbid;
    int i = b * 512 + t;
    int v = (i < N) ? cnt[i] : 0;
    sm[t] = v;
    __syncthreads();
    for (int o = 1; o < 512; o <<= 1) {
        int add = (t >= o) ? sm[t - o] : 0;
        __syncthreads();
        sm[t] += add;
        __syncthreads();
    }
    int incl  = sm[t];
    int total = sm[511];
    if (t == 0) {
        if (b == 0) {
            atomicExch(&state[0], FLG_PRE | (unsigned)total);
            sprefix = 0;
        } else {
            atomicExch(&state[b], FLG_AGG | (unsigned)total);
            int run = 0, j = b - 1;
            while (true) {
                ull s;
                do { s = atomicAdd(&state[j], 0ull); } while ((s >> 62) == 0);
                run += (int)(s & 0xffffffffu);
                if (s & FLG_PRE) break;
                --j;
            }
            atomicExch(&state[b], FLG_PRE | (unsigned)(run + total));
            sprefix = run;
        }
    }
    __syncthreads();
    if (i < N) rowp[i] = sprefix + incl - v;
    if (b == 0 && t == 0) rowp[N] = E;
}

__global__ void fill_csr(const int* __restrict__ src, const int* __restrict__ dst,
                         const int* __restrict__ rowp, int* __restrict__ cnt2,
                         int* __restrict__ col, int E) {
    int e = blockIdx.x * blockDim.x + threadIdx.x;
    if (e >= E) return;
    int d = __ldg(dst + e);
    int k = atomicAdd(&cnt2[d], 1);
    col[__ldg(rowp + d) + k] = __ldg(src + e);
}

// ---------------- GEMM via mma.sync tf32, fragment-packed smem ---------------
// Block tile 64 x NOUT, 8 warps: 4 row-warps x 2 col-warps. W k-split in two
// 64-row halves. A and W stored in smem pre-packed in fragment order so the
// mainloop uses only LDS.128: per k8, 1 A-load + JJ B-loads (2 n-tiles each).
// Lane rotation (+kb*5 / +jj*5) keeps consumer loads conflict-free and fill
// stores ~2-way.
template<int NOUT, bool RELU_BIAS>
__global__ void __launch_bounds__(256, 3)
gemm_mma(const float* __restrict__ A,
         const float* __restrict__ W,
         const float* __restrict__ bias,
         __half* __restrict__ outh, int N)
{
    constexpr int NTILE = NOUT / 16;   // n-tiles of 8 per col-warp (8 or 10)
    constexpr int JJ    = NOUT / 32;   // B quad-groups per col-warp (4 or 5)
    constexpr int A_U32 = 64 * 128;    // 8192
    extern __shared__ uint32_t usmem[];
    uint32_t* sA = usmem;              // fragment-packed A (full k=128)
    uint32_t* sW = usmem + A_U32;      // fragment-packed W (one k-half)

    const int tid  = threadIdx.x;
    const int warp = tid >> 5;
    const int lane = tid & 31;
    const int g    = lane >> 2;
    const int tg   = lane & 3;
    const int warp_r = warp & 3;
    const int warp_c = warp >> 2;
    const int r0   = warp_r * 16;
    const int row0 = blockIdx.x * 64;
    const int nbase = warp_c * (NOUT / 2);

    // ---- fill A (fragment-packed, tf32) ----
    for (int i = tid; i < 64 * 128 / 4; i += 256) {
        int idx = i * 4;
        int r   = idx >> 7;
        int k   = idx & 127;
        int gr  = row0 + r;
        float4 v = make_float4(0.f, 0.f, 0.f, 0.f);
        if (gr < N) {
            v = *reinterpret_cast<const float4*>(A + (size_t)gr * 128 + k);
            if (RELU_BIAS) {
                v.x = fmaxf(v.x + bias[k + 0], 0.f);
                v.y = fmaxf(v.y + bias[k + 1], 0.f);
                v.z = fmaxf(v.z + bias[k + 2], 0.f);
                v.w = fmaxf(v.w + bias[k + 3], 0.f);
            }
        }
        int rw    = r >> 4;
        int rr    = r & 15;
        int gq    = rr & 7;
        int rowhi = rr >> 3;
        int kb    = k >> 3;
        int khi   = (k >> 2) & 1;          // k%4==0 -> whole float4 same khi
        int slot  = khi * 2 + rowhi;
        uint32_t base = (uint32_t)(rw * 16 + kb) * 32;
        int lpb  = gq * 4 + kb * 5;
        float vv[4] = {v.x, v.y, v.z, v.w};
#pragma unroll
        for (int j = 0; j < 4; ++j)
            sA[(base + ((lpb + j) & 31)) * 4 + slot] = f2tf32(vv[j]);
    }

    float c[NTILE][4];
#pragma unroll
    for (int j = 0; j < NTILE; ++j) {
        c[j][0] = 0.f; c[j][1] = 0.f; c[j][2] = 0.f; c[j][3] = 0.f;
    }

#pragma unroll
    for (int kh = 0; kh < 2; ++kh) {
        if (kh) __syncthreads();
        // ---- fill W k-half (fragment-packed, tf32) ----
        for (int i = tid; i < 64 * NOUT / 4; i += 256) {
            int idx = i * 4;
            int kk  = idx / NOUT;
            int cc  = idx % NOUT;
            float4 v = *reinterpret_cast<const float4*>(
                W + (size_t)(kh * 64 + kk) * NOUT + cc);
            int kb  = kk >> 3;
            int km  = kk & 7;
            int tg2 = km & 3;
            int b01 = km >> 2;
            int wc  = cc / (NOUT / 2);
            int nn  = cc % (NOUT / 2);
            int jj  = nn >> 4;
            int rem = nn & 15;
            int jpar = rem >> 3;
            int gq  = rem & 7;                 // cc%4==0 -> gq in {0,4}
            int quad = jpar * 2 + b01;
            uint32_t base = (uint32_t)((kb * 2 + wc) * JJ + jj) * 32;
            float vv[4] = {v.x, v.y, v.z, v.w};
#pragma unroll
            for (int j = 0; j < 4; ++j) {
                int lp = ((gq + j) * 4 + tg2 + jj * 5) & 31;
                sW[(base + lp) * 4 + quad] = f2tf32(vv[j]);
            }
        }
        __syncthreads();

#pragma unroll
        for (int k8i = 0; k8i < 8; ++k8i) {
            int kb_abs = kh * 8 + k8i;
            int laneA = (lane + kb_abs * 5) & 31;
            uint4 av = *reinterpret_cast<uint4*>(
                sA + ((uint32_t)(warp_r * 16 + kb_abs) * 32 + laneA) * 4);
#pragma unroll
            for (int jj = 0; jj < JJ; ++jj) {
                int laneB = (lane + jj * 5) & 31;
                uint4 bv = *reinterpret_cast<uint4*>(
                    sW + ((uint32_t)((k8i * 2 + warp_c) * JJ + jj) * 32 + laneB) * 4);
                mma_tf32(c[2*jj][0], c[2*jj][1], c[2*jj][2], c[2*jj][3],
                         av.x, av.y, av.z, av.w, bv.x, bv.y);
                mma_tf32(c[2*jj+1][0], c[2*jj+1][1], c[2*jj+1][2], c[2*jj+1][3],
                         av.x, av.y, av.z, av.w, bv.z, bv.w);
            }
        }
    }

    // ---- store C as fp16 ----
    int rA = row0 + r0 + g;
    int rB = rA + 8;
#pragma unroll
    for (int j = 0; j < NTILE; ++j) {
        int colp = nbase + j * 8 + 2 * tg;
        if (rA < N)
            *reinterpret_cast<__half2*>(outh + (size_t)rA * NOUT + colp) =
                __floats2half2_rn(c[j][0], c[j][1]);
        if (rB < N)
            *reinterpret_cast<__half2*>(outh + (size_t)rB * NOUT + colp) =
                __floats2half2_rn(c[j][2], c[j][3]);
    }
}

// ---------------- attention coefficients from fp16 h -------------------------
__global__ void attn_coef_128(const __half* __restrict__ Hh,
                              const float* __restrict__ a_s,
                              const float* __restrict__ a_d,
                              float* __restrict__ als,
                              float* __restrict__ ald, int N)
{
    int n    = (int)((blockIdx.x * (size_t)blockDim.x + threadIdx.x) >> 5);
    int lane = threadIdx.x & 31;
    if (n >= N) return;
    const __half* row = Hh + (size_t)n * 128;
    float2 hA = __half22float2(*reinterpret_cast<const __half2*>(row + 2 * lane));
    float2 hB = __half22float2(*reinterpret_cast<const __half2*>(row + 64 + 2 * lane));
    float2 sA = *reinterpret_cast<const float2*>(a_s + 2 * lane);
    float2 sB = *reinterpret_cast<const float2*>(a_s + 64 + 2 * lane);
    float2 dA = *reinterpret_cast<const float2*>(a_d + 2 * lane);
    float2 dB = *reinterpret_cast<const float2*>(a_d + 64 + 2 * lane);
    float vsA = hA.x * sA.x + hA.y * sA.y;
    float vdA = hA.x * dA.x + hA.y * dA.y;
    float vsB = hB.x * sB.x + hB.y * sB.y;
    float vdB = hB.x * dB.x + hB.y * dB.y;
#pragma unroll
    for (int o = 8; o; o >>= 1) {
        vsA += __shfl_xor_sync(0xffffffffu, vsA, o);
        vdA += __shfl_xor_sync(0xffffffffu, vdA, o);
        vsB += __shfl_xor_sync(0xffffffffu, vsB, o);
        vdB += __shfl_xor_sync(0xffffffffu, vdB, o);
    }
    if (lane == 0) {
        als[(size_t)n * 4 + 0] = vsA;
        ald[(size_t)n * 4 + 0] = vdA;
        als[(size_t)n * 4 + 2] = vsB;
        ald[(size_t)n * 4 + 2] = vdB;
    } else if (lane == 16) {
        als[(size_t)n * 4 + 1] = vsA;
        ald[(size_t)n * 4 + 1] = vdA;
        als[(size_t)n * 4 + 3] = vsB;
        ald[(size_t)n * 4 + 3] = vdB;
    }
}

__global__ void attn_coef_160(const __half* __restrict__ Hh,
                              const float* __restrict__ a_s,
                              const float* __restrict__ a_d,
                              float* __restrict__ als,
                              float* __restrict__ ald, int N)
{
    int n    = (int)((blockIdx.x * (size_t)blockDim.x + threadIdx.x) >> 5);
    int lane = threadIdx.x & 31;
    if (n >= N) return;
    float ps = 0.f, pd = 0.f;
    int head = 0;
    if (lane < 20) {
        head = lane / 5;
        const __half* row = Hh + (size_t)n * 160 + lane * 8;
        uint4 u = *reinterpret_cast<const uint4*>(row);
        float2 f0 = __half22float2(*reinterpret_cast<__half2*>(&u.x));
        float2 f1 = __half22float2(*reinterpret_cast<__half2*>(&u.y));
        float2 f2 = __half22float2(*reinterpret_cast<__half2*>(&u.z));
        float2 f3 = __half22float2(*reinterpret_cast<__half2*>(&u.w));
        float4 s0 = *reinterpret_cast<const float4*>(a_s + lane * 8);
        float4 s1 = *reinterpret_cast<const float4*>(a_s + lane * 8 + 4);
        float4 d0 = *reinterpret_cast<const float4*>(a_d + lane * 8);
        float4 d1 = *reinterpret_cast<const float4*>(a_d + lane * 8 + 4);
        ps = f0.x * s0.x + f0.y * s0.y + f1.x * s0.z + f1.y * s0.w
           + f2.x * s1.x + f2.y * s1.y + f3.x * s1.z + f3.y * s1.w;
        pd = f0.x * d0.x + f0.y * d0.y + f1.x * d0.z + f1.y * d0.w
           + f2.x * d1.x + f2.y * d1.y + f3.x * d1.z + f3.y * d1.w;
    }
    float s0a = (head == 0) ? ps : 0.f, d0a = (head == 0) ? pd : 0.f;
    float s1a = (head == 1) ? ps : 0.f, d1a = (head == 1) ? pd : 0.f;
    float s2a = (head == 2) ? ps : 0.f, d2a = (head == 2) ? pd : 0.f;
    float s3a = (head == 3) ? ps : 0.f, d3a = (head == 3) ? pd : 0.f;
    if (lane >= 20) { s0a = d0a = s1a = d1a = s2a = d2a = s3a = d3a = 0.f; }
#pragma unroll
    for (int o = 16; o; o >>= 1) {
        s0a += __shfl_xor_sync(0xffffffffu, s0a, o);
        d0a += __shfl_xor_sync(0xffffffffu, d0a, o);
        s1a += __shfl_xor_sync(0xffffffffu, s1a, o);
        d1a += __shfl_xor_sync(0xffffffffu, d1a, o);
        s2a += __shfl_xor_sync(0xffffffffu, s2a, o);
        d2a += __shfl_xor_sync(0xffffffffu, d2a, o);
        s3a += __shfl_xor_sync(0xffffffffu, s3a, o);
        d3a += __shfl_xor_sync(0xffffffffu, d3a, o);
    }
    if (lane == 0) {
        als[(size_t)n * 4 + 0] = s0a; ald[(size_t)n * 4 + 0] = d0a;
        als[(size_t)n * 4 + 1] = s1a; ald[(size_t)n * 4 + 1] = d1a;
        als[(size_t)n * 4 + 2] = s2a; ald[(size_t)n * 4 + 2] = d2a;
        als[(size_t)n * 4 + 3] = s3a; ald[(size_t)n * 4 + 3] = d3a;
    }
}

// ---------------- layer-1 aggregation: 2 nodes per warp ----------------------
__device__ __forceinline__ void acc_h16x8(float4& p, float4& q, uint4 u, float e) {
    float2 f0 = __half22float2(*reinterpret_cast<__half2*>(&u.x));
    float2 f1 = __half22float2(*reinterpret_cast<__half2*>(&u.y));
    float2 f2 = __half22float2(*reinterpret_cast<__half2*>(&u.z));
    float2 f3 = __half22float2(*reinterpret_cast<__half2*>(&u.w));
    p.x = fmaf(e, f0.x, p.x); p.y = fmaf(e, f0.y, p.y);
    p.z = fmaf(e, f1.x, p.z); p.w = fmaf(e, f1.y, p.w);
    q.x = fmaf(e, f2.x, q.x); q.y = fmaf(e, f2.y, q.y);
    q.z = fmaf(e, f3.x, q.z); q.w = fmaf(e, f3.y, q.w);
}

__global__ void aggregate_csr_128(const int* __restrict__ rowp,
                                  const int* __restrict__ col,
                                  const float* __restrict__ als,
                                  const float* __restrict__ ald,
                                  const __half* __restrict__ Hh,
                                  float* __restrict__ outm, int N)
{
    int w    = (int)((blockIdx.x * (size_t)blockDim.x + threadIdx.x) >> 5);
    int lane = threadIdx.x & 31;
    int hw   = lane >> 4;
    int hl   = lane & 15;
    int n = w * 2 + hw;
    if (n >= N) return;
    int head = hl >> 2;
    float ald_h = __ldg(ald + (size_t)n * 4 + head);
    int beg = __ldg(rowp + n), end = __ldg(rowp + n + 1);

    float4 accP = make_float4(0.f, 0.f, 0.f, 0.f);
    float4 accQ = make_float4(0.f, 0.f, 0.f, 0.f);
    float den = 0.f;

    int i = beg;
    for (; i + 4 <= end; i += 4) {
        int s0 = __ldg(col + i),     s1 = __ldg(col + i + 1);
        int s2 = __ldg(col + i + 2), s3 = __ldg(col + i + 3);
        float al0 = __ldg(als + (size_t)s0 * 4 + head);
        float al1 = __ldg(als + (size_t)s1 * 4 + head);
        float al2 = __ldg(als + (size_t)s2 * 4 + head);
        float al3 = __ldg(als + (size_t)s3 * 4 + head);
        uint4 u0 = *reinterpret_cast<const uint4*>(Hh + (size_t)s0 * 128 + hl * 8);
        uint4 u1 = *reinterpret_cast<const uint4*>(Hh + (size_t)s1 * 128 + hl * 8);
        uint4 u2 = *reinterpret_cast<const uint4*>(Hh + (size_t)s2 * 128 + hl * 8);
        uint4 u3 = *reinterpret_cast<const uint4*>(Hh + (size_t)s3 * 128 + hl * 8);
        float e0 = __expf(lrelu(al0 + ald_h));
        float e1 = __expf(lrelu(al1 + ald_h));
        float e2 = __expf(lrelu(al2 + ald_h));
        float e3 = __expf(lrelu(al3 + ald_h));
        acc_h16x8(accP, accQ, u0, e0);
        acc_h16x8(accP, accQ, u1, e1);
        acc_h16x8(accP, accQ, u2, e2);
        acc_h16x8(accP, accQ, u3, e3);
        den += (e0 + e1) + (e2 + e3);
    }
    for (; i < end; ++i) {
        int s0 = __ldg(col + i);
        float e0 = __expf(lrelu(__ldg(als + (size_t)s0 * 4 + head) + ald_h));
        uint4 u0 = *reinterpret_cast<const uint4*>(Hh + (size_t)s0 * 128 + hl * 8);
        acc_h16x8(accP, accQ, u0, e0);
        den += e0;
    }
    float inv = 1.f / (den + 1e-16f);
    float* orow = outm + (size_t)n * 128 + hl * 8;
    *reinterpret_cast<float4*>(orow) =
        make_float4(accP.x * inv, accP.y * inv, accP.z * inv, accP.w * inv);
    *reinterpret_cast<float4*>(orow + 4) =
        make_float4(accQ.x * inv, accQ.y * inv, accQ.z * inv, accQ.w * inv);
}

// ---------------- layer-2 aggregation + head-mean + log_softmax --------------
__global__ void aggregate_csr_160_final(const int* __restrict__ rowp,
                                        const int* __restrict__ col,
                                        const float* __restrict__ als,
                                        const float* __restrict__ ald,
                                        const __half* __restrict__ Hh,
                                        const float* __restrict__ b2,
                                        float* __restrict__ y, int N)
{
    __shared__ __align__(16) float sbuf[8][160];
    int wid  = threadIdx.x >> 5;
    int n    = (int)((blockIdx.x * (size_t)blockDim.x + threadIdx.x) >> 5);
    int lane = threadIdx.x & 31;
    if (n >= N) return;
    bool act = (lane < 20);
    int head = act ? (lane / 5) : 0;
    float ald_h = __ldg(ald + (size_t)n * 4 + head);
    int beg = __ldg(rowp + n), end = __ldg(rowp + n + 1);

    float4 accP = make_float4(0.f, 0.f, 0.f, 0.f);
    float4 accQ = make_float4(0.f, 0.f, 0.f, 0.f);
    float den = 0.f;
    const uint4 uz = make_uint4(0u, 0u, 0u, 0u);

    int i = beg;
    for (; i + 4 <= end; i += 4) {
        int s0 = __ldg(col + i),     s1 = __ldg(col + i + 1);
        int s2 = __ldg(col + i + 2), s3 = __ldg(col + i + 3);
        float al0 = __ldg(als + (size_t)s0 * 4 + head);
        float al1 = __ldg(als + (size_t)s1 * 4 + head);
        float al2 = __ldg(als + (size_t)s2 * 4 + head);
        float al3 = __ldg(als + (size_t)s3 * 4 + head);
        uint4 u0 = act ? *reinterpret_cast<const uint4*>(Hh + (size_t)s0 * 160 + lane * 8) : uz;
        uint4 u1 = act ? *reinterpret_cast<const uint4*>(Hh + (size_t)s1 * 160 + lane * 8) : uz;
        uint4 u2 = act ? *reinterpret_cast<const uint4*>(Hh + (size_t)s2 * 160 + lane * 8) : uz;
        uint4 u3 = act ? *reinterpret_cast<const uint4*>(Hh + (size_t)s3 * 160 + lane * 8) : uz;
        float e0 = __expf(lrelu(al0 + ald_h));
        float e1 = __expf(lrelu(al1 + ald_h));
        float e2 = __expf(lrelu(al2 + ald_h));
        float e3 = __expf(lrelu(al3 + ald_h));
        acc_h16x8(accP, accQ, u0, e0);
        acc_h16x8(accP, accQ, u1, e1);
        acc_h16x8(accP, accQ, u2, e2);
        acc_h16x8(accP, accQ, u3, e3);
        den += (e0 + e1) + (e2 + e3);
    }
    for (; i < end; ++i) {
        int s0 = __ldg(col + i);
        float e0 = __expf(lrelu(__ldg(als + (size_t)s0 * 4 + head) + ald_h));
        uint4 u0 = act ? *reinterpret_cast<const uint4*>(Hh + (size_t)s0 * 160 + lane * 8) : uz;
        acc_h16x8(accP, accQ, u0, e0);
        den += e0;
    }
    float inv = 1.f / (den + 1e-16f);
    if (act) {
        *reinterpret_cast<float4*>(&sbuf[wid][lane * 8]) =
            make_float4(accP.x * inv, accP.y * inv, accP.z * inv, accP.w * inv);
        *reinterpret_cast<float4*>(&sbuf[wid][lane * 8 + 4]) =
            make_float4(accQ.x * inv, accQ.y * inv, accQ.z * inv, accQ.w * inv);
    }
    __syncwarp();

    const float* S = sbuf[wid];
    int c0 = lane;
    int c1 = lane + 32;
    bool has1 = (c1 < 40);

    float v0 = 0.25f * (S[c0] + S[40 + c0] + S[80 + c0] + S[120 + c0]) + __ldg(&b2[c0]);
    float v1 = -1e30f;
    if (has1)
        v1 = 0.25f * (S[c1] + S[40 + c1] + S[80 + c1] + S[120 + c1]) + __ldg(&b2[c1]);

    float m = fmaxf(v0, v1);
#pragma unroll
    for (int o = 16; o; o >>= 1) m = fmaxf(m, __shfl_xor_sync(0xffffffffu, m, o));
    float se = __expf(v0 - m) + (has1 ? __expf(v1 - m) : 0.f);
#pragma unroll
    for (int o = 16; o; o >>= 1) se += __shfl_xor_sync(0xffffffffu, se, o);
    float lse = logf(se) + m;

    y[(size_t)n * 40 + c0] = v0 - lse;
    if (has1) y[(size_t)n * 40 + c1] = v1 - lse;
}

// ---------------- host side --------------------------------------------------
extern "C" void kernel_launch(void* const* d_in, const int* in_sizes, int n_in,
                              void* d_out, int out_size)
{
    const float* x   = (const float*)d_in[0];
    const int*   ei  = (const int*)  d_in[1];
    const float* W1  = (const float*)d_in[2];
    const float* as1 = (const float*)d_in[3];
    const float* ad1 = (const float*)d_in[4];
    const float* b1  = (const float*)d_in[5];
    const float* W2  = (const float*)d_in[6];
    const float* as2 = (const float*)d_in[7];
    const float* ad2 = (const float*)d_in[8];
    const float* b2  = (const float*)d_in[9];
    float* y = (float*)d_out;

    const int N = in_sizes[0] / F1;
    const int E = in_sizes[1] / 2;
    const int* src = ei;
    const int* dst = ei + E;

    void* p;
    cudaGetSymbolAddress(&p, g_h1h);   __half* h1h = (__half*)p;
    cudaGetSymbolAddress(&p, g_h2h);   __half* h2h = (__half*)p;
    cudaGetSymbolAddress(&p, g_out1);  float* o1   = (float*)p;
    cudaGetSymbolAddress(&p, g_als1);  float* als1 = (float*)p;
    cudaGetSymbolAddress(&p, g_ald1);  float* ald1 = (float*)p;
    cudaGetSymbolAddress(&p, g_als2);  float* als2 = (float*)p;
    cudaGetSymbolAddress(&p, g_ald2);  float* ald2 = (float*)p;
    cudaGetSymbolAddress(&p, g_cnt);   int* cnt  = (int*)p;
    cudaGetSymbolAddress(&p, g_rowp);  int* rowp = (int*)p;
    cudaGetSymbolAddress(&p, g_col);   int* col  = (int*)p;
    cudaGetSymbolAddress(&p, g_state); ull* state = (ull*)p;
    cudaGetSymbolAddress(&p, g_ticket); int* ticket = (int*)p;
    int* cnt2 = cnt + MAXN;

    static cudaStream_t s2 = nullptr;
    static cudaEvent_t evFork = nullptr, evJoin = nullptr;
    if (!s2) {
        cudaStreamCreateWithFlags(&s2, cudaStreamNonBlocking);
        cudaEventCreateWithFlags(&evFork, cudaEventDisableTiming);
        cudaEventCreateWithFlags(&evJoin, cudaEventDisableTiming);
    }

    const int smem1 = (64 * 128 + 2048 * (F1 / 32)) * 4;   // 64 KB
    const int smem2 = (64 * 128 + 2048 * (F2 / 32)) * 4;   // 72 KB
    cudaFuncSetAttribute(gemm_mma<F1, false>,
                         cudaFuncAttributeMaxDynamicSharedMemorySize, smem1);
    cudaFuncSetAttribute(gemm_mma<F2, true>,
                         cudaFuncAttributeMaxDynamicSharedMemorySize, smem2);

    const int TB = 256;
    const int NB = (N + 511) / 512;
    const int gemmBlocks   = (N + 63) / 64;
    const int nodeWBlocks  = (int)(((size_t)N * 32 + TB - 1) / TB);
    const int node2WBlocks = (int)((((size_t)(N + 1) / 2) * 32 + TB - 1) / TB);

    cudaMemsetAsync(cnt, 0, 2 * (size_t)MAXN * sizeof(int));
    cudaMemsetAsync(state, 0, 256 * sizeof(ull));
    cudaMemsetAsync(ticket, 0, sizeof(int));

    // fork: CSR build on s2 concurrent with gemm1 + attn1
    cudaEventRecord(evFork, 0);
    cudaStreamWaitEvent(s2, evFork, 0);

    count_deg<<<(E + TB - 1) / TB, TB, 0, s2>>>(dst, cnt, E);
    scan_one<<<NB, 512, 0, s2>>>(cnt, rowp, state, ticket, N, E);
    fill_csr<<<(E + TB - 1) / TB, TB, 0, s2>>>(src, dst, rowp, cnt2, col, E);
    cudaEventRecord(evJoin, s2);

    // main stream: layer-1 GEMM (k3 — ncu samples this index)
    gemm_mma<F1, false><<<gemmBlocks, TB, smem1>>>(x, W1, nullptr, h1h, N);
    attn_coef_128<<<nodeWBlocks, TB>>>(h1h, as1, ad1, als1, ald1, N);

    cudaStreamWaitEvent(0, evJoin, 0);

    aggregate_csr_128<<<node2WBlocks, TB>>>(rowp, col, als1, ald1, h1h, o1, N);

    gemm_mma<F2, true><<<gemmBlocks, TB, smem2>>>(o1, W2, b1, h2h, N);
    attn_coef_160<<<nodeWBlocks, TB>>>(h2h, as2, ad2, als2, ald2, N);

    aggregate_csr_160_final<<<nodeWBlocks, TB>>>(rowp, col, als2, ald2, h2h, b2, y, N);
}

// round 13
// speedup vs baseline: 3.5138x; 1.0902x over previous
#include <cuda_runtime.h>
#include <cuda_fp16.h>
#include <math.h>
#include <stdint.h>

static constexpr int MAXN = 100000;
static constexpr int MAXE = 1600000;
static constexpr int F1   = 128;   // F_in and H*HID
static constexpr int F2   = 160;   // H*NCLS
static constexpr int NH   = 4;
static constexpr float NEG_SLOPE = 0.2f;

typedef unsigned long long ull;

// ---------------- scratch ----------------------------------------------------
__device__ ull   g_h1h [(size_t)MAXN * F1 / 4];   // fp16 h1
__device__ ull   g_h2h [(size_t)MAXN * F2 / 4];   // fp16 h2
__device__ float g_out1[(size_t)MAXN * F1];
__device__ float g_als1[(size_t)MAXN * NH];
__device__ float g_ald1[(size_t)MAXN * NH];
__device__ float g_als2[(size_t)MAXN * NH];
__device__ float g_ald2[(size_t)MAXN * NH];
__device__ int   g_cnt [2 * MAXN];
__device__ int   g_rowp[MAXN + 1];
__device__ int   g_col [MAXE];
__device__ ull   g_state[256];
__device__ int   g_ticket;
__device__ uint32_t g_wp1[128 * F1];   // fragment-packed tf32 W1
__device__ uint32_t g_wp2[128 * F2];   // fragment-packed tf32 W2

__device__ __forceinline__ float lrelu(float v) {
    return v > 0.f ? v : NEG_SLOPE * v;
}

__device__ __forceinline__ uint32_t f2tf32(float f) {
    uint32_t u;
    asm("cvt.rna.tf32.f32 %0, %1;" : "=r"(u) : "f"(f));
    return u;
}

__device__ __forceinline__ void mma_tf32(float& c0, float& c1, float& c2, float& c3,
                                         uint32_t a0, uint32_t a1, uint32_t a2, uint32_t a3,
                                         uint32_t b0, uint32_t b1) {
    asm volatile(
        "mma.sync.aligned.m16n8k8.row.col.f32.tf32.tf32.f32 "
        "{%0,%1,%2,%3}, {%4,%5,%6,%7}, {%8,%9}, {%0,%1,%2,%3};"
        : "+f"(c0), "+f"(c1), "+f"(c2), "+f"(c3)
        : "r"(a0), "r"(a1), "r"(a2), "r"(a3), "r"(b0), "r"(b1));
}

// ---------------- CSR build --------------------------------------------------
__global__ void count_deg(const int* __restrict__ dst, int* __restrict__ cnt, int E) {
    int e = blockIdx.x * blockDim.x + threadIdx.x;
    if (e < E) atomicAdd(&cnt[dst[e]], 1);
}

static constexpr ull FLG_AGG = 1ull << 62;
static constexpr ull FLG_PRE = 2ull << 62;

__global__ void scan_one(const int* __restrict__ cnt, int* __restrict__ rowp,
                         ull* __restrict__ state, int* __restrict__ ticket,
                         int N, int E)
{
    __shared__ int sm[512];
    __shared__ int sbid, sprefix;
    int t = threadIdx.x;
    if (t == 0) sbid = atomicAdd(ticket, 1);
    __syncthreads();
    int b = sbid;
    int i = b * 512 + t;
    int v = (i < N) ? cnt[i] : 0;
    sm[t] = v;
    __syncthreads();
    for (int o = 1; o < 512; o <<= 1) {
        int add = (t >= o) ? sm[t - o] : 0;
        __syncthreads();
        sm[t] += add;
        __syncthreads();
    }
    int incl  = sm[t];
    int total = sm[511];
    if (t == 0) {
        if (b == 0) {
            atomicExch(&state[0], FLG_PRE | (unsigned)total);
            sprefix = 0;
        } else {
            atomicExch(&state[b], FLG_AGG | (unsigned)total);
            int run = 0, j = b - 1;
            while (true) {
                ull s;
                do { s = atomicAdd(&state[j], 0ull); } while ((s >> 62) == 0);
                run += (int)(s & 0xffffffffu);
                if (s & FLG_PRE) break;
                --j;
            }
            atomicExch(&state[b], FLG_PRE | (unsigned)(run + total));
            sprefix = run;
        }
    }
    __syncthreads();
    if (i < N) rowp[i] = sprefix + incl - v;
    if (b == 0 && t == 0) rowp[N] = E;
}

__global__ void fill_csr(const int* __restrict__ src, const int* __restrict__ dst,
                         const int* __restrict__ rowp, int* __restrict__ cnt2,
                         int* __restrict__ col, int E) {
    int e = blockIdx.x * blockDim.x + threadIdx.x;
    if (e >= E) return;
    int d = __ldg(dst + e);
    int k = atomicAdd(&cnt2[d], 1);
    col[__ldg(rowp + d) + k] = __ldg(src + e);
}

// ---------------- one-shot W pack: row-major fp32 -> fragment-order tf32 -----
// Layout: idx = (((kb*2 + wc)*JJ + jj)*32 + lp)*4 + quad
//   kb = k/8, wc = col-warp, jj = n-quad-group, quad = jpar*2 + b01.
template<int NOUT>
__global__ void pack_w(const float* __restrict__ W, uint32_t* __restrict__ out)
{
    constexpr int JJ = NOUT / 32;
    int i = blockIdx.x * blockDim.x + threadIdx.x;
    if (i >= 128 * NOUT / 4) return;
    int idx = i * 4;
    int kk  = idx / NOUT;
    int cc  = idx % NOUT;
    float4 v = *reinterpret_cast<const float4*>(W + (size_t)kk * NOUT + cc);
    int kb  = kk >> 3;
    int km  = kk & 7;
    int tg2 = km & 3;
    int b01 = km >> 2;
    int wc  = cc / (NOUT / 2);
    int nn  = cc % (NOUT / 2);
    int jj  = nn >> 4;
    int rem = nn & 15;
    int jpar = rem >> 3;
    int gq  = rem & 7;
    int quad = jpar * 2 + b01;
    uint32_t base = (uint32_t)((kb * 2 + wc) * JJ + jj) * 32;
    float vv[4] = {v.x, v.y, v.z, v.w};
#pragma unroll
    for (int j = 0; j < 4; ++j) {
        int lp = ((gq + j) * 4 + tg2) & 31;
        out[(base + lp) * 4 + quad] = f2tf32(vv[j]);
    }
}

// ---------------- GEMM via mma.sync tf32, packed-W from global ---------------
// Block tile 64 x NOUT, 8 warps (4 row x 2 col). A fragment-packed in smem
// (32 KB); B fragments read directly from packed global buffer via LDG.128
// (L1-resident). Single pass over all 16 k-blocks, one __syncthreads.
template<int NOUT, bool RELU_BIAS>
__global__ void __launch_bounds__(256, 3)
gemm_mma(const float* __restrict__ A,
         const uint32_t* __restrict__ WP,
         const float* __restrict__ bias,
         __half* __restrict__ outh, int N)
{
    constexpr int NTILE = NOUT / 16;
    constexpr int JJ    = NOUT / 32;
    extern __shared__ uint32_t usmem[];
    uint32_t* sA = usmem;              // fragment-packed A (64 x 128)

    const int tid  = threadIdx.x;
    const int warp = tid >> 5;
    const int lane = tid & 31;
    const int g    = lane >> 2;
    const int tg   = lane & 3;
    const int warp_r = warp & 3;
    const int warp_c = warp >> 2;
    const int r0   = warp_r * 16;
    const int row0 = blockIdx.x * 64;
    const int nbase = warp_c * (NOUT / 2);

    // ---- fill A (fragment-packed, tf32) ----
    for (int i = tid; i < 64 * 128 / 4; i += 256) {
        int idx = i * 4;
        int r   = idx >> 7;
        int k   = idx & 127;
        int gr  = row0 + r;
        float4 v = make_float4(0.f, 0.f, 0.f, 0.f);
        if (gr < N) {
            v = *reinterpret_cast<const float4*>(A + (size_t)gr * 128 + k);
            if (RELU_BIAS) {
                v.x = fmaxf(v.x + bias[k + 0], 0.f);
                v.y = fmaxf(v.y + bias[k + 1], 0.f);
                v.z = fmaxf(v.z + bias[k + 2], 0.f);
                v.w = fmaxf(v.w + bias[k + 3], 0.f);
            }
        }
        int rw    = r >> 4;
        int rr    = r & 15;
        int gq    = rr & 7;
        int rowhi = rr >> 3;
        int kb    = k >> 3;
        int khi   = (k >> 2) & 1;
        int slot  = khi * 2 + rowhi;
        uint32_t base = (uint32_t)(rw * 16 + kb) * 32;
        int lpb  = gq * 4 + kb * 5;
        float vv[4] = {v.x, v.y, v.z, v.w};
#pragma unroll
        for (int j = 0; j < 4; ++j)
            sA[(base + ((lpb + j) & 31)) * 4 + slot] = f2tf32(vv[j]);
    }
    __syncthreads();

    float c[NTILE][4];
#pragma unroll
    for (int j = 0; j < NTILE; ++j) {
        c[j][0] = 0.f; c[j][1] = 0.f; c[j][2] = 0.f; c[j][3] = 0.f;
    }

    const uint4* wp4 = reinterpret_cast<const uint4*>(WP);

#pragma unroll
    for (int kb = 0; kb < 16; ++kb) {
        int laneA = (lane + kb * 5) & 31;
        uint4 av = *reinterpret_cast<uint4*>(
            sA + ((uint32_t)(warp_r * 16 + kb) * 32 + laneA) * 4);
        const uint4* wrow = wp4 + (uint32_t)((kb * 2 + warp_c) * JJ) * 32 + lane;
#pragma unroll
        for (int jj = 0; jj < JJ; ++jj) {
            uint4 bv = __ldg(wrow + jj * 32);
            mma_tf32(c[2*jj][0], c[2*jj][1], c[2*jj][2], c[2*jj][3],
                     av.x, av.y, av.z, av.w, bv.x, bv.y);
            mma_tf32(c[2*jj+1][0], c[2*jj+1][1], c[2*jj+1][2], c[2*jj+1][3],
                     av.x, av.y, av.z, av.w, bv.z, bv.w);
        }
    }

    // ---- store C as fp16 ----
    int rA = row0 + r0 + g;
    int rB = rA + 8;
#pragma unroll
    for (int j = 0; j < NTILE; ++j) {
        int colp = nbase + j * 8 + 2 * tg;
        if (rA < N)
            *reinterpret_cast<__half2*>(outh + (size_t)rA * NOUT + colp) =
                __floats2half2_rn(c[j][0], c[j][1]);
        if (rB < N)
            *reinterpret_cast<__half2*>(outh + (size_t)rB * NOUT + colp) =
                __floats2half2_rn(c[j][2], c[j][3]);
    }
}

// ---------------- attention coefficients from fp16 h -------------------------
__global__ void attn_coef_128(const __half* __restrict__ Hh,
                              const float* __restrict__ a_s,
                              const float* __restrict__ a_d,
                              float* __restrict__ als,
                              float* __restrict__ ald, int N)
{
    int n    = (int)((blockIdx.x * (size_t)blockDim.x + threadIdx.x) >> 5);
    int lane = threadIdx.x & 31;
    if (n >= N) return;
    const __half* row = Hh + (size_t)n * 128;
    float2 hA = __half22float2(*reinterpret_cast<const __half2*>(row + 2 * lane));
    float2 hB = __half22float2(*reinterpret_cast<const __half2*>(row + 64 + 2 * lane));
    float2 sA = *reinterpret_cast<const float2*>(a_s + 2 * lane);
    float2 sB = *reinterpret_cast<const float2*>(a_s + 64 + 2 * lane);
    float2 dA = *reinterpret_cast<const float2*>(a_d + 2 * lane);
    float2 dB = *reinterpret_cast<const float2*>(a_d + 64 + 2 * lane);
    float vsA = hA.x * sA.x + hA.y * sA.y;
    float vdA = hA.x * dA.x + hA.y * dA.y;
    float vsB = hB.x * sB.x + hB.y * sB.y;
    float vdB = hB.x * dB.x + hB.y * dB.y;
#pragma unroll
    for (int o = 8; o; o >>= 1) {
        vsA += __shfl_xor_sync(0xffffffffu, vsA, o);
        vdA += __shfl_xor_sync(0xffffffffu, vdA, o);
        vsB += __shfl_xor_sync(0xffffffffu, vsB, o);
        vdB += __shfl_xor_sync(0xffffffffu, vdB, o);
    }
    if (lane == 0) {
        als[(size_t)n * 4 + 0] = vsA;
        ald[(size_t)n * 4 + 0] = vdA;
        als[(size_t)n * 4 + 2] = vsB;
        ald[(size_t)n * 4 + 2] = vdB;
    } else if (lane == 16) {
        als[(size_t)n * 4 + 1] = vsA;
        ald[(size_t)n * 4 + 1] = vdA;
        als[(size_t)n * 4 + 3] = vsB;
        ald[(size_t)n * 4 + 3] = vdB;
    }
}

__global__ void attn_coef_160(const __half* __restrict__ Hh,
                              const float* __restrict__ a_s,
                              const float* __restrict__ a_d,
                              float* __restrict__ als,
                              float* __restrict__ ald, int N)
{
    int n    = (int)((blockIdx.x * (size_t)blockDim.x + threadIdx.x) >> 5);
    int lane = threadIdx.x & 31;
    if (n >= N) return;
    float ps = 0.f, pd = 0.f;
    int head = 0;
    if (lane < 20) {
        head = lane / 5;
        const __half* row = Hh + (size_t)n * 160 + lane * 8;
        uint4 u = *reinterpret_cast<const uint4*>(row);
        float2 f0 = __half22float2(*reinterpret_cast<__half2*>(&u.x));
        float2 f1 = __half22float2(*reinterpret_cast<__half2*>(&u.y));
        float2 f2 = __half22float2(*reinterpret_cast<__half2*>(&u.z));
        float2 f3 = __half22float2(*reinterpret_cast<__half2*>(&u.w));
        float4 s0 = *reinterpret_cast<const float4*>(a_s + lane * 8);
        float4 s1 = *reinterpret_cast<const float4*>(a_s + lane * 8 + 4);
        float4 d0 = *reinterpret_cast<const float4*>(a_d + lane * 8);
        float4 d1 = *reinterpret_cast<const float4*>(a_d + lane * 8 + 4);
        ps = f0.x * s0.x + f0.y * s0.y + f1.x * s0.z + f1.y * s0.w
           + f2.x * s1.x + f2.y * s1.y + f3.x * s1.z + f3.y * s1.w;
        pd = f0.x * d0.x + f0.y * d0.y + f1.x * d0.z + f1.y * d0.w
           + f2.x * d1.x + f2.y * d1.y + f3.x * d1.z + f3.y * d1.w;
    }
    float s0a = (head == 0) ? ps : 0.f, d0a = (head == 0) ? pd : 0.f;
    float s1a = (head == 1) ? ps : 0.f, d1a = (head == 1) ? pd : 0.f;
    float s2a = (head == 2) ? ps : 0.f, d2a = (head == 2) ? pd : 0.f;
    float s3a = (head == 3) ? ps : 0.f, d3a = (head == 3) ? pd : 0.f;
    if (lane >= 20) { s0a = d0a = s1a = d1a = s2a = d2a = s3a = d3a = 0.f; }
#pragma unroll
    for (int o = 16; o; o >>= 1) {
        s0a += __shfl_xor_sync(0xffffffffu, s0a, o);
        d0a += __shfl_xor_sync(0xffffffffu, d0a, o);
        s1a += __shfl_xor_sync(0xffffffffu, s1a, o);
        d1a += __shfl_xor_sync(0xffffffffu, d1a, o);
        s2a += __shfl_xor_sync(0xffffffffu, s2a, o);
        d2a += __shfl_xor_sync(0xffffffffu, d2a, o);
        s3a += __shfl_xor_sync(0xffffffffu, s3a, o);
        d3a += __shfl_xor_sync(0xffffffffu, d3a, o);
    }
    if (lane == 0) {
        als[(size_t)n * 4 + 0] = s0a; ald[(size_t)n * 4 + 0] = d0a;
        als[(size_t)n * 4 + 1] = s1a; ald[(size_t)n * 4 + 1] = d1a;
        als[(size_t)n * 4 + 2] = s2a; ald[(size_t)n * 4 + 2] = d2a;
        als[(size_t)n * 4 + 3] = s3a; ald[(size_t)n * 4 + 3] = d3a;
    }
}

// ---------------- layer-1 aggregation: 2 nodes per warp ----------------------
__device__ __forceinline__ void acc_h16x8(float4& p, float4& q, uint4 u, float e) {
    float2 f0 = __half22float2(*reinterpret_cast<__half2*>(&u.x));
    float2 f1 = __half22float2(*reinterpret_cast<__half2*>(&u.y));
    float2 f2 = __half22float2(*reinterpret_cast<__half2*>(&u.z));
    float2 f3 = __half22float2(*reinterpret_cast<__half2*>(&u.w));
    p.x = fmaf(e, f0.x, p.x); p.y = fmaf(e, f0.y, p.y);
    p.z = fmaf(e, f1.x, p.z); p.w = fmaf(e, f1.y, p.w);
    q.x = fmaf(e, f2.x, q.x); q.y = fmaf(e, f2.y, q.y);
    q.z = fmaf(e, f3.x, q.z); q.w = fmaf(e, f3.y, q.w);
}

__global__ void aggregate_csr_128(const int* __restrict__ rowp,
                                  const int* __restrict__ col,
                                  const float* __restrict__ als,
                                  const float* __restrict__ ald,
                                  const __half* __restrict__ Hh,
                                  float* __restrict__ outm, int N)
{
    int w    = (int)((blockIdx.x * (size_t)blockDim.x + threadIdx.x) >> 5);
    int lane = threadIdx.x & 31;
    int hw   = lane >> 4;
    int hl   = lane & 15;
    int n = w * 2 + hw;
    if (n >= N) return;
    int head = hl >> 2;
    float ald_h = __ldg(ald + (size_t)n * 4 + head);
    int beg = __ldg(rowp + n), end = __ldg(rowp + n + 1);

    float4 accP = make_float4(0.f, 0.f, 0.f, 0.f);
    float4 accQ = make_float4(0.f, 0.f, 0.f, 0.f);
    float den = 0.f;

    int i = beg;
    for (; i + 4 <= end; i += 4) {
        int s0 = __ldg(col + i),     s1 = __ldg(col + i + 1);
        int s2 = __ldg(col + i + 2), s3 = __ldg(col + i + 3);
        float al0 = __ldg(als + (size_t)s0 * 4 + head);
        float al1 = __ldg(als + (size_t)s1 * 4 + head);
        float al2 = __ldg(als + (size_t)s2 * 4 + head);
        float al3 = __ldg(als + (size_t)s3 * 4 + head);
        uint4 u0 = *reinterpret_cast<const uint4*>(Hh + (size_t)s0 * 128 + hl * 8);
        uint4 u1 = *reinterpret_cast<const uint4*>(Hh + (size_t)s1 * 128 + hl * 8);
        uint4 u2 = *reinterpret_cast<const uint4*>(Hh + (size_t)s2 * 128 + hl * 8);
        uint4 u3 = *reinterpret_cast<const uint4*>(Hh + (size_t)s3 * 128 + hl * 8);
        float e0 = __expf(lrelu(al0 + ald_h));
        float e1 = __expf(lrelu(al1 + ald_h));
        float e2 = __expf(lrelu(al2 + ald_h));
        float e3 = __expf(lrelu(al3 + ald_h));
        acc_h16x8(accP, accQ, u0, e0);
        acc_h16x8(accP, accQ, u1, e1);
        acc_h16x8(accP, accQ, u2, e2);
        acc_h16x8(accP, accQ, u3, e3);
        den += (e0 + e1) + (e2 + e3);
    }
    for (; i < end; ++i) {
        int s0 = __ldg(col + i);
        float e0 = __expf(lrelu(__ldg(als + (size_t)s0 * 4 + head) + ald_h));
        uint4 u0 = *reinterpret_cast<const uint4*>(Hh + (size_t)s0 * 128 + hl * 8);
        acc_h16x8(accP, accQ, u0, e0);
        den += e0;
    }
    float inv = 1.f / (den + 1e-16f);
    float* orow = outm + (size_t)n * 128 + hl * 8;
    *reinterpret_cast<float4*>(orow) =
        make_float4(accP.x * inv, accP.y * inv, accP.z * inv, accP.w * inv);
    *reinterpret_cast<float4*>(orow + 4) =
        make_float4(accQ.x * inv, accQ.y * inv, accQ.z * inv, accQ.w * inv);
}

// ---------------- layer-2 aggregation + head-mean + log_softmax --------------
__global__ void aggregate_csr_160_final(const int* __restrict__ rowp,
                                        const int* __restrict__ col,
                                        const float* __restrict__ als,
                                        const float* __restrict__ ald,
                                        const __half* __restrict__ Hh,
                                        const float* __restrict__ b2,
                                        float* __restrict__ y, int N)
{
    __shared__ __align__(16) float sbuf[8][160];
    int wid  = threadIdx.x >> 5;
    int n    = (int)((blockIdx.x * (size_t)blockDim.x + threadIdx.x) >> 5);
    int lane = threadIdx.x & 31;
    if (n >= N) return;
    bool act = (lane < 20);
    int head = act ? (lane / 5) : 0;
    float ald_h = __ldg(ald + (size_t)n * 4 + head);
    int beg = __ldg(rowp + n), end = __ldg(rowp + n + 1);

    float4 accP = make_float4(0.f, 0.f, 0.f, 0.f);
    float4 accQ = make_float4(0.f, 0.f, 0.f, 0.f);
    float den = 0.f;
    const uint4 uz = make_uint4(0u, 0u, 0u, 0u);

    int i = beg;
    for (; i + 4 <= end; i += 4) {
        int s0 = __ldg(col + i),     s1 = __ldg(col + i + 1);
        int s2 = __ldg(col + i + 2), s3 = __ldg(col + i + 3);
        float al0 = __ldg(als + (size_t)s0 * 4 + head);
        float al1 = __ldg(als + (size_t)s1 * 4 + head);
        float al2 = __ldg(als + (size_t)s2 * 4 + head);
        float al3 = __ldg(als + (size_t)s3 * 4 + head);
        uint4 u0 = act ? *reinterpret_cast<const uint4*>(Hh + (size_t)s0 * 160 + lane * 8) : uz;
        uint4 u1 = act ? *reinterpret_cast<const uint4*>(Hh + (size_t)s1 * 160 + lane * 8) : uz;
        uint4 u2 = act ? *reinterpret_cast<const uint4*>(Hh + (size_t)s2 * 160 + lane * 8) : uz;
        uint4 u3 = act ? *reinterpret_cast<const uint4*>(Hh + (size_t)s3 * 160 + lane * 8) : uz;
        float e0 = __expf(lrelu(al0 + ald_h));
        float e1 = __expf(lrelu(al1 + ald_h));
        float e2 = __expf(lrelu(al2 + ald_h));
        float e3 = __expf(lrelu(al3 + ald_h));
        acc_h16x8(accP, accQ, u0, e0);
        acc_h16x8(accP, accQ, u1, e1);
        acc_h16x8(accP, accQ, u2, e2);
        acc_h16x8(accP, accQ, u3, e3);
        den += (e0 + e1) + (e2 + e3);
    }
    for (; i < end; ++i) {
        int s0 = __ldg(col + i);
        float e0 = __expf(lrelu(__ldg(als + (size_t)s0 * 4 + head) + ald_h));
        uint4 u0 = act ? *reinterpret_cast<const uint4*>(Hh + (size_t)s0 * 160 + lane * 8) : uz;
        acc_h16x8(accP, accQ, u0, e0);
        den += e0;
    }
    float inv = 1.f / (den + 1e-16f);
    if (act) {
        *reinterpret_cast<float4*>(&sbuf[wid][lane * 8]) =
            make_float4(accP.x * inv, accP.y * inv, accP.z * inv, accP.w * inv);
        *reinterpret_cast<float4*>(&sbuf[wid][lane * 8 + 4]) =
            make_float4(accQ.x * inv, accQ.y * inv, accQ.z * inv, accQ.w * inv);
    }
    __syncwarp();

    const float* S = sbuf[wid];
    int c0 = lane;
    int c1 = lane + 32;
    bool has1 = (c1 < 40);

    float v0 = 0.25f * (S[c0] + S[40 + c0] + S[80 + c0] + S[120 + c0]) + __ldg(&b2[c0]);
    float v1 = -1e30f;
    if (has1)
        v1 = 0.25f * (S[c1] + S[40 + c1] + S[80 + c1] + S[120 + c1]) + __ldg(&b2[c1]);

    float m = fmaxf(v0, v1);
#pragma unroll
    for (int o = 16; o; o >>= 1) m = fmaxf(m, __shfl_xor_sync(0xffffffffu, m, o));
    float se = __expf(v0 - m) + (has1 ? __expf(v1 - m) : 0.f);
#pragma unroll
    for (int o = 16; o; o >>= 1) se += __shfl_xor_sync(0xffffffffu, se, o);
    float lse = logf(se) + m;

    y[(size_t)n * 40 + c0] = v0 - lse;
    if (has1) y[(size_t)n * 40 + c1] = v1 - lse;
}

// ---------------- host side --------------------------------------------------
extern "C" void kernel_launch(void* const* d_in, const int* in_sizes, int n_in,
                              void* d_out, int out_size)
{
    const float* x   = (const float*)d_in[0];
    const int*   ei  = (const int*)  d_in[1];
    const float* W1  = (const float*)d_in[2];
    const float* as1 = (const float*)d_in[3];
    const float* ad1 = (const float*)d_in[4];
    const float* b1  = (const float*)d_in[5];
    const float* W2  = (const float*)d_in[6];
    const float* as2 = (const float*)d_in[7];
    const float* ad2 = (const float*)d_in[8];
    const float* b2  = (const float*)d_in[9];
    float* y = (float*)d_out;

    const int N = in_sizes[0] / F1;
    const int E = in_sizes[1] / 2;
    const int* src = ei;
    const int* dst = ei + E;

    void* p;
    cudaGetSymbolAddress(&p, g_h1h);   __half* h1h = (__half*)p;
    cudaGetSymbolAddress(&p, g_h2h);   __half* h2h = (__half*)p;
    cudaGetSymbolAddress(&p, g_out1);  float* o1   = (float*)p;
    cudaGetSymbolAddress(&p, g_als1);  float* als1 = (float*)p;
    cudaGetSymbolAddress(&p, g_ald1);  float* ald1 = (float*)p;
    cudaGetSymbolAddress(&p, g_als2);  float* als2 = (float*)p;
    cudaGetSymbolAddress(&p, g_ald2);  float* ald2 = (float*)p;
    cudaGetSymbolAddress(&p, g_cnt);   int* cnt  = (int*)p;
    cudaGetSymbolAddress(&p, g_rowp);  int* rowp = (int*)p;
    cudaGetSymbolAddress(&p, g_col);   int* col  = (int*)p;
    cudaGetSymbolAddress(&p, g_state); ull* state = (ull*)p;
    cudaGetSymbolAddress(&p, g_ticket); int* ticket = (int*)p;
    cudaGetSymbolAddress(&p, g_wp1);   uint32_t* wp1 = (uint32_t*)p;
    cudaGetSymbolAddress(&p, g_wp2);   uint32_t* wp2 = (uint32_t*)p;
    int* cnt2 = cnt + MAXN;

    static cudaStream_t s2 = nullptr;
    static cudaEvent_t evFork = nullptr, evJoin = nullptr;
    if (!s2) {
        cudaStreamCreateWithFlags(&s2, cudaStreamNonBlocking);
        cudaEventCreateWithFlags(&evFork, cudaEventDisableTiming);
        cudaEventCreateWithFlags(&evJoin, cudaEventDisableTiming);
    }

    const int smem = 64 * 128 * 4;     // 32 KB (A only)
    cudaFuncSetAttribute(gemm_mma<F1, false>,
                         cudaFuncAttributeMaxDynamicSharedMemorySize, smem);
    cudaFuncSetAttribute(gemm_mma<F2, true>,
                         cudaFuncAttributeMaxDynamicSharedMemorySize, smem);

    const int TB = 256;
    const int NB = (N + 511) / 512;
    const int gemmBlocks   = (N + 63) / 64;
    const int nodeWBlocks  = (int)(((size_t)N * 32 + TB - 1) / TB);
    const int node2WBlocks = (int)((((size_t)(N + 1) / 2) * 32 + TB - 1) / TB);

    cudaMemsetAsync(cnt, 0, 2 * (size_t)MAXN * sizeof(int));
    cudaMemsetAsync(state, 0, 256 * sizeof(ull));
    cudaMemsetAsync(ticket, 0, sizeof(int));

    // fork: CSR build on s2 concurrent with W-pack + gemm1 + attn1
    cudaEventRecord(evFork, 0);
    cudaStreamWaitEvent(s2, evFork, 0);

    count_deg<<<(E + TB - 1) / TB, TB, 0, s2>>>(dst, cnt, E);
    scan_one<<<NB, 512, 0, s2>>>(cnt, rowp, state, ticket, N, E);
    fill_csr<<<(E + TB - 1) / TB, TB, 0, s2>>>(src, dst, rowp, cnt2, col, E);
    cudaEventRecord(evJoin, s2);

    // main stream: pack both W matrices (tiny, one-shot)
    pack_w<F1><<<(128 * F1 / 4 + TB - 1) / TB, TB>>>(W1, wp1);
    pack_w<F2><<<(128 * F2 / 4 + TB - 1) / TB, TB>>>(W2, wp2);

    // layer-1 GEMM (launch idx 5 — ncu samples this)
    gemm_mma<F1, false><<<gemmBlocks, TB, smem>>>(x, wp1, nullptr, h1h, N);
    attn_coef_128<<<nodeWBlocks, TB>>>(h1h, as1, ad1, als1, ald1, N);

    cudaStreamWaitEvent(0, evJoin, 0);

    aggregate_csr_128<<<node2WBlocks, TB>>>(rowp, col, als1, ald1, h1h, o1, N);

    gemm_mma<F2, true><<<gemmBlocks, TB, smem>>>(o1, wp2, b1, h2h, N);
    attn_coef_160<<<nodeWBlocks, TB>>>(h2h, as2, ad2, als2, ald2, N);

    aggregate_csr_160_final<<<nodeWBlocks, TB>>>(rowp, col, als2, ald2, h2h, b2, y, N);
}

// round 14
// speedup vs baseline: 3.6747x; 1.0458x over previous
#include <cuda_runtime.h>
#include <cuda_fp16.h>
#include <math.h>
#include <stdint.h>

static constexpr int MAXN = 100000;
static constexpr int MAXE = 1600000;
static constexpr int F1   = 128;   // F_in and H*HID
static constexpr int F2   = 160;   // H*NCLS
static constexpr int NH   = 4;
static constexpr float NEG_SLOPE = 0.2f;

typedef unsigned long long ull;

// ---------------- scratch ----------------------------------------------------
__device__ ull   g_h1h [(size_t)MAXN * F1 / 4];   // fp16 h1
__device__ ull   g_h2h [(size_t)MAXN * F2 / 4];   // fp16 h2
__device__ float g_out1[(size_t)MAXN * F1];
__device__ float g_als1[(size_t)MAXN * NH];
__device__ float g_ald1[(size_t)MAXN * NH];
__device__ float g_als2[(size_t)MAXN * NH];
__device__ float g_ald2[(size_t)MAXN * NH];
__device__ int   g_cnt [2 * MAXN];
__device__ int   g_rowp[MAXN + 1];
__device__ int   g_col [MAXE];
__device__ ull   g_state[256];
__device__ int   g_ticket;
__device__ uint32_t g_wp1[128 * F1];   // fragment-packed tf32 W1
__device__ uint32_t g_wp2[128 * F2];   // fragment-packed tf32 W2

__device__ __forceinline__ float lrelu(float v) {
    return v > 0.f ? v : NEG_SLOPE * v;
}

__device__ __forceinline__ uint32_t f2tf32(float f) {
    uint32_t u;
    asm("cvt.rna.tf32.f32 %0, %1;" : "=r"(u) : "f"(f));
    return u;
}

__device__ __forceinline__ void mma_tf32(float& c0, float& c1, float& c2, float& c3,
                                         uint32_t a0, uint32_t a1, uint32_t a2, uint32_t a3,
                                         uint32_t b0, uint32_t b1) {
    asm volatile(
        "mma.sync.aligned.m16n8k8.row.col.f32.tf32.tf32.f32 "
        "{%0,%1,%2,%3}, {%4,%5,%6,%7}, {%8,%9}, {%0,%1,%2,%3};"
        : "+f"(c0), "+f"(c1), "+f"(c2), "+f"(c3)
        : "r"(a0), "r"(a1), "r"(a2), "r"(a3), "r"(b0), "r"(b1));
}

// ---------------- CSR build --------------------------------------------------
__global__ void count_deg(const int* __restrict__ dst, int* __restrict__ cnt, int E) {
    int e = blockIdx.x * blockDim.x + threadIdx.x;
    if (e < E) atomicAdd(&cnt[dst[e]], 1);
}

static constexpr ull FLG_AGG = 1ull << 62;
static constexpr ull FLG_PRE = 2ull << 62;

__global__ void scan_one(const int* __restrict__ cnt, int* __restrict__ rowp,
                         ull* __restrict__ state, int* __restrict__ ticket,
                         int N, int E)
{
    __shared__ int sm[512];
    __shared__ int sbid, sprefix;
    int t = threadIdx.x;
    if (t == 0) sbid = atomicAdd(ticket, 1);
    __syncthreads();
    int b = sbid;
    int i = b * 512 + t;
    int v = (i < N) ? cnt[i] : 0;
    sm[t] = v;
    __syncthreads();
    for (int o = 1; o < 512; o <<= 1) {
        int add = (t >= o) ? sm[t - o] : 0;
        __syncthreads();
        sm[t] += add;
        __syncthreads();
    }
    int incl  = sm[t];
    int total = sm[511];
    if (t == 0) {
        if (b == 0) {
            atomicExch(&state[0], FLG_PRE | (unsigned)total);
            sprefix = 0;
        } else {
            atomicExch(&state[b], FLG_AGG | (unsigned)total);
            int run = 0, j = b - 1;
            while (true) {
                ull s;
                do { s = atomicAdd(&state[j], 0ull); } while ((s >> 62) == 0);
                run += (int)(s & 0xffffffffu);
                if (s & FLG_PRE) break;
                --j;
            }
            atomicExch(&state[b], FLG_PRE | (unsigned)(run + total));
            sprefix = run;
        }
    }
    __syncthreads();
    if (i < N) rowp[i] = sprefix + incl - v;
    if (b == 0 && t == 0) rowp[N] = E;
}

__global__ void fill_csr(const int* __restrict__ src, const int* __restrict__ dst,
                         const int* __restrict__ rowp, int* __restrict__ cnt2,
                         int* __restrict__ col, int E) {
    int e = blockIdx.x * blockDim.x + threadIdx.x;
    if (e >= E) return;
    int d = __ldg(dst + e);
    int k = atomicAdd(&cnt2[d], 1);
    col[__ldg(rowp + d) + k] = __ldg(src + e);
}

// ---------------- one-shot W pack --------------------------------------------
template<int NOUT>
__global__ void pack_w(const float* __restrict__ W, uint32_t* __restrict__ out)
{
    constexpr int JJ = NOUT / 32;
    int i = blockIdx.x * blockDim.x + threadIdx.x;
    if (i >= 128 * NOUT / 4) return;
    int idx = i * 4;
    int kk  = idx / NOUT;
    int cc  = idx % NOUT;
    float4 v = *reinterpret_cast<const float4*>(W + (size_t)kk * NOUT + cc);
    int kb  = kk >> 3;
    int km  = kk & 7;
    int tg2 = km & 3;
    int b01 = km >> 2;
    int wc  = cc / (NOUT / 2);
    int nn  = cc % (NOUT / 2);
    int jj  = nn >> 4;
    int rem = nn & 15;
    int jpar = rem >> 3;
    int gq  = rem & 7;
    int quad = jpar * 2 + b01;
    uint32_t base = (uint32_t)((kb * 2 + wc) * JJ + jj) * 32;
    float vv[4] = {v.x, v.y, v.z, v.w};
#pragma unroll
    for (int j = 0; j < 4; ++j) {
        int lp = ((gq + j) * 4 + tg2) & 31;
        out[(base + lp) * 4 + quad] = f2tf32(vv[j]);
    }
}

// ---------------- GEMM (mma.sync tf32) + fused attention epilogue ------------
// A fragment-packed in smem (32 KB) + 2 KB attn-partial table. B fragments
// from packed global (L1-resident LDG.128). Epilogue reduces attention dots
// per (row, head) via smem atomics; block writes als/ald directly.
template<int NOUT, bool RELU_BIAS>
__global__ void __launch_bounds__(256, 3)
gemm_mma(const float* __restrict__ A,
         const uint32_t* __restrict__ WP,
         const float* __restrict__ bias,
         const float* __restrict__ a_s,
         const float* __restrict__ a_d,
         __half* __restrict__ outh,
         float* __restrict__ als,
         float* __restrict__ ald, int N)
{
    constexpr int NTILE = NOUT / 16;
    constexpr int JJ    = NOUT / 32;
    constexpr int HALF  = NTILE / 2;   // j-count per head within a col-warp
    extern __shared__ uint32_t usmem[];
    uint32_t* sA   = usmem;            // fragment-packed A (64 x 128)
    float*    sAls = reinterpret_cast<float*>(usmem + 64 * 128);        // [64][4]
    float*    sAld = sAls + 256;                                         // [64][4]

    const int tid  = threadIdx.x;
    const int warp = tid >> 5;
    const int lane = tid & 31;
    const int g    = lane >> 2;
    const int tg   = lane & 3;
    const int warp_r = warp & 3;
    const int warp_c = warp >> 2;
    const int r0   = warp_r * 16;
    const int row0 = blockIdx.x * 64;
    const int nbase = warp_c * (NOUT / 2);

    // ---- zero attn partials + fill A (fragment-packed, tf32) ----
    for (int i = tid; i < 512; i += 256) { sAls[i] = 0.f; }  // covers sAls+sAld
    for (int i = tid; i < 64 * 128 / 4; i += 256) {
        int idx = i * 4;
        int r   = idx >> 7;
        int k   = idx & 127;
        int gr  = row0 + r;
        float4 v = make_float4(0.f, 0.f, 0.f, 0.f);
        if (gr < N) {
            v = *reinterpret_cast<const float4*>(A + (size_t)gr * 128 + k);
            if (RELU_BIAS) {
                v.x = fmaxf(v.x + bias[k + 0], 0.f);
                v.y = fmaxf(v.y + bias[k + 1], 0.f);
                v.z = fmaxf(v.z + bias[k + 2], 0.f);
                v.w = fmaxf(v.w + bias[k + 3], 0.f);
            }
        }
        int rw    = r >> 4;
        int rr    = r & 15;
        int gq    = rr & 7;
        int rowhi = rr >> 3;
        int kb    = k >> 3;
        int khi   = (k >> 2) & 1;
        int slot  = khi * 2 + rowhi;
        uint32_t base = (uint32_t)(rw * 16 + kb) * 32;
        int lpb  = gq * 4 + kb * 5;
        float vv[4] = {v.x, v.y, v.z, v.w};
#pragma unroll
        for (int j = 0; j < 4; ++j)
            sA[(base + ((lpb + j) & 31)) * 4 + slot] = f2tf32(vv[j]);
    }
    __syncthreads();

    float c[NTILE][4];
#pragma unroll
    for (int j = 0; j < NTILE; ++j) {
        c[j][0] = 0.f; c[j][1] = 0.f; c[j][2] = 0.f; c[j][3] = 0.f;
    }

    const uint4* wp4 = reinterpret_cast<const uint4*>(WP);

#pragma unroll
    for (int kb = 0; kb < 16; ++kb) {
        int laneA = (lane + kb * 5) & 31;
        uint4 av = *reinterpret_cast<uint4*>(
            sA + ((uint32_t)(warp_r * 16 + kb) * 32 + laneA) * 4);
        const uint4* wrow = wp4 + (uint32_t)((kb * 2 + warp_c) * JJ) * 32 + lane;
#pragma unroll
        for (int jj = 0; jj < JJ; ++jj) {
            uint4 bv = __ldg(wrow + jj * 32);
            mma_tf32(c[2*jj][0], c[2*jj][1], c[2*jj][2], c[2*jj][3],
                     av.x, av.y, av.z, av.w, bv.x, bv.y);
            mma_tf32(c[2*jj+1][0], c[2*jj+1][1], c[2*jj+1][2], c[2*jj+1][3],
                     av.x, av.y, av.z, av.w, bv.z, bv.w);
        }
    }

    // ---- store C as fp16 + accumulate attention partials ----
    int rA = row0 + r0 + g;
    int rB = rA + 8;
    float pa[2][2] = {{0.f, 0.f}, {0.f, 0.f}};   // [head-in-warp][row A/B]  (a_s)
    float pd[2][2] = {{0.f, 0.f}, {0.f, 0.f}};   // (a_d)
#pragma unroll
    for (int j = 0; j < NTILE; ++j) {
        int colp = nbase + j * 8 + 2 * tg;
        if (rA < N)
            *reinterpret_cast<__half2*>(outh + (size_t)rA * NOUT + colp) =
                __floats2half2_rn(c[j][0], c[j][1]);
        if (rB < N)
            *reinterpret_cast<__half2*>(outh + (size_t)rB * NOUT + colp) =
                __floats2half2_rn(c[j][2], c[j][3]);
        float2 asv = __ldg(reinterpret_cast<const float2*>(a_s + colp));
        float2 adv = __ldg(reinterpret_cast<const float2*>(a_d + colp));
        int hsel = j / HALF;   // compile-time per j
        pa[hsel][0] += c[j][0] * asv.x + c[j][1] * asv.y;
        pa[hsel][1] += c[j][2] * asv.x + c[j][3] * asv.y;
        pd[hsel][0] += c[j][0] * adv.x + c[j][1] * adv.y;
        pd[hsel][1] += c[j][2] * adv.x + c[j][3] * adv.y;
    }
    int raL = r0 + g;
    int rbL = raL + 8;
    int h0 = 2 * warp_c;
#pragma unroll
    for (int hs = 0; hs < 2; ++hs) {
        atomicAdd(&sAls[raL * 4 + h0 + hs], pa[hs][0]);
        atomicAdd(&sAls[rbL * 4 + h0 + hs], pa[hs][1]);
        atomicAdd(&sAld[raL * 4 + h0 + hs], pd[hs][0]);
        atomicAdd(&sAld[rbL * 4 + h0 + hs], pd[hs][1]);
    }
    __syncthreads();

    // write als/ald (64 rows x 4 heads = 256 floats each)
    if (tid < 256) {
        int r = tid >> 2;
        int gr = row0 + r;
        if (gr < N) {
            als[(size_t)gr * 4 + (tid & 3)] = sAls[tid];
            ald[(size_t)gr * 4 + (tid & 3)] = sAld[tid];
        }
    }
}

// ---------------- layer-1 aggregation: 2 nodes per warp ----------------------
__device__ __forceinline__ void acc_h16x8(float4& p, float4& q, uint4 u, float e) {
    float2 f0 = __half22float2(*reinterpret_cast<__half2*>(&u.x));
    float2 f1 = __half22float2(*reinterpret_cast<__half2*>(&u.y));
    float2 f2 = __half22float2(*reinterpret_cast<__half2*>(&u.z));
    float2 f3 = __half22float2(*reinterpret_cast<__half2*>(&u.w));
    p.x = fmaf(e, f0.x, p.x); p.y = fmaf(e, f0.y, p.y);
    p.z = fmaf(e, f1.x, p.z); p.w = fmaf(e, f1.y, p.w);
    q.x = fmaf(e, f2.x, q.x); q.y = fmaf(e, f2.y, q.y);
    q.z = fmaf(e, f3.x, q.z); q.w = fmaf(e, f3.y, q.w);
}

__global__ void aggregate_csr_128(const int* __restrict__ rowp,
                                  const int* __restrict__ col,
                                  const float* __restrict__ als,
                                  const float* __restrict__ ald,
                                  const __half* __restrict__ Hh,
                                  float* __restrict__ outm, int N)
{
    int w    = (int)((blockIdx.x * (size_t)blockDim.x + threadIdx.x) >> 5);
    int lane = threadIdx.x & 31;
    int hw   = lane >> 4;
    int hl   = lane & 15;
    int n = w * 2 + hw;
    if (n >= N) return;
    int head = hl >> 2;
    float ald_h = __ldg(ald + (size_t)n * 4 + head);
    int beg = __ldg(rowp + n), end = __ldg(rowp + n + 1);

    float4 accP = make_float4(0.f, 0.f, 0.f, 0.f);
    float4 accQ = make_float4(0.f, 0.f, 0.f, 0.f);
    float den = 0.f;

    int i = beg;
    for (; i + 4 <= end; i += 4) {
        int s0 = __ldg(col + i),     s1 = __ldg(col + i + 1);
        int s2 = __ldg(col + i + 2), s3 = __ldg(col + i + 3);
        float al0 = __ldg(als + (size_t)s0 * 4 + head);
        float al1 = __ldg(als + (size_t)s1 * 4 + head);
        float al2 = __ldg(als + (size_t)s2 * 4 + head);
        float al3 = __ldg(als + (size_t)s3 * 4 + head);
        uint4 u0 = *reinterpret_cast<const uint4*>(Hh + (size_t)s0 * 128 + hl * 8);
        uint4 u1 = *reinterpret_cast<const uint4*>(Hh + (size_t)s1 * 128 + hl * 8);
        uint4 u2 = *reinterpret_cast<const uint4*>(Hh + (size_t)s2 * 128 + hl * 8);
        uint4 u3 = *reinterpret_cast<const uint4*>(Hh + (size_t)s3 * 128 + hl * 8);
        float e0 = __expf(lrelu(al0 + ald_h));
        float e1 = __expf(lrelu(al1 + ald_h));
        float e2 = __expf(lrelu(al2 + ald_h));
        float e3 = __expf(lrelu(al3 + ald_h));
        acc_h16x8(accP, accQ, u0, e0);
        acc_h16x8(accP, accQ, u1, e1);
        acc_h16x8(accP, accQ, u2, e2);
        acc_h16x8(accP, accQ, u3, e3);
        den += (e0 + e1) + (e2 + e3);
    }
    for (; i < end; ++i) {
        int s0 = __ldg(col + i);
        float e0 = __expf(lrelu(__ldg(als + (size_t)s0 * 4 + head) + ald_h));
        uint4 u0 = *reinterpret_cast<const uint4*>(Hh + (size_t)s0 * 128 + hl * 8);
        acc_h16x8(accP, accQ, u0, e0);
        den += e0;
    }
    float inv = 1.f / (den + 1e-16f);
    float* orow = outm + (size_t)n * 128 + hl * 8;
    *reinterpret_cast<float4*>(orow) =
        make_float4(accP.x * inv, accP.y * inv, accP.z * inv, accP.w * inv);
    *reinterpret_cast<float4*>(orow + 4) =
        make_float4(accQ.x * inv, accQ.y * inv, accQ.z * inv, accQ.w * inv);
}

// ---------------- layer-2 aggregation + head-mean + log_softmax --------------
__global__ void aggregate_csr_160_final(const int* __restrict__ rowp,
                                        const int* __restrict__ col,
                                        const float* __restrict__ als,
                                        const float* __restrict__ ald,
                                        const __half* __restrict__ Hh,
                                        const float* __restrict__ b2,
                                        float* __restrict__ y, int N)
{
    __shared__ __align__(16) float sbuf[8][160];
    int wid  = threadIdx.x >> 5;
    int n    = (int)((blockIdx.x * (size_t)blockDim.x + threadIdx.x) >> 5);
    int lane = threadIdx.x & 31;
    if (n >= N) return;
    bool act = (lane < 20);
    int head = act ? (lane / 5) : 0;
    float ald_h = __ldg(ald + (size_t)n * 4 + head);
    int beg = __ldg(rowp + n), end = __ldg(rowp + n + 1);

    float4 accP = make_float4(0.f, 0.f, 0.f, 0.f);
    float4 accQ = make_float4(0.f, 0.f, 0.f, 0.f);
    float den = 0.f;
    const uint4 uz = make_uint4(0u, 0u, 0u, 0u);

    int i = beg;
    for (; i + 4 <= end; i += 4) {
        int s0 = __ldg(col + i),     s1 = __ldg(col + i + 1);
        int s2 = __ldg(col + i + 2), s3 = __ldg(col + i + 3);
        float al0 = __ldg(als + (size_t)s0 * 4 + head);
        float al1 = __ldg(als + (size_t)s1 * 4 + head);
        float al2 = __ldg(als + (size_t)s2 * 4 + head);
        float al3 = __ldg(als + (size_t)s3 * 4 + head);
        uint4 u0 = act ? *reinterpret_cast<const uint4*>(Hh + (size_t)s0 * 160 + lane * 8) : uz;
        uint4 u1 = act ? *reinterpret_cast<const uint4*>(Hh + (size_t)s1 * 160 + lane * 8) : uz;
        uint4 u2 = act ? *reinterpret_cast<const uint4*>(Hh + (size_t)s2 * 160 + lane * 8) : uz;
        uint4 u3 = act ? *reinterpret_cast<const uint4*>(Hh + (size_t)s3 * 160 + lane * 8) : uz;
        float e0 = __expf(lrelu(al0 + ald_h));
        float e1 = __expf(lrelu(al1 + ald_h));
        float e2 = __expf(lrelu(al2 + ald_h));
        float e3 = __expf(lrelu(al3 + ald_h));
        acc_h16x8(accP, accQ, u0, e0);
        acc_h16x8(accP, accQ, u1, e1);
        acc_h16x8(accP, accQ, u2, e2);
        acc_h16x8(accP, accQ, u3, e3);
        den += (e0 + e1) + (e2 + e3);
    }
    for (; i < end; ++i) {
        int s0 = __ldg(col + i);
        float e0 = __expf(lrelu(__ldg(als + (size_t)s0 * 4 + head) + ald_h));
        uint4 u0 = act ? *reinterpret_cast<const uint4*>(Hh + (size_t)s0 * 160 + lane * 8) : uz;
        acc_h16x8(accP, accQ, u0, e0);
        den += e0;
    }
    float inv = 1.f / (den + 1e-16f);
    if (act) {
        *reinterpret_cast<float4*>(&sbuf[wid][lane * 8]) =
            make_float4(accP.x * inv, accP.y * inv, accP.z * inv, accP.w * inv);
        *reinterpret_cast<float4*>(&sbuf[wid][lane * 8 + 4]) =
            make_float4(accQ.x * inv, accQ.y * inv, accQ.z * inv, accQ.w * inv);
    }
    __syncwarp();

    const float* S = sbuf[wid];
    int c0 = lane;
    int c1 = lane + 32;
    bool has1 = (c1 < 40);

    float v0 = 0.25f * (S[c0] + S[40 + c0] + S[80 + c0] + S[120 + c0]) + __ldg(&b2[c0]);
    float v1 = -1e30f;
    if (has1)
        v1 = 0.25f * (S[c1] + S[40 + c1] + S[80 + c1] + S[120 + c1]) + __ldg(&b2[c1]);

    float m = fmaxf(v0, v1);
#pragma unroll
    for (int o = 16; o; o >>= 1) m = fmaxf(m, __shfl_xor_sync(0xffffffffu, m, o));
    float se = __expf(v0 - m) + (has1 ? __expf(v1 - m) : 0.f);
#pragma unroll
    for (int o = 16; o; o >>= 1) se += __shfl_xor_sync(0xffffffffu, se, o);
    float lse = logf(se) + m;

    y[(size_t)n * 40 + c0] = v0 - lse;
    if (has1) y[(size_t)n * 40 + c1] = v1 - lse;
}

// ---------------- host side --------------------------------------------------
extern "C" void kernel_launch(void* const* d_in, const int* in_sizes, int n_in,
                              void* d_out, int out_size)
{
    const float* x   = (const float*)d_in[0];
    const int*   ei  = (const int*)  d_in[1];
    const float* W1  = (const float*)d_in[2];
    const float* as1 = (const float*)d_in[3];
    const float* ad1 = (const float*)d_in[4];
    const float* b1  = (const float*)d_in[5];
    const float* W2  = (const float*)d_in[6];
    const float* as2 = (const float*)d_in[7];
    const float* ad2 = (const float*)d_in[8];
    const float* b2  = (const float*)d_in[9];
    float* y = (float*)d_out;

    const int N = in_sizes[0] / F1;
    const int E = in_sizes[1] / 2;
    const int* src = ei;
    const int* dst = ei + E;

    void* p;
    cudaGetSymbolAddress(&p, g_h1h);   __half* h1h = (__half*)p;
    cudaGetSymbolAddress(&p, g_h2h);   __half* h2h = (__half*)p;
    cudaGetSymbolAddress(&p, g_out1);  float* o1   = (float*)p;
    cudaGetSymbolAddress(&p, g_als1);  float* als1 = (float*)p;
    cudaGetSymbolAddress(&p, g_ald1);  float* ald1 = (float*)p;
    cudaGetSymbolAddress(&p, g_als2);  float* als2 = (float*)p;
    cudaGetSymbolAddress(&p, g_ald2);  float* ald2 = (float*)p;
    cudaGetSymbolAddress(&p, g_cnt);   int* cnt  = (int*)p;
    cudaGetSymbolAddress(&p, g_rowp);  int* rowp = (int*)p;
    cudaGetSymbolAddress(&p, g_col);   int* col  = (int*)p;
    cudaGetSymbolAddress(&p, g_state); ull* state = (ull*)p;
    cudaGetSymbolAddress(&p, g_ticket); int* ticket = (int*)p;
    cudaGetSymbolAddress(&p, g_wp1);   uint32_t* wp1 = (uint32_t*)p;
    cudaGetSymbolAddress(&p, g_wp2);   uint32_t* wp2 = (uint32_t*)p;
    int* cnt2 = cnt + MAXN;

    static cudaStream_t s2 = nullptr;
    static cudaEvent_t evFork = nullptr, evJoin = nullptr;
    if (!s2) {
        cudaStreamCreateWithFlags(&s2, cudaStreamNonBlocking);
        cudaEventCreateWithFlags(&evFork, cudaEventDisableTiming);
        cudaEventCreateWithFlags(&evJoin, cudaEventDisableTiming);
    }

    const int smem = (64 * 128 + 512) * 4;   // 34 KB (A + attn partials)
    cudaFuncSetAttribute(gemm_mma<F1, false>,
                         cudaFuncAttributeMaxDynamicSharedMemorySize, smem);
    cudaFuncSetAttribute(gemm_mma<F2, true>,
                         cudaFuncAttributeMaxDynamicSharedMemorySize, smem);

    const int TB = 256;
    const int NB = (N + 511) / 512;
    const int gemmBlocks   = (N + 63) / 64;
    const int nodeWBlocks  = (int)(((size_t)N * 32 + TB - 1) / TB);
    const int node2WBlocks = (int)((((size_t)(N + 1) / 2) * 32 + TB - 1) / TB);

    cudaMemsetAsync(cnt, 0, 2 * (size_t)MAXN * sizeof(int));
    cudaMemsetAsync(state, 0, 256 * sizeof(ull));
    cudaMemsetAsync(ticket, 0, sizeof(int));

    // fork: CSR build + W2 pack on s2, concurrent with gemm1
    cudaEventRecord(evFork, 0);
    cudaStreamWaitEvent(s2, evFork, 0);

    pack_w<F2><<<(128 * F2 / 4 + TB - 1) / TB, TB, 0, s2>>>(W2, wp2);
    count_deg<<<(E + TB - 1) / TB, TB, 0, s2>>>(dst, cnt, E);
    scan_one<<<NB, 512, 0, s2>>>(cnt, rowp, state, ticket, N, E);
    fill_csr<<<(E + TB - 1) / TB, TB, 0, s2>>>(src, dst, rowp, cnt2, col, E);
    cudaEventRecord(evJoin, s2);

    // main stream: pack W1, then layer-1 GEMM (+ fused attention)
    pack_w<F1><<<(128 * F1 / 4 + TB - 1) / TB, TB>>>(W1, wp1);
    gemm_mma<F1, false><<<gemmBlocks, TB, smem>>>(
        x, wp1, nullptr, as1, ad1, h1h, als1, ald1, N);

    cudaStreamWaitEvent(0, evJoin, 0);

    aggregate_csr_128<<<node2WBlocks, TB>>>(rowp, col, als1, ald1, h1h, o1, N);

    gemm_mma<F2, true><<<gemmBlocks, TB, smem>>>(
        o1, wp2, b1, as2, ad2, h2h, als2, ald2, N);

    aggregate_csr_160_final<<<nodeWBlocks, TB>>>(rowp, col, als2, ald2, h2h, b2, y, N);
}

// round 15
// speedup vs baseline: 3.7325x; 1.0157x over previous
#include <cuda_runtime.h>
#include <cuda_fp16.h>
#include <math.h>
#include <stdint.h>

static constexpr int MAXN = 100000;
static constexpr int MAXE = 1600000;
static constexpr int F1   = 128;   // F_in and H*HID
static constexpr int F2   = 160;   // H*NCLS
static constexpr int NH   = 4;
static constexpr float NEG_SLOPE = 0.2f;

typedef unsigned long long ull;

// ---------------- scratch ----------------------------------------------------
__device__ ull   g_h1h [(size_t)MAXN * F1 / 4];   // fp16 h1
__device__ ull   g_h2h [(size_t)MAXN * F2 / 4];   // fp16 h2
__device__ ull   g_o1h [(size_t)MAXN * F1 / 4];   // fp16 layer-1 output
__device__ float g_als1[(size_t)MAXN * NH];
__device__ float g_ald1[(size_t)MAXN * NH];
__device__ float g_als2[(size_t)MAXN * NH];
__device__ float g_ald2[(size_t)MAXN * NH];
__device__ int   g_cnt [2 * MAXN];
__device__ int   g_rowp[MAXN + 1];
__device__ int   g_col [MAXE];
__device__ ull   g_state[256];
__device__ int   g_ticket;
__device__ uint32_t g_wp1[128 * F1];   // fragment-packed tf32 W1
__device__ uint32_t g_wp2[128 * F2];   // fragment-packed tf32 W2

__device__ __forceinline__ float lrelu(float v) {
    return v > 0.f ? v : NEG_SLOPE * v;
}

__device__ __forceinline__ uint32_t f2tf32(float f) {
    uint32_t u;
    asm("cvt.rna.tf32.f32 %0, %1;" : "=r"(u) : "f"(f));
    return u;
}

__device__ __forceinline__ void mma_tf32(float& c0, float& c1, float& c2, float& c3,
                                         uint32_t a0, uint32_t a1, uint32_t a2, uint32_t a3,
                                         uint32_t b0, uint32_t b1) {
    asm volatile(
        "mma.sync.aligned.m16n8k8.row.col.f32.tf32.tf32.f32 "
        "{%0,%1,%2,%3}, {%4,%5,%6,%7}, {%8,%9}, {%0,%1,%2,%3};"
        : "+f"(c0), "+f"(c1), "+f"(c2), "+f"(c3)
        : "r"(a0), "r"(a1), "r"(a2), "r"(a3), "r"(b0), "r"(b1));
}

// ---------------- CSR build --------------------------------------------------
__global__ void count_deg(const int* __restrict__ dst, int* __restrict__ cnt, int E) {
    int e = blockIdx.x * blockDim.x + threadIdx.x;
    if (e < E) atomicAdd(&cnt[dst[e]], 1);
}

static constexpr ull FLG_AGG = 1ull << 62;
static constexpr ull FLG_PRE = 2ull << 62;

// scan also seeds cnt2 with the row-start offsets, so fill_csr's atomicAdd
// return value is the absolute col[] position (no rowp gather needed).
__global__ void scan_one(const int* __restrict__ cnt, int* __restrict__ rowp,
                         int* __restrict__ cnt2,
                         ull* __restrict__ state, int* __restrict__ ticket,
                         int N, int E)
{
    __shared__ int sm[512];
    __shared__ int sbid, sprefix;
    int t = threadIdx.x;
    if (t == 0) sbid = atomicAdd(ticket, 1);
    __syncthreads();
    int b = sbid;
    int i = b * 512 + t;
    int v = (i < N) ? cnt[i] : 0;
    sm[t] = v;
    __syncthreads();
    for (int o = 1; o < 512; o <<= 1) {
        int add = (t >= o) ? sm[t - o] : 0;
        __syncthreads();
        sm[t] += add;
        __syncthreads();
    }
    int incl  = sm[t];
    int total = sm[511];
    if (t == 0) {
        if (b == 0) {
            atomicExch(&state[0], FLG_PRE | (unsigned)total);
            sprefix = 0;
        } else {
            atomicExch(&state[b], FLG_AGG | (unsigned)total);
            int run = 0, j = b - 1;
            while (true) {
                ull s;
                do { s = atomicAdd(&state[j], 0ull); } while ((s >> 62) == 0);
                run += (int)(s & 0xffffffffu);
                if (s & FLG_PRE) break;
                --j;
            }
            atomicExch(&state[b], FLG_PRE | (unsigned)(run + total));
            sprefix = run;
        }
    }
    __syncthreads();
    if (i < N) {
        int off = sprefix + incl - v;
        rowp[i] = off;
        cnt2[i] = off;
    }
    if (b == 0 && t == 0) rowp[N] = E;
}

__global__ void fill_csr(const int* __restrict__ src, const int* __restrict__ dst,
                         int* __restrict__ cnt2, int* __restrict__ col, int E) {
    int e = blockIdx.x * blockDim.x + threadIdx.x;
    if (e >= E) return;
    int d = __ldg(dst + e);
    int k = atomicAdd(&cnt2[d], 1);
    col[k] = __ldg(src + e);
}

// ---------------- one-shot W pack --------------------------------------------
template<int NOUT>
__global__ void pack_w(const float* __restrict__ W, uint32_t* __restrict__ out)
{
    constexpr int JJ = NOUT / 32;
    int i = blockIdx.x * blockDim.x + threadIdx.x;
    if (i >= 128 * NOUT / 4) return;
    int idx = i * 4;
    int kk  = idx / NOUT;
    int cc  = idx % NOUT;
    float4 v = *reinterpret_cast<const float4*>(W + (size_t)kk * NOUT + cc);
    int kb  = kk >> 3;
    int km  = kk & 7;
    int tg2 = km & 3;
    int b01 = km >> 2;
    int wc  = cc / (NOUT / 2);
    int nn  = cc % (NOUT / 2);
    int jj  = nn >> 4;
    int rem = nn & 15;
    int jpar = rem >> 3;
    int gq  = rem & 7;
    int quad = jpar * 2 + b01;
    uint32_t base = (uint32_t)((kb * 2 + wc) * JJ + jj) * 32;
    float vv[4] = {v.x, v.y, v.z, v.w};
#pragma unroll
    for (int j = 0; j < 4; ++j) {
        int lp = ((gq + j) * 4 + tg2) & 31;
        out[(base + lp) * 4 + quad] = f2tf32(vv[j]);
    }
}

// ---------------- GEMM (mma.sync tf32) + fused attention epilogue ------------
// A fragment-packed in smem + 2 KB attn-partial table. B from packed global.
// AHALF: A matrix stored fp16 (layer-2 path).
template<int NOUT, bool RELU_BIAS, bool AHALF>
__global__ void __launch_bounds__(256, 3)
gemm_mma(const void* __restrict__ Ap,
         const uint32_t* __restrict__ WP,
         const float* __restrict__ bias,
         const float* __restrict__ a_s,
         const float* __restrict__ a_d,
         __half* __restrict__ outh,
         float* __restrict__ als,
         float* __restrict__ ald, int N)
{
    constexpr int NTILE = NOUT / 16;
    constexpr int JJ    = NOUT / 32;
    constexpr int HALF  = NTILE / 2;
    extern __shared__ uint32_t usmem[];
    uint32_t* sA   = usmem;
    float*    sAls = reinterpret_cast<float*>(usmem + 64 * 128);   // [64][4]
    float*    sAld = sAls + 256;                                    // [64][4]

    const int tid  = threadIdx.x;
    const int warp = tid >> 5;
    const int lane = tid & 31;
    const int g    = lane >> 2;
    const int tg   = lane & 3;
    const int warp_r = warp & 3;
    const int warp_c = warp >> 2;
    const int r0   = warp_r * 16;
    const int row0 = blockIdx.x * 64;
    const int nbase = warp_c * (NOUT / 2);

    for (int i = tid; i < 512; i += 256) { sAls[i] = 0.f; }

    if (!AHALF) {
        const float* A = (const float*)Ap;
        for (int i = tid; i < 64 * 128 / 4; i += 256) {
            int idx = i * 4;
            int r   = idx >> 7;
            int k   = idx & 127;
            int gr  = row0 + r;
            float4 v = make_float4(0.f, 0.f, 0.f, 0.f);
            if (gr < N) {
                v = *reinterpret_cast<const float4*>(A + (size_t)gr * 128 + k);
                if (RELU_BIAS) {
                    v.x = fmaxf(v.x + bias[k + 0], 0.f);
                    v.y = fmaxf(v.y + bias[k + 1], 0.f);
                    v.z = fmaxf(v.z + bias[k + 2], 0.f);
                    v.w = fmaxf(v.w + bias[k + 3], 0.f);
                }
            }
            int rw    = r >> 4;
            int rr    = r & 15;
            int gq    = rr & 7;
            int rowhi = rr >> 3;
            int kb    = k >> 3;
            int khi   = (k >> 2) & 1;
            int slot  = khi * 2 + rowhi;
            uint32_t base = (uint32_t)(rw * 16 + kb) * 32;
            int lpb  = gq * 4 + kb * 5;
            float vv[4] = {v.x, v.y, v.z, v.w};
#pragma unroll
            for (int j = 0; j < 4; ++j)
                sA[(base + ((lpb + j) & 31)) * 4 + slot] = f2tf32(vv[j]);
        }
    } else {
        const __half* A = (const __half*)Ap;
        for (int i = tid; i < 64 * 128 / 8; i += 256) {
            int idx = i * 8;
            int r   = idx >> 7;
            int k   = idx & 127;          // multiple of 8 == kb*8
            int gr  = row0 + r;
            float f[8];
            if (gr < N) {
                uint4 u = *reinterpret_cast<const uint4*>(A + (size_t)gr * 128 + k);
                float2 p0 = __half22float2(*reinterpret_cast<__half2*>(&u.x));
                float2 p1 = __half22float2(*reinterpret_cast<__half2*>(&u.y));
                float2 p2 = __half22float2(*reinterpret_cast<__half2*>(&u.z));
                float2 p3 = __half22float2(*reinterpret_cast<__half2*>(&u.w));
                f[0] = p0.x; f[1] = p0.y; f[2] = p1.x; f[3] = p1.y;
                f[4] = p2.x; f[5] = p2.y; f[6] = p3.x; f[7] = p3.y;
                if (RELU_BIAS) {
#pragma unroll
                    for (int j = 0; j < 8; ++j)
                        f[j] = fmaxf(f[j] + __ldg(bias + k + j), 0.f);
                }
            } else {
#pragma unroll
                for (int j = 0; j < 8; ++j) f[j] = 0.f;
            }
            int rw    = r >> 4;
            int rr    = r & 15;
            int gq    = rr & 7;
            int rowhi = rr >> 3;
            int kb    = k >> 3;
            uint32_t base = (uint32_t)(rw * 16 + kb) * 32;
            int lpb  = gq * 4 + kb * 5;
#pragma unroll
            for (int j = 0; j < 8; ++j) {
                int slot = (j >> 2) * 2 + rowhi;
                sA[(base + ((lpb + (j & 3)) & 31)) * 4 + slot] = f2tf32(f[j]);
            }
        }
    }
    __syncthreads();

    float c[NTILE][4];
#pragma unroll
    for (int j = 0; j < NTILE; ++j) {
        c[j][0] = 0.f; c[j][1] = 0.f; c[j][2] = 0.f; c[j][3] = 0.f;
    }

    const uint4* wp4 = reinterpret_cast<const uint4*>(WP);

#pragma unroll
    for (int kb = 0; kb < 16; ++kb) {
        int laneA = (lane + kb * 5) & 31;
        uint4 av = *reinterpret_cast<uint4*>(
            sA + ((uint32_t)(warp_r * 16 + kb) * 32 + laneA) * 4);
        const uint4* wrow = wp4 + (uint32_t)((kb * 2 + warp_c) * JJ) * 32 + lane;
#pragma unroll
        for (int jj = 0; jj < JJ; ++jj) {
            uint4 bv = __ldg(wrow + jj * 32);
            mma_tf32(c[2*jj][0], c[2*jj][1], c[2*jj][2], c[2*jj][3],
                     av.x, av.y, av.z, av.w, bv.x, bv.y);
            mma_tf32(c[2*jj+1][0], c[2*jj+1][1], c[2*jj+1][2], c[2*jj+1][3],
                     av.x, av.y, av.z, av.w, bv.z, bv.w);
        }
    }

    // ---- store C as fp16 + accumulate attention partials ----
    int rA = row0 + r0 + g;
    int rB = rA + 8;
    float pa[2][2] = {{0.f, 0.f}, {0.f, 0.f}};
    float pd[2][2] = {{0.f, 0.f}, {0.f, 0.f}};
#pragma unroll
    for (int j = 0; j < NTILE; ++j) {
        int colp = nbase + j * 8 + 2 * tg;
        if (rA < N)
            *reinterpret_cast<__half2*>(outh + (size_t)rA * NOUT + colp) =
                __floats2half2_rn(c[j][0], c[j][1]);
        if (rB < N)
            *reinterpret_cast<__half2*>(outh + (size_t)rB * NOUT + colp) =
                __floats2half2_rn(c[j][2], c[j][3]);
        float2 asv = __ldg(reinterpret_cast<const float2*>(a_s + colp));
        float2 adv = __ldg(reinterpret_cast<const float2*>(a_d + colp));
        int hsel = j / HALF;
        pa[hsel][0] += c[j][0] * asv.x + c[j][1] * asv.y;
        pa[hsel][1] += c[j][2] * asv.x + c[j][3] * asv.y;
        pd[hsel][0] += c[j][0] * adv.x + c[j][1] * adv.y;
        pd[hsel][1] += c[j][2] * adv.x + c[j][3] * adv.y;
    }
    int raL = r0 + g;
    int rbL = raL + 8;
    int h0 = 2 * warp_c;
#pragma unroll
    for (int hs = 0; hs < 2; ++hs) {
        atomicAdd(&sAls[raL * 4 + h0 + hs], pa[hs][0]);
        atomicAdd(&sAls[rbL * 4 + h0 + hs], pa[hs][1]);
        atomicAdd(&sAld[raL * 4 + h0 + hs], pd[hs][0]);
        atomicAdd(&sAld[rbL * 4 + h0 + hs], pd[hs][1]);
    }
    __syncthreads();

    if (tid < 256) {
        int r = tid >> 2;
        int gr = row0 + r;
        if (gr < N) {
            als[(size_t)gr * 4 + (tid & 3)] = sAls[tid];
            ald[(size_t)gr * 4 + (tid & 3)] = sAld[tid];
        }
    }
}

// ---------------- layer-1 aggregation: 2 nodes per warp, fp16 out ------------
__device__ __forceinline__ void acc_h16x8(float4& p, float4& q, uint4 u, float e) {
    float2 f0 = __half22float2(*reinterpret_cast<__half2*>(&u.x));
    float2 f1 = __half22float2(*reinterpret_cast<__half2*>(&u.y));
    float2 f2 = __half22float2(*reinterpret_cast<__half2*>(&u.z));
    float2 f3 = __half22float2(*reinterpret_cast<__half2*>(&u.w));
    p.x = fmaf(e, f0.x, p.x); p.y = fmaf(e, f0.y, p.y);
    p.z = fmaf(e, f1.x, p.z); p.w = fmaf(e, f1.y, p.w);
    q.x = fmaf(e, f2.x, q.x); q.y = fmaf(e, f2.y, q.y);
    q.z = fmaf(e, f3.x, q.z); q.w = fmaf(e, f3.y, q.w);
}

__global__ void aggregate_csr_128(const int* __restrict__ rowp,
                                  const int* __restrict__ col,
                                  const float* __restrict__ als,
                                  const float* __restrict__ ald,
                                  const __half* __restrict__ Hh,
                                  __half* __restrict__ outh, int N)
{
    int w    = (int)((blockIdx.x * (size_t)blockDim.x + threadIdx.x) >> 5);
    int lane = threadIdx.x & 31;
    int hw   = lane >> 4;
    int hl   = lane & 15;
    int n = w * 2 + hw;
    if (n >= N) return;
    int head = hl >> 2;
    float ald_h = __ldg(ald + (size_t)n * 4 + head);
    int beg = __ldg(rowp + n), end = __ldg(rowp + n + 1);

    float4 accP = make_float4(0.f, 0.f, 0.f, 0.f);
    float4 accQ = make_float4(0.f, 0.f, 0.f, 0.f);
    float den = 0.f;

    int i = beg;
    for (; i + 4 <= end; i += 4) {
        int s0 = __ldg(col + i),     s1 = __ldg(col + i + 1);
        int s2 = __ldg(col + i + 2), s3 = __ldg(col + i + 3);
        float al0 = __ldg(als + (size_t)s0 * 4 + head);
        float al1 = __ldg(als + (size_t)s1 * 4 + head);
        float al2 = __ldg(als + (size_t)s2 * 4 + head);
        float al3 = __ldg(als + (size_t)s3 * 4 + head);
        uint4 u0 = *reinterpret_cast<const uint4*>(Hh + (size_t)s0 * 128 + hl * 8);
        uint4 u1 = *reinterpret_cast<const uint4*>(Hh + (size_t)s1 * 128 + hl * 8);
        uint4 u2 = *reinterpret_cast<const uint4*>(Hh + (size_t)s2 * 128 + hl * 8);
        uint4 u3 = *reinterpret_cast<const uint4*>(Hh + (size_t)s3 * 128 + hl * 8);
        float e0 = __expf(lrelu(al0 + ald_h));
        float e1 = __expf(lrelu(al1 + ald_h));
        float e2 = __expf(lrelu(al2 + ald_h));
        float e3 = __expf(lrelu(al3 + ald_h));
        acc_h16x8(accP, accQ, u0, e0);
        acc_h16x8(accP, accQ, u1, e1);
        acc_h16x8(accP, accQ, u2, e2);
        acc_h16x8(accP, accQ, u3, e3);
        den += (e0 + e1) + (e2 + e3);
    }
    for (; i < end; ++i) {
        int s0 = __ldg(col + i);
        float e0 = __expf(lrelu(__ldg(als + (size_t)s0 * 4 + head) + ald_h));
        uint4 u0 = *reinterpret_cast<const uint4*>(Hh + (size_t)s0 * 128 + hl * 8);
        acc_h16x8(accP, accQ, u0, e0);
        den += e0;
    }
    float inv = 1.f / (den + 1e-16f);
    uint4 o;
    *reinterpret_cast<__half2*>(&o.x) = __floats2half2_rn(accP.x * inv, accP.y * inv);
    *reinterpret_cast<__half2*>(&o.y) = __floats2half2_rn(accP.z * inv, accP.w * inv);
    *reinterpret_cast<__half2*>(&o.z) = __floats2half2_rn(accQ.x * inv, accQ.y * inv);
    *reinterpret_cast<__half2*>(&o.w) = __floats2half2_rn(accQ.z * inv, accQ.w * inv);
    *reinterpret_cast<uint4*>(outh + (size_t)n * 128 + hl * 8) = o;
}

// ---------------- layer-2 aggregation + head-mean + log_softmax --------------
__global__ void aggregate_csr_160_final(const int* __restrict__ rowp,
                                        const int* __restrict__ col,
                                        const float* __restrict__ als,
                                        const float* __restrict__ ald,
                                        const __half* __restrict__ Hh,
                                        const float* __restrict__ b2,
                                        float* __restrict__ y, int N)
{
    __shared__ __align__(16) float sbuf[8][160];
    int wid  = threadIdx.x >> 5;
    int n    = (int)((blockIdx.x * (size_t)blockDim.x + threadIdx.x) >> 5);
    int lane = threadIdx.x & 31;
    if (n >= N) return;
    bool act = (lane < 20);
    int head = act ? (lane / 5) : 0;
    float ald_h = __ldg(ald + (size_t)n * 4 + head);
    int beg = __ldg(rowp + n), end = __ldg(rowp + n + 1);

    float4 accP = make_float4(0.f, 0.f, 0.f, 0.f);
    float4 accQ = make_float4(0.f, 0.f, 0.f, 0.f);
    float den = 0.f;
    const uint4 uz = make_uint4(0u, 0u, 0u, 0u);

    int i = beg;
    for (; i + 4 <= end; i += 4) {
        int s0 = __ldg(col + i),     s1 = __ldg(col + i + 1);
        int s2 = __ldg(col + i + 2), s3 = __ldg(col + i + 3);
        float al0 = __ldg(als + (size_t)s0 * 4 + head);
        float al1 = __ldg(als + (size_t)s1 * 4 + head);
        float al2 = __ldg(als + (size_t)s2 * 4 + head);
        float al3 = __ldg(als + (size_t)s3 * 4 + head);
        uint4 u0 = act ? *reinterpret_cast<const uint4*>(Hh + (size_t)s0 * 160 + lane * 8) : uz;
        uint4 u1 = act ? *reinterpret_cast<const uint4*>(Hh + (size_t)s1 * 160 + lane * 8) : uz;
        uint4 u2 = act ? *reinterpret_cast<const uint4*>(Hh + (size_t)s2 * 160 + lane * 8) : uz;
        uint4 u3 = act ? *reinterpret_cast<const uint4*>(Hh + (size_t)s3 * 160 + lane * 8) : uz;
        float e0 = __expf(lrelu(al0 + ald_h));
        float e1 = __expf(lrelu(al1 + ald_h));
        float e2 = __expf(lrelu(al2 + ald_h));
        float e3 = __expf(lrelu(al3 + ald_h));
        acc_h16x8(accP, accQ, u0, e0);
        acc_h16x8(accP, accQ, u1, e1);
        acc_h16x8(accP, accQ, u2, e2);
        acc_h16x8(accP, accQ, u3, e3);
        den += (e0 + e1) + (e2 + e3);
    }
    for (; i < end; ++i) {
        int s0 = __ldg(col + i);
        float e0 = __expf(lrelu(__ldg(als + (size_t)s0 * 4 + head) + ald_h));
        uint4 u0 = act ? *reinterpret_cast<const uint4*>(Hh + (size_t)s0 * 160 + lane * 8) : uz;
        acc_h16x8(accP, accQ, u0, e0);
        den += e0;
    }
    float inv = 1.f / (den + 1e-16f);
    if (act) {
        *reinterpret_cast<float4*>(&sbuf[wid][lane * 8]) =
            make_float4(accP.x * inv, accP.y * inv, accP.z * inv, accP.w * inv);
        *reinterpret_cast<float4*>(&sbuf[wid][lane * 8 + 4]) =
            make_float4(accQ.x * inv, accQ.y * inv, accQ.z * inv, accQ.w * inv);
    }
    __syncwarp();

    const float* S = sbuf[wid];
    int c0 = lane;
    int c1 = lane + 32;
    bool has1 = (c1 < 40);

    float v0 = 0.25f * (S[c0] + S[40 + c0] + S[80 + c0] + S[120 + c0]) + __ldg(&b2[c0]);
    float v1 = -1e30f;
    if (has1)
        v1 = 0.25f * (S[c1] + S[40 + c1] + S[80 + c1] + S[120 + c1]) + __ldg(&b2[c1]);

    float m = fmaxf(v0, v1);
#pragma unroll
    for (int o = 16; o; o >>= 1) m = fmaxf(m, __shfl_xor_sync(0xffffffffu, m, o));
    float se = __expf(v0 - m) + (has1 ? __expf(v1 - m) : 0.f);
#pragma unroll
    for (int o = 16; o; o >>= 1) se += __shfl_xor_sync(0xffffffffu, se, o);
    float lse = logf(se) + m;

    y[(size_t)n * 40 + c0] = v0 - lse;
    if (has1) y[(size_t)n * 40 + c1] = v1 - lse;
}

// ---------------- host side --------------------------------------------------
extern "C" void kernel_launch(void* const* d_in, const int* in_sizes, int n_in,
                              void* d_out, int out_size)
{
    const float* x   = (const float*)d_in[0];
    const int*   ei  = (const int*)  d_in[1];
    const float* W1  = (const float*)d_in[2];
    const float* as1 = (const float*)d_in[3];
    const float* ad1 = (const float*)d_in[4];
    const float* b1  = (const float*)d_in[5];
    const float* W2  = (const float*)d_in[6];
    const float* as2 = (const float*)d_in[7];
    const float* ad2 = (const float*)d_in[8];
    const float* b2  = (const float*)d_in[9];
    float* y = (float*)d_out;

    const int N = in_sizes[0] / F1;
    const int E = in_sizes[1] / 2;
    const int* src = ei;
    const int* dst = ei + E;

    void* p;
    cudaGetSymbolAddress(&p, g_h1h);   __half* h1h = (__half*)p;
    cudaGetSymbolAddress(&p, g_h2h);   __half* h2h = (__half*)p;
    cudaGetSymbolAddress(&p, g_o1h);   __half* o1h = (__half*)p;
    cudaGetSymbolAddress(&p, g_als1);  float* als1 = (float*)p;
    cudaGetSymbolAddress(&p, g_ald1);  float* ald1 = (float*)p;
    cudaGetSymbolAddress(&p, g_als2);  float* als2 = (float*)p;
    cudaGetSymbolAddress(&p, g_ald2);  float* ald2 = (float*)p;
    cudaGetSymbolAddress(&p, g_cnt);   int* cnt  = (int*)p;
    cudaGetSymbolAddress(&p, g_rowp);  int* rowp = (int*)p;
    cudaGetSymbolAddress(&p, g_col);   int* col  = (int*)p;
    cudaGetSymbolAddress(&p, g_state); ull* state = (ull*)p;
    cudaGetSymbolAddress(&p, g_ticket); int* ticket = (int*)p;
    cudaGetSymbolAddress(&p, g_wp1);   uint32_t* wp1 = (uint32_t*)p;
    cudaGetSymbolAddress(&p, g_wp2);   uint32_t* wp2 = (uint32_t*)p;
    int* cnt2 = cnt + MAXN;

    static cudaStream_t s2 = nullptr;
    static cudaEvent_t evFork = nullptr, evJoin = nullptr;
    if (!s2) {
        cudaStreamCreateWithFlags(&s2, cudaStreamNonBlocking);
        cudaEventCreateWithFlags(&evFork, cudaEventDisableTiming);
        cudaEventCreateWithFlags(&evJoin, cudaEventDisableTiming);
    }

    const int smem = (64 * 128 + 512) * 4;   // 34 KB
    cudaFuncSetAttribute(gemm_mma<F1, false, false>,
                         cudaFuncAttributeMaxDynamicSharedMemorySize, smem);
    cudaFuncSetAttribute(gemm_mma<F2, true, true>,
                         cudaFuncAttributeMaxDynamicSharedMemorySize, smem);

    const int TB = 256;
    const int NB = (N + 511) / 512;
    const int gemmBlocks   = (N + 63) / 64;
    const int nodeWBlocks  = (int)(((size_t)N * 32 + TB - 1) / TB);
    const int node2WBlocks = (int)((((size_t)(N + 1) / 2) * 32 + TB - 1) / TB);

    cudaMemsetAsync(cnt, 0, (size_t)MAXN * sizeof(int));   // cnt only; cnt2 seeded by scan
    cudaMemsetAsync(state, 0, 256 * sizeof(ull));
    cudaMemsetAsync(ticket, 0, sizeof(int));

    // fork: CSR build + W2 pack on s2, concurrent with gemm1
    cudaEventRecord(evFork, 0);
    cudaStreamWaitEvent(s2, evFork, 0);

    pack_w<F2><<<(128 * F2 / 4 + TB - 1) / TB, TB, 0, s2>>>(W2, wp2);
    count_deg<<<(E + TB - 1) / TB, TB, 0, s2>>>(dst, cnt, E);
    scan_one<<<NB, 512, 0, s2>>>(cnt, rowp, cnt2, state, ticket, N, E);
    fill_csr<<<(E + TB - 1) / TB, TB, 0, s2>>>(src, dst, cnt2, col, E);
    cudaEventRecord(evJoin, s2);

    // main stream: pack W1, then layer-1 GEMM (+ fused attention)
    pack_w<F1><<<(128 * F1 / 4 + TB - 1) / TB, TB>>>(W1, wp1);
    gemm_mma<F1, false, false><<<gemmBlocks, TB, smem>>>(
        x, wp1, nullptr, as1, ad1, h1h, als1, ald1, N);

    cudaStreamWaitEvent(0, evJoin, 0);

    aggregate_csr_128<<<node2WBlocks, TB>>>(rowp, col, als1, ald1, h1h, o1h, N);

    gemm_mma<F2, true, true><<<gemmBlocks, TB, smem>>>(
        o1h, wp2, b1, as2, ad2, h2h, als2, ald2, N);

    aggregate_csr_160_final<<<nodeWBlocks, TB>>>(rowp, col, als2, ald2, h2h, b2, y, N);
}